// round 1
// baseline (speedup 1.0000x reference)
#include <cuda_runtime.h>
#include <cuda_bf16.h>

// ---------------------------------------------------------------------------
// Static scratch (no allocation allowed)
// ---------------------------------------------------------------------------
#define NMAX 100000
#define EMAX 1600000

__device__ float g_B0[NMAX * 128];
__device__ float g_B1[NMAX * 128];
__device__ float g_B2[NMAX * 128];
__device__ float g_w [NMAX];
__device__ float g_dinv[NMAX];
__device__ int   g_cnt[NMAX];
__device__ int   g_ptr[NMAX + 1];
__device__ int   g_cur[NMAX];
__device__ int   g_rows[EMAX];
__device__ int   g_bsum[512];
__device__ float g_gmax[256];
__device__ float g_gsum[256];
__device__ float g_pooled[256 * 128];
__device__ float g_h[256 * 128];

// ---------------------------------------------------------------------------
// Small utility kernels
// ---------------------------------------------------------------------------
__global__ void init_k(int* cnt, float* gmax, float* gsum, float* pooled, int n) {
    int i = blockIdx.x * blockDim.x + threadIdx.x;
    if (i < n) cnt[i] = 0;
    if (i < 256) { gmax[i] = 0.0f; gsum[i] = 0.0f; }
    if (i < 256 * 128) pooled[i] = 0.0f;
}

__global__ void count_k(const int* __restrict__ col, int* __restrict__ cnt, int e) {
    int i = blockIdx.x * blockDim.x + threadIdx.x;
    if (i < e) atomicAdd(&cnt[col[i]], 1);
}

__global__ void dinv_k(const int* __restrict__ cnt, float* __restrict__ dinv, int n) {
    int i = blockIdx.x * blockDim.x + threadIdx.x;
    if (i < n) dinv[i] = rsqrtf((float)cnt[i] + 1.0f);   // +1 = self loop
}

// Block-wise exclusive scan (512 per block)
__global__ void scan1_k(const int* __restrict__ cnt, int* __restrict__ ptr,
                        int* __restrict__ bsum, int n) {
    __shared__ int s[512];
    int t = threadIdx.x;
    int i = blockIdx.x * 512 + t;
    int v = (i < n) ? cnt[i] : 0;
    s[t] = v; __syncthreads();
    for (int off = 1; off < 512; off <<= 1) {
        int tmp = (t >= off) ? s[t - off] : 0;
        __syncthreads();
        s[t] += tmp;
        __syncthreads();
    }
    if (i < n) ptr[i] = s[t] - v;
    if (t == 511) bsum[blockIdx.x] = s[511];
}

__global__ void scan2_k(int* __restrict__ bsum, int nb) {
    __shared__ int s[512];
    int t = threadIdx.x;
    int v = (t < nb) ? bsum[t] : 0;
    s[t] = v; __syncthreads();
    for (int off = 1; off < 512; off <<= 1) {
        int tmp = (t >= off) ? s[t - off] : 0;
        __syncthreads();
        s[t] += tmp;
        __syncthreads();
    }
    if (t < nb) bsum[t] = s[t] - v;
}

__global__ void scan3_k(int* __restrict__ ptr, const int* __restrict__ bsum,
                        int* __restrict__ cur, int n, int etot) {
    int i = blockIdx.x * blockDim.x + threadIdx.x;
    if (i < n) {
        int p = ptr[i] + bsum[i >> 9];
        ptr[i] = p;
        cur[i] = p;
    }
    if (i == 0) ptr[n] = etot;
}

__global__ void fill_k(const int* __restrict__ row, const int* __restrict__ col,
                       int* __restrict__ cur, int* __restrict__ rows, int e) {
    int i = blockIdx.x * blockDim.x + threadIdx.x;
    if (i < e) {
        int c = col[i];
        int p = atomicAdd(&cur[c], 1);
        rows[p] = row[i];
    }
}

// ---------------------------------------------------------------------------
// SGEMM: OUT[M, ldW] = X[M, K] @ W[K, ldW], 128-row tiles, FT-wide col tiles.
// 256 threads (16x16), thread microtile 8 x (FT/16).
// ---------------------------------------------------------------------------
template<int K, int FT>
__global__ __launch_bounds__(256)
void sgemm_k(const float* __restrict__ X, const float* __restrict__ W,
             const float* __restrict__ bias, float* __restrict__ OUT,
             int M, int ldW, int doRelu) {
    constexpr int KC = 32;
    constexpr int TN = FT / 16;
    __shared__ float Xs[KC][132];   // transposed, padded
    __shared__ float Ws[KC][FT];

    int tid = threadIdx.x;
    int tx = tid & 15, ty = tid >> 4;
    int rowBase = blockIdx.x * 128;
    int cBase = blockIdx.y * FT;

    float acc[8][TN];
#pragma unroll
    for (int i = 0; i < 8; ++i)
#pragma unroll
        for (int j = 0; j < TN; ++j) acc[i][j] = 0.0f;

    for (int k0 = 0; k0 < K; k0 += KC) {
        // Load X tile transposed: Xs[k][r]
#pragma unroll
        for (int p = 0; p < 4; ++p) {
            int id = tid + p * 256;      // 0..1023
            int r = id >> 3;             // 0..127
            int k4 = id & 7;             // 0..7 (float4 idx within 32 k's)
            float4 xv = make_float4(0.f, 0.f, 0.f, 0.f);
            int grow = rowBase + r;
            if (grow < M)
                xv = *(const float4*)(X + (size_t)grow * K + k0 + k4 * 4);
            Xs[k4 * 4 + 0][r] = xv.x;
            Xs[k4 * 4 + 1][r] = xv.y;
            Xs[k4 * 4 + 2][r] = xv.z;
            Xs[k4 * 4 + 3][r] = xv.w;
        }
        // Load W tile
        for (int id = tid; id < KC * FT / 4; id += 256) {
            int kk = (id * 4) / FT;
            int c  = (id * 4) % FT;
            *(float4*)&Ws[kk][c] =
                *(const float4*)(W + (size_t)(k0 + kk) * ldW + cBase + c);
        }
        __syncthreads();

#pragma unroll 8
        for (int kk = 0; kk < KC; ++kk) {
            float xr[8];
            float4 a = *(const float4*)&Xs[kk][ty * 8];
            float4 b = *(const float4*)&Xs[kk][ty * 8 + 4];
            xr[0] = a.x; xr[1] = a.y; xr[2] = a.z; xr[3] = a.w;
            xr[4] = b.x; xr[5] = b.y; xr[6] = b.z; xr[7] = b.w;
            float wv[TN];
            if (TN == 8) {
                float4 w0 = *(const float4*)&Ws[kk][tx * 8];
                float4 w1 = *(const float4*)&Ws[kk][tx * 8 + 4];
                wv[0] = w0.x; wv[1] = w0.y; wv[2] = w0.z; wv[3] = w0.w;
                wv[4] = w1.x; wv[5] = w1.y; wv[6] = w1.z; wv[7] = w1.w;
            } else if (TN == 4) {
                float4 w0 = *(const float4*)&Ws[kk][tx * 4];
                wv[0] = w0.x; wv[1] = w0.y; wv[2] = w0.z; wv[3] = w0.w;
            } else {  // TN == 2
                float2 w0 = *(const float2*)&Ws[kk][tx * 2];
                wv[0] = w0.x; wv[1] = w0.y;
            }
#pragma unroll
            for (int i = 0; i < 8; ++i)
#pragma unroll
                for (int j = 0; j < TN; ++j)
                    acc[i][j] += xr[i] * wv[j];
        }
        __syncthreads();
    }

#pragma unroll
    for (int i = 0; i < 8; ++i) {
        int grow = rowBase + ty * 8 + i;
        if (grow >= M) continue;
#pragma unroll
        for (int j = 0; j < TN; ++j) {
            int c = cBase + tx * TN + j;
            float v = acc[i][j];
            if (bias) v += bias[c];
            if (doRelu) v = fmaxf(v, 0.0f);
            OUT[(size_t)grow * ldW + c] = v;
        }
    }
}

// ---------------------------------------------------------------------------
// Pull-based GCN propagation: OUT[n] = relu( sum_{e:col=n} dinv[row]*dinv[n]*H[row]
//                                            + dinv[n]^2*H[n] + bias )
// One warp per node. F in {128, 64, 32}.
// ---------------------------------------------------------------------------
template<int F>
__global__ __launch_bounds__(256)
void prop_k(const float* __restrict__ H, const int* __restrict__ ptr,
            const int* __restrict__ rows, const float* __restrict__ dinv,
            const float* __restrict__ bias, float* __restrict__ OUT, int n) {
    constexpr int V = F / 32;
    int warp = (blockIdx.x * blockDim.x + threadIdx.x) >> 5;
    int lane = threadIdx.x & 31;
    if (warp >= n) return;

    const float dn = dinv[warp];
    const float selfw = dn * dn;
    float acc[V];
    const float* hp = H + (size_t)warp * F + lane * V;
    if (V == 4) {
        float4 v = *(const float4*)hp;
        acc[0] = selfw * v.x; acc[1] = selfw * v.y;
        acc[2] = selfw * v.z; acc[3] = selfw * v.w;
    } else if (V == 2) {
        float2 v = *(const float2*)hp;
        acc[0] = selfw * v.x; acc[1] = selfw * v.y;
    } else {
        acc[0] = selfw * hp[0];
    }

    int beg = ptr[warp], end = ptr[warp + 1];
    for (int j0 = beg; j0 < end; j0 += 32) {
        int j = j0 + lane;
        int r = 0; float dv = 0.0f;
        if (j < end) { r = rows[j]; dv = dinv[r]; }
        int cnt = min(32, end - j0);
        for (int t = 0; t < cnt; ++t) {
            int rr  = __shfl_sync(0xffffffffu, r,  t);
            float w = __shfl_sync(0xffffffffu, dv, t) * dn;
            const float* q = H + (size_t)rr * F + lane * V;
            if (V == 4) {
                float4 v = *(const float4*)q;
                acc[0] += w * v.x; acc[1] += w * v.y;
                acc[2] += w * v.z; acc[3] += w * v.w;
            } else if (V == 2) {
                float2 v = *(const float2*)q;
                acc[0] += w * v.x; acc[1] += w * v.y;
            } else {
                acc[0] += w * q[0];
            }
        }
    }

    float* o = OUT + (size_t)warp * F + lane * V;
    if (V == 4) {
        float4 v;
        v.x = fmaxf(acc[0] + bias[lane * 4 + 0], 0.0f);
        v.y = fmaxf(acc[1] + bias[lane * 4 + 1], 0.0f);
        v.z = fmaxf(acc[2] + bias[lane * 4 + 2], 0.0f);
        v.w = fmaxf(acc[3] + bias[lane * 4 + 3], 0.0f);
        *(float4*)o = v;
    } else if (V == 2) {
        float2 v;
        v.x = fmaxf(acc[0] + bias[lane * 2 + 0], 0.0f);
        v.y = fmaxf(acc[1] + bias[lane * 2 + 1], 0.0f);
        *(float2*)o = v;
    } else {
        o[0] = fmaxf(acc[0] + bias[lane], 0.0f);
    }
}

// F=1 propagation (scalar features)
__global__ __launch_bounds__(256)
void prop1_k(const float* __restrict__ H, const int* __restrict__ ptr,
             const int* __restrict__ rows, const float* __restrict__ dinv,
             const float* __restrict__ bias, float* __restrict__ OUT, int n) {
    int warp = (blockIdx.x * blockDim.x + threadIdx.x) >> 5;
    int lane = threadIdx.x & 31;
    if (warp >= n) return;
    float dn = dinv[warp];
    int beg = ptr[warp], end = ptr[warp + 1];
    float acc = 0.0f;
    for (int j = beg + lane; j < end; j += 32) {
        int r = rows[j];
        acc += dinv[r] * H[r];
    }
#pragma unroll
    for (int o = 16; o; o >>= 1) acc += __shfl_down_sync(0xffffffffu, acc, o);
    if (lane == 0) {
        float v = acc * dn + dn * dn * H[warp] + bias[0];
        OUT[warp] = fmaxf(v, 0.0f);
    }
}

// dot: out[n] = H[n,0:32] . w[0:32]   (Wa3 GEMM, FOUT=1)
__global__ __launch_bounds__(256)
void dot32_k(const float* __restrict__ H, const float* __restrict__ w,
             float* __restrict__ out, int n) {
    int warp = (blockIdx.x * blockDim.x + threadIdx.x) >> 5;
    int lane = threadIdx.x & 31;
    if (warp >= n) return;
    float v = H[(size_t)warp * 32 + lane] * w[lane];
#pragma unroll
    for (int o = 16; o; o >>= 1) v += __shfl_down_sync(0xffffffffu, v, o);
    if (lane == 0) out[warp] = v;
}

// segment softmax pieces (w >= 0 after relu, so uint atomicMax is order-preserving)
__global__ void segmax_k(const float* __restrict__ w, const int* __restrict__ batch,
                         float* __restrict__ gmax, int n) {
    int i = blockIdx.x * blockDim.x + threadIdx.x;
    if (i < n) atomicMax((unsigned int*)&gmax[batch[i]], __float_as_uint(w[i]));
}

__global__ void expsum_k(const float* __restrict__ w, const int* __restrict__ batch,
                         const float* __restrict__ gmax, float* __restrict__ ew,
                         float* __restrict__ gsum, int n) {
    int i = blockIdx.x * blockDim.x + threadIdx.x;
    if (i < n) {
        int b = batch[i];
        float e = expf(w[i] - gmax[b]);
        ew[i] = e;
        atomicAdd(&gsum[b], e);
    }
}

__global__ __launch_bounds__(256)
void pool_k(const float* __restrict__ x3, const float* __restrict__ ew,
            const float* __restrict__ gsum, const int* __restrict__ batch,
            float* __restrict__ pooled, int n) {
    int warp = (blockIdx.x * blockDim.x + threadIdx.x) >> 5;
    int lane = threadIdx.x & 31;
    if (warp >= n) return;
    int b = batch[warp];
    float coef = ew[warp] / (gsum[b] + 1e-16f);
    float4 xv = *(const float4*)(x3 + (size_t)warp * 128 + lane * 4);
    float* pb = pooled + b * 128 + lane * 4;
    atomicAdd(pb + 0, coef * xv.x);
    atomicAdd(pb + 1, coef * xv.y);
    atomicAdd(pb + 2, coef * xv.z);
    atomicAdd(pb + 3, coef * xv.w);
}

// ---------------------------------------------------------------------------
// Host launcher
// ---------------------------------------------------------------------------
extern "C" void kernel_launch(void* const* d_in, const int* in_sizes, int n_in,
                              void* d_out, int out_size) {
    const float* x     = (const float*)d_in[0];
    const int*   ei    = (const int*)d_in[1];
    const int*   batch = (const int*)d_in[2];
    const float* W1 = (const float*)d_in[3];   const float* b1 = (const float*)d_in[4];
    const float* W2 = (const float*)d_in[5];   const float* b2 = (const float*)d_in[6];
    const float* W3 = (const float*)d_in[7];   const float* b3 = (const float*)d_in[8];
    const float* Wa1 = (const float*)d_in[9];  const float* ba1 = (const float*)d_in[10];
    const float* Wa2 = (const float*)d_in[11]; const float* ba2 = (const float*)d_in[12];
    const float* Wa3 = (const float*)d_in[13]; const float* ba3 = (const float*)d_in[14];
    const float* Wm1 = (const float*)d_in[15]; const float* bm1 = (const float*)d_in[16];
    const float* Wm2 = (const float*)d_in[17]; const float* bm2 = (const float*)d_in[18];

    int N = in_sizes[0] / 128;
    int E = in_sizes[1] / 2;
    const int* row = ei;
    const int* col = ei + E;

    float *B0, *B1, *B2, *wv, *dinv, *gmax, *gsum, *pooled, *hbuf;
    int *cnt, *ptr, *cur, *rows, *bsum;
    cudaGetSymbolAddress((void**)&B0, g_B0);
    cudaGetSymbolAddress((void**)&B1, g_B1);
    cudaGetSymbolAddress((void**)&B2, g_B2);
    cudaGetSymbolAddress((void**)&wv, g_w);
    cudaGetSymbolAddress((void**)&dinv, g_dinv);
    cudaGetSymbolAddress((void**)&cnt, g_cnt);
    cudaGetSymbolAddress((void**)&ptr, g_ptr);
    cudaGetSymbolAddress((void**)&cur, g_cur);
    cudaGetSymbolAddress((void**)&rows, g_rows);
    cudaGetSymbolAddress((void**)&bsum, g_bsum);
    cudaGetSymbolAddress((void**)&gmax, g_gmax);
    cudaGetSymbolAddress((void**)&gsum, g_gsum);
    cudaGetSymbolAddress((void**)&pooled, g_pooled);
    cudaGetSymbolAddress((void**)&hbuf, g_h);

    int NB = (N + 511) / 512;
    int nInit = (N > 256 * 128) ? N : 256 * 128;

    // --- build CSC + norms ---
    init_k<<<(nInit + 255) / 256, 256>>>(cnt, gmax, gsum, pooled, N);
    count_k<<<(E + 255) / 256, 256>>>(col, cnt, E);
    dinv_k<<<(N + 255) / 256, 256>>>(cnt, dinv, N);
    scan1_k<<<NB, 512>>>(cnt, ptr, bsum, N);
    scan2_k<<<1, 512>>>(bsum, NB);
    scan3_k<<<(N + 255) / 256, 256>>>(ptr, bsum, cur, N, E);
    fill_k<<<(E + 255) / 256, 256>>>(row, col, cur, rows, E);

    dim3 g128((N + 127) / 128, 1);
    int propBlocks = (N + 7) / 8;   // warp per node, 8 warps/block

    // --- 3 GCN layers (128 -> 128) ---
    sgemm_k<128, 128><<<g128, 256>>>(x,  W1, nullptr, B0, N, 128, 0);
    prop_k<128><<<propBlocks, 256>>>(B0, ptr, rows, dinv, b1, B1, N);
    sgemm_k<128, 128><<<g128, 256>>>(B1, W2, nullptr, B0, N, 128, 0);
    prop_k<128><<<propBlocks, 256>>>(B0, ptr, rows, dinv, b2, B1, N);
    sgemm_k<128, 128><<<g128, 256>>>(B1, W3, nullptr, B0, N, 128, 0);
    prop_k<128><<<propBlocks, 256>>>(B0, ptr, rows, dinv, b3, B2, N);   // B2 = x3

    // --- attention branch (128 -> 64 -> 32 -> 1) ---
    sgemm_k<128, 64><<<g128, 256>>>(B2, Wa1, nullptr, B0, N, 64, 0);
    prop_k<64><<<propBlocks, 256>>>(B0, ptr, rows, dinv, ba1, B1, N);
    sgemm_k<64, 32><<<g128, 256>>>(B1, Wa2, nullptr, B0, N, 32, 0);
    prop_k<32><<<propBlocks, 256>>>(B0, ptr, rows, dinv, ba2, B1, N);
    dot32_k<<<propBlocks, 256>>>(B1, Wa3, B0, N);
    prop1_k<<<propBlocks, 256>>>(B0, ptr, rows, dinv, ba3, wv, N);

    // --- segment softmax + attention pooling ---
    segmax_k<<<(N + 255) / 256, 256>>>(wv, batch, gmax, N);
    expsum_k<<<(N + 255) / 256, 256>>>(wv, batch, gmax, B0, gsum, N);
    pool_k<<<propBlocks, 256>>>(B2, B0, gsum, batch, pooled, N);

    // --- MLP head ---
    sgemm_k<128, 128><<<dim3(2, 1), 256>>>(pooled, Wm1, bm1, hbuf, 256, 128, 1);
    sgemm_k<128, 128><<<dim3(2, 2), 256>>>(hbuf, Wm2, bm2, (float*)d_out, 256, 256, 0);
}

// round 3
// speedup vs baseline: 1.1254x; 1.1254x over previous
#include <cuda_runtime.h>
#include <cuda_bf16.h>
#include <cstdint>

// ---------------------------------------------------------------------------
// Static scratch (no allocation allowed)
// ---------------------------------------------------------------------------
#define NMAX 100000
#define EMAX 1600000

__device__ float g_B0[NMAX * 128];
__device__ float g_B1[NMAX * 128];
__device__ float g_B2[NMAX * 128];
__device__ float g_w [NMAX];
__device__ float g_dinv[NMAX];
__device__ int   g_cnt[NMAX];
__device__ int   g_ptr[NMAX + 1];
__device__ int   g_cur[NMAX];
__device__ int   g_rows[EMAX];
__device__ int   g_bsum[512];
__device__ float g_gmax[256];
__device__ float g_gsum[256];
__device__ float g_pooled[256 * 128];
__device__ float g_h[256 * 128];
__device__ __nv_bfloat16 g_Wthi[65536];
__device__ __nv_bfloat16 g_Wtlo[65536];

// ---------------------------------------------------------------------------
// Warp-MMA helpers (portable PTX: ldmatrix + mma.sync, valid on sm_103 target)
// ---------------------------------------------------------------------------
__device__ __forceinline__ uint32_t smem_u32(const void* p) {
    uint32_t a;
    asm("{ .reg .u64 t; cvta.to.shared.u64 t, %1; cvt.u32.u64 %0, t; }"
        : "=r"(a) : "l"(p));
    return a;
}

__device__ __forceinline__ void ldsm_x4(uint32_t& r0, uint32_t& r1,
                                        uint32_t& r2, uint32_t& r3, uint32_t addr) {
    asm volatile("ldmatrix.sync.aligned.m8n8.x4.shared.b16 {%0,%1,%2,%3}, [%4];"
                 : "=r"(r0), "=r"(r1), "=r"(r2), "=r"(r3) : "r"(addr));
}

__device__ __forceinline__ void mma_bf16(float* c, uint32_t a0, uint32_t a1,
                                         uint32_t a2, uint32_t a3,
                                         uint32_t b0, uint32_t b1) {
    asm volatile(
        "mma.sync.aligned.m16n8k16.row.col.f32.bf16.bf16.f32 "
        "{%0,%1,%2,%3}, {%4,%5,%6,%7}, {%8,%9}, {%0,%1,%2,%3};"
        : "+f"(c[0]), "+f"(c[1]), "+f"(c[2]), "+f"(c[3])
        : "r"(a0), "r"(a1), "r"(a2), "r"(a3), "r"(b0), "r"(b1));
}

// ---------------------------------------------------------------------------
// Weight prep: transpose to WT[n][k] (row-major, k contiguous), fp32 -> bf16
// hi/lo split. W is [K, N] row-major.
// ---------------------------------------------------------------------------
__global__ void wprep_k(const float* __restrict__ W, int K, int N,
                        __nv_bfloat16* __restrict__ hi, __nv_bfloat16* __restrict__ lo) {
    int idx = blockIdx.x * blockDim.x + threadIdx.x;
    if (idx >= N * K) return;
    int n = idx / K, k = idx % K;
    float v = W[(size_t)k * N + n];
    __nv_bfloat16 h = __float2bfloat16(v);
    __nv_bfloat16 l = __float2bfloat16(v - __bfloat162float(h));
    hi[idx] = h;
    lo[idx] = l;
}

// ---------------------------------------------------------------------------
// Tensor-core GEMM (HMMA): OUT[M, N] = X[M, K(fp32)] @ W[K, N]
// via bf16 hi/lo split (3 accumulation passes).
// 256 threads, 8 warps; 128-row tile per block; warp owns 16 rows x all N.
// ---------------------------------------------------------------------------
template<int K, int N>
__global__ __launch_bounds__(256)
void hgemm_k(const float* __restrict__ X,
             const __nv_bfloat16* __restrict__ WThi,
             const __nv_bfloat16* __restrict__ WTlo,
             float* __restrict__ OUT, int M) {
    extern __shared__ char smem[];
    constexpr int SA = K * 2 + 16;          // padded row stride (bytes), 16B-mult
    constexpr int A_HI = 0;
    constexpr int A_LO = 128 * SA;
    constexpr int B_HI = 2 * 128 * SA;
    constexpr int B_LO = B_HI + N * SA;

    const int tid = threadIdx.x;
    const int warp = tid >> 5;
    const int lane = tid & 31;
    const int rowBase = blockIdx.x * 128;
    const uint32_t sb = smem_u32(smem);

    // ---- stage W hi/lo into padded smem rows (uint2 = 4 bf16) ----
    for (int i = tid; i < N * K / 4; i += 256) {
        int n = i / (K / 4);
        int kq = i % (K / 4);
        *(uint2*)(smem + B_HI + n * SA + kq * 8) = ((const uint2*)WThi)[i];
        *(uint2*)(smem + B_LO + n * SA + kq * 8) = ((const uint2*)WTlo)[i];
    }

    // ---- stage X: fp32 -> bf16 hi/lo, padded rows ----
    for (int item = tid; item < 128 * (K / 8); item += 256) {
        int r = item / (K / 8);
        int k0 = (item % (K / 8)) * 8;
        float v[8];
        int grow = rowBase + r;
        if (grow < M) {
            const float4* p = (const float4*)(X + (size_t)grow * K + k0);
            float4 a = p[0], b = p[1];
            v[0] = a.x; v[1] = a.y; v[2] = a.z; v[3] = a.w;
            v[4] = b.x; v[5] = b.y; v[6] = b.z; v[7] = b.w;
        } else {
#pragma unroll
            for (int j = 0; j < 8; ++j) v[j] = 0.0f;
        }
        uint32_t hw[4], lw[4];
#pragma unroll
        for (int j = 0; j < 4; ++j) {
            __nv_bfloat16 h0 = __float2bfloat16(v[2 * j]);
            __nv_bfloat16 h1 = __float2bfloat16(v[2 * j + 1]);
            __nv_bfloat162 hp; hp.x = h0; hp.y = h1;
            __nv_bfloat162 lp;
            lp.x = __float2bfloat16(v[2 * j]     - __bfloat162float(h0));
            lp.y = __float2bfloat16(v[2 * j + 1] - __bfloat162float(h1));
            hw[j] = *(uint32_t*)&hp;
            lw[j] = *(uint32_t*)&lp;
        }
        *(uint4*)(smem + A_HI + r * SA + k0 * 2) = make_uint4(hw[0], hw[1], hw[2], hw[3]);
        *(uint4*)(smem + A_LO + r * SA + k0 * 2) = make_uint4(lw[0], lw[1], lw[2], lw[3]);
    }
    __syncthreads();

    // ---- compute ----
    constexpr int NT = N / 8;               // 8-col accum tiles
    float acc[NT][4];
#pragma unroll
    for (int i = 0; i < NT; ++i)
#pragma unroll
        for (int j = 0; j < 4; ++j) acc[i][j] = 0.0f;

    const int m0 = warp * 16;
    const int q = lane >> 3;                // ldmatrix matrix id
    const int r8 = lane & 7;

    // A lane address: matrix q -> row +8*(q&1), k +8*(q>>1)
    const uint32_t aRowOff = (uint32_t)(m0 + (q & 1) * 8 + r8) * SA + (uint32_t)(q >> 1) * 16;
    // B lane address: matrix q -> n +8*(q>>1) (next tile), k +8*(q&1)
    const uint32_t bRowIdx = (uint32_t)((q >> 1) * 8 + r8);
    const uint32_t bKOff = (uint32_t)(q & 1) * 16;

    const uint32_t abase[3] = { sb + A_HI, sb + A_LO, sb + A_HI };
    const uint32_t bbase[3] = { sb + B_HI, sb + B_HI, sb + B_LO };

#pragma unroll
    for (int p = 0; p < 3; ++p) {
        const uint32_t ab = abase[p] + aRowOff;
        const uint32_t bb = bbase[p] + bRowIdx * SA + bKOff;
#pragma unroll
        for (int kc = 0; kc < K / 16; ++kc) {
            uint32_t a0, a1, a2, a3;
            ldsm_x4(a0, a1, a2, a3, ab + kc * 32);
#pragma unroll
            for (int nt2 = 0; nt2 < N / 16; ++nt2) {
                uint32_t b0, b1, b2, b3;
                ldsm_x4(b0, b1, b2, b3, bb + (uint32_t)(nt2 * 16) * SA + kc * 32);
                mma_bf16(acc[2 * nt2],     a0, a1, a2, a3, b0, b1);
                mma_bf16(acc[2 * nt2 + 1], a0, a1, a2, a3, b2, b3);
            }
        }
    }

    // ---- epilogue: c0,c1 -> row lane/4; c2,c3 -> row+8; cols nt*8+(lane%4)*2 ----
    const int row0 = rowBase + m0 + (lane >> 2);
    const int row1 = row0 + 8;
    const int cb = (lane & 3) * 2;
#pragma unroll
    for (int nt = 0; nt < NT; ++nt) {
        if (row0 < M)
            *(float2*)(OUT + (size_t)row0 * N + nt * 8 + cb) = make_float2(acc[nt][0], acc[nt][1]);
        if (row1 < M)
            *(float2*)(OUT + (size_t)row1 * N + nt * 8 + cb) = make_float2(acc[nt][2], acc[nt][3]);
    }
}

// ---------------------------------------------------------------------------
// Small utility kernels (CSC build, norms)
// ---------------------------------------------------------------------------
__global__ void init_k(int* cnt, float* gmax, float* gsum, float* pooled, int n) {
    int i = blockIdx.x * blockDim.x + threadIdx.x;
    if (i < n) cnt[i] = 0;
    if (i < 256) { gmax[i] = 0.0f; gsum[i] = 0.0f; }
    if (i < 256 * 128) pooled[i] = 0.0f;
}

__global__ void count_k(const int* __restrict__ col, int* __restrict__ cnt, int e) {
    int i = blockIdx.x * blockDim.x + threadIdx.x;
    if (i < e) atomicAdd(&cnt[col[i]], 1);
}

__global__ void dinv_k(const int* __restrict__ cnt, float* __restrict__ dinv, int n) {
    int i = blockIdx.x * blockDim.x + threadIdx.x;
    if (i < n) dinv[i] = rsqrtf((float)cnt[i] + 1.0f);   // +1 = self loop
}

__global__ void scan1_k(const int* __restrict__ cnt, int* __restrict__ ptr,
                        int* __restrict__ bsum, int n) {
    __shared__ int s[512];
    int t = threadIdx.x;
    int i = blockIdx.x * 512 + t;
    int v = (i < n) ? cnt[i] : 0;
    s[t] = v; __syncthreads();
    for (int off = 1; off < 512; off <<= 1) {
        int tmp = (t >= off) ? s[t - off] : 0;
        __syncthreads();
        s[t] += tmp;
        __syncthreads();
    }
    if (i < n) ptr[i] = s[t] - v;
    if (t == 511) bsum[blockIdx.x] = s[511];
}

__global__ void scan2_k(int* __restrict__ bsum, int nb) {
    __shared__ int s[512];
    int t = threadIdx.x;
    int v = (t < nb) ? bsum[t] : 0;
    s[t] = v; __syncthreads();
    for (int off = 1; off < 512; off <<= 1) {
        int tmp = (t >= off) ? s[t - off] : 0;
        __syncthreads();
        s[t] += tmp;
        __syncthreads();
    }
    if (t < nb) bsum[t] = s[t] - v;
}

__global__ void scan3_k(int* __restrict__ ptr, const int* __restrict__ bsum,
                        int* __restrict__ cur, int n, int etot) {
    int i = blockIdx.x * blockDim.x + threadIdx.x;
    if (i < n) {
        int p = ptr[i] + bsum[i >> 9];
        ptr[i] = p;
        cur[i] = p;
    }
    if (i == 0) ptr[n] = etot;
}

__global__ void fill_k(const int* __restrict__ row, const int* __restrict__ col,
                       int* __restrict__ cur, int* __restrict__ rows, int e) {
    int i = blockIdx.x * blockDim.x + threadIdx.x;
    if (i < e) {
        int c = col[i];
        int p = atomicAdd(&cur[c], 1);
        rows[p] = row[i];
    }
}

// ---------------------------------------------------------------------------
// SIMT SGEMM (kept for the tiny MLP head only)
// ---------------------------------------------------------------------------
template<int K, int FT>
__global__ __launch_bounds__(256)
void sgemm_k(const float* __restrict__ X, const float* __restrict__ W,
             const float* __restrict__ bias, float* __restrict__ OUT,
             int M, int ldW, int doRelu) {
    constexpr int KC = 32;
    constexpr int TN = FT / 16;
    __shared__ float Xs[KC][132];
    __shared__ float Ws[KC][FT];

    int tid = threadIdx.x;
    int tx = tid & 15, ty = tid >> 4;
    int rowBase = blockIdx.x * 128;
    int cBase = blockIdx.y * FT;

    float acc[8][TN];
#pragma unroll
    for (int i = 0; i < 8; ++i)
#pragma unroll
        for (int j = 0; j < TN; ++j) acc[i][j] = 0.0f;

    for (int k0 = 0; k0 < K; k0 += KC) {
#pragma unroll
        for (int p = 0; p < 4; ++p) {
            int id = tid + p * 256;
            int r = id >> 3;
            int k4 = id & 7;
            float4 xv = make_float4(0.f, 0.f, 0.f, 0.f);
            int grow = rowBase + r;
            if (grow < M)
                xv = *(const float4*)(X + (size_t)grow * K + k0 + k4 * 4);
            Xs[k4 * 4 + 0][r] = xv.x;
            Xs[k4 * 4 + 1][r] = xv.y;
            Xs[k4 * 4 + 2][r] = xv.z;
            Xs[k4 * 4 + 3][r] = xv.w;
        }
        for (int id = tid; id < KC * FT / 4; id += 256) {
            int kk = (id * 4) / FT;
            int c  = (id * 4) % FT;
            *(float4*)&Ws[kk][c] =
                *(const float4*)(W + (size_t)(k0 + kk) * ldW + cBase + c);
        }
        __syncthreads();

#pragma unroll 8
        for (int kk = 0; kk < KC; ++kk) {
            float xr[8];
            float4 a = *(const float4*)&Xs[kk][ty * 8];
            float4 b = *(const float4*)&Xs[kk][ty * 8 + 4];
            xr[0] = a.x; xr[1] = a.y; xr[2] = a.z; xr[3] = a.w;
            xr[4] = b.x; xr[5] = b.y; xr[6] = b.z; xr[7] = b.w;
            float wv[TN];
            float4 w0 = *(const float4*)&Ws[kk][tx * 8];
            float4 w1 = *(const float4*)&Ws[kk][tx * 8 + 4];
            wv[0] = w0.x; wv[1] = w0.y; wv[2] = w0.z; wv[3] = w0.w;
            wv[4] = w1.x; wv[5] = w1.y; wv[6] = w1.z; wv[7] = w1.w;
#pragma unroll
            for (int i = 0; i < 8; ++i)
#pragma unroll
                for (int j = 0; j < TN; ++j)
                    acc[i][j] += xr[i] * wv[j];
        }
        __syncthreads();
    }

#pragma unroll
    for (int i = 0; i < 8; ++i) {
        int grow = rowBase + ty * 8 + i;
        if (grow >= M) continue;
#pragma unroll
        for (int j = 0; j < TN; ++j) {
            int c = cBase + tx * TN + j;
            float v = acc[i][j];
            if (bias) v += bias[c];
            if (doRelu) v = fmaxf(v, 0.0f);
            OUT[(size_t)grow * ldW + c] = v;
        }
    }
}

// ---------------------------------------------------------------------------
// Pull-based GCN propagation
// ---------------------------------------------------------------------------
template<int F>
__global__ __launch_bounds__(256)
void prop_k(const float* __restrict__ H, const int* __restrict__ ptr,
            const int* __restrict__ rows, const float* __restrict__ dinv,
            const float* __restrict__ bias, float* __restrict__ OUT, int n) {
    constexpr int V = F / 32;
    int warp = (blockIdx.x * blockDim.x + threadIdx.x) >> 5;
    int lane = threadIdx.x & 31;
    if (warp >= n) return;

    const float dn = dinv[warp];
    const float selfw = dn * dn;
    float acc[V];
    const float* hp = H + (size_t)warp * F + lane * V;
    if (V == 4) {
        float4 v = *(const float4*)hp;
        acc[0] = selfw * v.x; acc[1] = selfw * v.y;
        acc[2] = selfw * v.z; acc[3] = selfw * v.w;
    } else if (V == 2) {
        float2 v = *(const float2*)hp;
        acc[0] = selfw * v.x; acc[1] = selfw * v.y;
    } else {
        acc[0] = selfw * hp[0];
    }

    int beg = ptr[warp], end = ptr[warp + 1];
    for (int j0 = beg; j0 < end; j0 += 32) {
        int j = j0 + lane;
        int r = 0; float dv = 0.0f;
        if (j < end) { r = rows[j]; dv = dinv[r]; }
        int cnt = min(32, end - j0);
        for (int t = 0; t < cnt; ++t) {
            int rr  = __shfl_sync(0xffffffffu, r,  t);
            float w = __shfl_sync(0xffffffffu, dv, t) * dn;
            const float* q = H + (size_t)rr * F + lane * V;
            if (V == 4) {
                float4 v = *(const float4*)q;
                acc[0] += w * v.x; acc[1] += w * v.y;
                acc[2] += w * v.z; acc[3] += w * v.w;
            } else if (V == 2) {
                float2 v = *(const float2*)q;
                acc[0] += w * v.x; acc[1] += w * v.y;
            } else {
                acc[0] += w * q[0];
            }
        }
    }

    float* o = OUT + (size_t)warp * F + lane * V;
    if (V == 4) {
        float4 v;
        v.x = fmaxf(acc[0] + bias[lane * 4 + 0], 0.0f);
        v.y = fmaxf(acc[1] + bias[lane * 4 + 1], 0.0f);
        v.z = fmaxf(acc[2] + bias[lane * 4 + 2], 0.0f);
        v.w = fmaxf(acc[3] + bias[lane * 4 + 3], 0.0f);
        *(float4*)o = v;
    } else if (V == 2) {
        float2 v;
        v.x = fmaxf(acc[0] + bias[lane * 2 + 0], 0.0f);
        v.y = fmaxf(acc[1] + bias[lane * 2 + 1], 0.0f);
        *(float2*)o = v;
    } else {
        o[0] = fmaxf(acc[0] + bias[lane], 0.0f);
    }
}

__global__ __launch_bounds__(256)
void prop1_k(const float* __restrict__ H, const int* __restrict__ ptr,
             const int* __restrict__ rows, const float* __restrict__ dinv,
             const float* __restrict__ bias, float* __restrict__ OUT, int n) {
    int warp = (blockIdx.x * blockDim.x + threadIdx.x) >> 5;
    int lane = threadIdx.x & 31;
    if (warp >= n) return;
    float dn = dinv[warp];
    int beg = ptr[warp], end = ptr[warp + 1];
    float acc = 0.0f;
    for (int j = beg + lane; j < end; j += 32) {
        int r = rows[j];
        acc += dinv[r] * H[r];
    }
#pragma unroll
    for (int o = 16; o; o >>= 1) acc += __shfl_down_sync(0xffffffffu, acc, o);
    if (lane == 0) {
        float v = acc * dn + dn * dn * H[warp] + bias[0];
        OUT[warp] = fmaxf(v, 0.0f);
    }
}

__global__ __launch_bounds__(256)
void dot32_k(const float* __restrict__ H, const float* __restrict__ w,
             float* __restrict__ out, int n) {
    int warp = (blockIdx.x * blockDim.x + threadIdx.x) >> 5;
    int lane = threadIdx.x & 31;
    if (warp >= n) return;
    float v = H[(size_t)warp * 32 + lane] * w[lane];
#pragma unroll
    for (int o = 16; o; o >>= 1) v += __shfl_down_sync(0xffffffffu, v, o);
    if (lane == 0) out[warp] = v;
}

__global__ void segmax_k(const float* __restrict__ w, const int* __restrict__ batch,
                         float* __restrict__ gmax, int n) {
    int i = blockIdx.x * blockDim.x + threadIdx.x;
    if (i < n) atomicMax((unsigned int*)&gmax[batch[i]], __float_as_uint(w[i]));
}

__global__ void expsum_k(const float* __restrict__ w, const int* __restrict__ batch,
                         const float* __restrict__ gmax, float* __restrict__ ew,
                         float* __restrict__ gsum, int n) {
    int i = blockIdx.x * blockDim.x + threadIdx.x;
    if (i < n) {
        int b = batch[i];
        float e = expf(w[i] - gmax[b]);
        ew[i] = e;
        atomicAdd(&gsum[b], e);
    }
}

__global__ __launch_bounds__(256)
void pool_k(const float* __restrict__ x3, const float* __restrict__ ew,
            const float* __restrict__ gsum, const int* __restrict__ batch,
            float* __restrict__ pooled, int n) {
    int warp = (blockIdx.x * blockDim.x + threadIdx.x) >> 5;
    int lane = threadIdx.x & 31;
    if (warp >= n) return;
    int b = batch[warp];
    float coef = ew[warp] / (gsum[b] + 1e-16f);
    float4 xv = *(const float4*)(x3 + (size_t)warp * 128 + lane * 4);
    float* pb = pooled + b * 128 + lane * 4;
    atomicAdd(pb + 0, coef * xv.x);
    atomicAdd(pb + 1, coef * xv.y);
    atomicAdd(pb + 2, coef * xv.z);
    atomicAdd(pb + 3, coef * xv.w);
}

// ---------------------------------------------------------------------------
// Host launcher
// ---------------------------------------------------------------------------
extern "C" void kernel_launch(void* const* d_in, const int* in_sizes, int n_in,
                              void* d_out, int out_size) {
    const float* x     = (const float*)d_in[0];
    const int*   ei    = (const int*)d_in[1];
    const int*   batch = (const int*)d_in[2];
    const float* W1 = (const float*)d_in[3];   const float* b1 = (const float*)d_in[4];
    const float* W2 = (const float*)d_in[5];   const float* b2 = (const float*)d_in[6];
    const float* W3 = (const float*)d_in[7];   const float* b3 = (const float*)d_in[8];
    const float* Wa1 = (const float*)d_in[9];  const float* ba1 = (const float*)d_in[10];
    const float* Wa2 = (const float*)d_in[11]; const float* ba2 = (const float*)d_in[12];
    const float* Wa3 = (const float*)d_in[13]; const float* ba3 = (const float*)d_in[14];
    const float* Wm1 = (const float*)d_in[15]; const float* bm1 = (const float*)d_in[16];
    const float* Wm2 = (const float*)d_in[17]; const float* bm2 = (const float*)d_in[18];

    int N = in_sizes[0] / 128;
    int E = in_sizes[1] / 2;
    const int* row = ei;
    const int* col = ei + E;

    float *B0, *B1, *B2, *wv, *dinv, *gmax, *gsum, *pooled, *hbuf;
    int *cnt, *ptr, *cur, *rows, *bsum;
    __nv_bfloat16 *wthi, *wtlo;
    cudaGetSymbolAddress((void**)&B0, g_B0);
    cudaGetSymbolAddress((void**)&B1, g_B1);
    cudaGetSymbolAddress((void**)&B2, g_B2);
    cudaGetSymbolAddress((void**)&wv, g_w);
    cudaGetSymbolAddress((void**)&dinv, g_dinv);
    cudaGetSymbolAddress((void**)&cnt, g_cnt);
    cudaGetSymbolAddress((void**)&ptr, g_ptr);
    cudaGetSymbolAddress((void**)&cur, g_cur);
    cudaGetSymbolAddress((void**)&rows, g_rows);
    cudaGetSymbolAddress((void**)&bsum, g_bsum);
    cudaGetSymbolAddress((void**)&gmax, g_gmax);
    cudaGetSymbolAddress((void**)&gsum, g_gsum);
    cudaGetSymbolAddress((void**)&pooled, g_pooled);
    cudaGetSymbolAddress((void**)&hbuf, g_h);
    cudaGetSymbolAddress((void**)&wthi, g_Wthi);
    cudaGetSymbolAddress((void**)&wtlo, g_Wtlo);

    // dynamic smem: 2*128*SA (A hi/lo) + 2*N*SA (B hi/lo), SA = K*2+16
    const int SM_128_128 = 2 * 128 * 272 + 2 * 128 * 272;  // 139264
    const int SM_128_64  = 2 * 128 * 272 + 2 *  64 * 272;  // 104448
    const int SM_64_32   = 2 * 128 * 144 + 2 *  32 * 144;  //  46080
    cudaFuncSetAttribute(hgemm_k<128, 128>, cudaFuncAttributeMaxDynamicSharedMemorySize, SM_128_128);
    cudaFuncSetAttribute(hgemm_k<128, 64>,  cudaFuncAttributeMaxDynamicSharedMemorySize, SM_128_64);
    cudaFuncSetAttribute(hgemm_k<64, 32>,   cudaFuncAttributeMaxDynamicSharedMemorySize, SM_64_32);

    int NB = (N + 511) / 512;
    int nInit = (N > 256 * 128) ? N : 256 * 128;

    // --- build CSC + norms ---
    init_k<<<(nInit + 255) / 256, 256>>>(cnt, gmax, gsum, pooled, N);
    count_k<<<(E + 255) / 256, 256>>>(col, cnt, E);
    dinv_k<<<(N + 255) / 256, 256>>>(cnt, dinv, N);
    scan1_k<<<NB, 512>>>(cnt, ptr, bsum, N);
    scan2_k<<<1, 512>>>(bsum, NB);
    scan3_k<<<(N + 255) / 256, 256>>>(ptr, bsum, cur, N, E);
    fill_k<<<(E + 255) / 256, 256>>>(row, col, cur, rows, E);

    // --- prep weights: transpose + bf16 split ---
    // offsets (elements): W1:0  W2:16384  W3:32768  Wa1:49152  Wa2:57344
    wprep_k<<<64, 256>>>(W1, 128, 128, wthi + 0,     wtlo + 0);
    wprep_k<<<64, 256>>>(W2, 128, 128, wthi + 16384, wtlo + 16384);
    wprep_k<<<64, 256>>>(W3, 128, 128, wthi + 32768, wtlo + 32768);
    wprep_k<<<32, 256>>>(Wa1, 128, 64, wthi + 49152, wtlo + 49152);
    wprep_k<<<8, 256>>>(Wa2, 64, 32,   wthi + 57344, wtlo + 57344);

    int MT = (N + 127) / 128;
    int propBlocks = (N + 7) / 8;

    // --- 3 GCN layers (128 -> 128) ---
    hgemm_k<128, 128><<<MT, 256, SM_128_128>>>(x,  wthi + 0,     wtlo + 0,     B0, N);
    prop_k<128><<<propBlocks, 256>>>(B0, ptr, rows, dinv, b1, B1, N);
    hgemm_k<128, 128><<<MT, 256, SM_128_128>>>(B1, wthi + 16384, wtlo + 16384, B0, N);
    prop_k<128><<<propBlocks, 256>>>(B0, ptr, rows, dinv, b2, B1, N);
    hgemm_k<128, 128><<<MT, 256, SM_128_128>>>(B1, wthi + 32768, wtlo + 32768, B0, N);
    prop_k<128><<<propBlocks, 256>>>(B0, ptr, rows, dinv, b3, B2, N);   // B2 = x3

    // --- attention branch (128 -> 64 -> 32 -> 1) ---
    hgemm_k<128, 64><<<MT, 256, SM_128_64>>>(B2, wthi + 49152, wtlo + 49152, B0, N);
    prop_k<64><<<propBlocks, 256>>>(B0, ptr, rows, dinv, ba1, B1, N);
    hgemm_k<64, 32><<<MT, 256, SM_64_32>>>(B1, wthi + 57344, wtlo + 57344, B0, N);
    prop_k<32><<<propBlocks, 256>>>(B0, ptr, rows, dinv, ba2, B1, N);
    dot32_k<<<propBlocks, 256>>>(B1, Wa3, B0, N);
    prop1_k<<<propBlocks, 256>>>(B0, ptr, rows, dinv, ba3, wv, N);

    // --- segment softmax + attention pooling ---
    segmax_k<<<(N + 255) / 256, 256>>>(wv, batch, gmax, N);
    expsum_k<<<(N + 255) / 256, 256>>>(wv, batch, gmax, B0, gsum, N);
    pool_k<<<propBlocks, 256>>>(B2, B0, gsum, batch, pooled, N);

    // --- MLP head ---
    sgemm_k<128, 128><<<dim3(2, 1), 256>>>(pooled, Wm1, bm1, hbuf, 256, 128, 1);
    sgemm_k<128, 128><<<dim3(2, 2), 256>>>(hbuf, Wm2, bm2, (float*)d_out, 256, 256, 0);
}

// round 4
// speedup vs baseline: 1.1316x; 1.0055x over previous
#include <cuda_runtime.h>
#include <cuda_bf16.h>
#include <cstdint>

// ---------------------------------------------------------------------------
// Static scratch (no allocation allowed)
// ---------------------------------------------------------------------------
#define NMAX 100000
#define EMAX 1600000

__device__ float g_G0[NMAX * 128];                 // fp32 GEMM outputs / gather input
__device__ __nv_bfloat16 g_Hhi[NMAX * 128];        // prop output hi (recycled)
__device__ __nv_bfloat16 g_Hlo[NMAX * 128];        // prop output lo
__device__ __nv_bfloat16 g_X3hi[NMAX * 128];       // layer-3 output hi (kept for pool)
__device__ __nv_bfloat16 g_X3lo[NMAX * 128];
__device__ float g_s [NMAX];                       // attention scalar / exp weights
__device__ float g_wv[NMAX];
__device__ float g_dinv[NMAX];
__device__ int   g_cnt[NMAX];
__device__ int   g_ptr[NMAX + 1];
__device__ int   g_cur[NMAX];
__device__ int   g_rows[EMAX];
__device__ int   g_bsum[512];
__device__ float g_gmax[256];
__device__ float g_gsum[256];
__device__ float g_pooled[256 * 128];
__device__ float g_h[256 * 128];
__device__ __nv_bfloat16 g_Wthi[65536];
__device__ __nv_bfloat16 g_Wtlo[65536];

// ---------------------------------------------------------------------------
// Helpers
// ---------------------------------------------------------------------------
__device__ __forceinline__ uint32_t smem_u32(const void* p) {
    uint32_t a;
    asm("{ .reg .u64 t; cvta.to.shared.u64 t, %1; cvt.u32.u64 %0, t; }"
        : "=r"(a) : "l"(p));
    return a;
}

__device__ __forceinline__ void ldsm_x4(uint32_t& r0, uint32_t& r1,
                                        uint32_t& r2, uint32_t& r3, uint32_t addr) {
    asm volatile("ldmatrix.sync.aligned.m8n8.x4.shared.b16 {%0,%1,%2,%3}, [%4];"
                 : "=r"(r0), "=r"(r1), "=r"(r2), "=r"(r3) : "r"(addr));
}

__device__ __forceinline__ void mma_bf16(float* c, uint32_t a0, uint32_t a1,
                                         uint32_t a2, uint32_t a3,
                                         uint32_t b0, uint32_t b1) {
    asm volatile(
        "mma.sync.aligned.m16n8k16.row.col.f32.bf16.bf16.f32 "
        "{%0,%1,%2,%3}, {%4,%5,%6,%7}, {%8,%9}, {%0,%1,%2,%3};"
        : "+f"(c[0]), "+f"(c[1]), "+f"(c[2]), "+f"(c[3])
        : "r"(a0), "r"(a1), "r"(a2), "r"(a3), "r"(b0), "r"(b1));
}

// Packed split: (f0,f1) fp32 -> hi bf16x2 + lo bf16x2 (lo = rounded residual)
__device__ __forceinline__ void split2(float f0, float f1, uint32_t& h, uint32_t& l) {
    asm("cvt.rn.bf16x2.f32 %0, %1, %2;" : "=r"(h) : "f"(f1), "f"(f0));
    float h0 = __uint_as_float(h << 16);
    float h1 = __uint_as_float(h & 0xffff0000u);
    asm("cvt.rn.bf16x2.f32 %0, %1, %2;" : "=r"(l) : "f"(f1 - h1), "f"(f0 - h0));
}

// ---------------------------------------------------------------------------
// Weight prep: transpose to WT[n][k], fp32 -> bf16 hi/lo. W is [K, N].
// ---------------------------------------------------------------------------
__global__ void wprep_k(const float* __restrict__ W, int K, int N,
                        __nv_bfloat16* __restrict__ hi, __nv_bfloat16* __restrict__ lo) {
    int idx = blockIdx.x * blockDim.x + threadIdx.x;
    if (idx >= N * K) return;
    int n = idx / K, k = idx % K;
    float v = W[(size_t)k * N + n];
    __nv_bfloat16 h = __float2bfloat16(v);
    __nv_bfloat16 l = __float2bfloat16(v - __bfloat162float(h));
    hi[idx] = h;
    lo[idx] = l;
}

// ---------------------------------------------------------------------------
// HMMA GEMM core (shared by both A-input variants)
// ---------------------------------------------------------------------------
template<int K, int N>
__device__ __forceinline__ void hgemm_core(char* smem, uint32_t sb,
                                           float* __restrict__ OUT,
                                           int M, int rowBase) {
    constexpr int SA = K * 2 + 16;
    constexpr int A_HI = 0;
    constexpr int A_LO = 128 * SA;
    constexpr int B_HI = 2 * 128 * SA;
    constexpr int B_LO = B_HI + N * SA;

    const int tid = threadIdx.x;
    const int warp = tid >> 5;
    const int lane = tid & 31;

    constexpr int NT = N / 8;
    float acc[NT][4];
#pragma unroll
    for (int i = 0; i < NT; ++i)
#pragma unroll
        for (int j = 0; j < 4; ++j) acc[i][j] = 0.0f;

    const int m0 = warp * 16;
    const int q = lane >> 3;
    const int r8 = lane & 7;
    const uint32_t aRowOff = (uint32_t)(m0 + (q & 1) * 8 + r8) * SA + (uint32_t)(q >> 1) * 16;
    const uint32_t bRowIdx = (uint32_t)((q >> 1) * 8 + r8);
    const uint32_t bKOff = (uint32_t)(q & 1) * 16;

    const uint32_t abase[3] = { sb + A_HI, sb + A_LO, sb + A_HI };
    const uint32_t bbase[3] = { sb + B_HI, sb + B_HI, sb + B_LO };

#pragma unroll
    for (int p = 0; p < 3; ++p) {
        const uint32_t ab = abase[p] + aRowOff;
        const uint32_t bb = bbase[p] + bRowIdx * SA + bKOff;
#pragma unroll
        for (int kc = 0; kc < K / 16; ++kc) {
            uint32_t a0, a1, a2, a3;
            ldsm_x4(a0, a1, a2, a3, ab + kc * 32);
#pragma unroll
            for (int nt2 = 0; nt2 < N / 16; ++nt2) {
                uint32_t b0, b1, b2, b3;
                ldsm_x4(b0, b1, b2, b3, bb + (uint32_t)(nt2 * 16) * SA + kc * 32);
                mma_bf16(acc[2 * nt2],     a0, a1, a2, a3, b0, b1);
                mma_bf16(acc[2 * nt2 + 1], a0, a1, a2, a3, b2, b3);
            }
        }
    }

    const int row0 = rowBase + m0 + (lane >> 2);
    const int row1 = row0 + 8;
    const int cb = (lane & 3) * 2;
#pragma unroll
    for (int nt = 0; nt < NT; ++nt) {
        if (row0 < M)
            *(float2*)(OUT + (size_t)row0 * N + nt * 8 + cb) = make_float2(acc[nt][0], acc[nt][1]);
        if (row1 < M)
            *(float2*)(OUT + (size_t)row1 * N + nt * 8 + cb) = make_float2(acc[nt][2], acc[nt][3]);
    }
}

template<int K, int N>
__device__ __forceinline__ void stage_B(char* smem, const __nv_bfloat16* __restrict__ WThi,
                                        const __nv_bfloat16* __restrict__ WTlo) {
    constexpr int SA = K * 2 + 16;
    constexpr int B_HI = 2 * 128 * SA;
    constexpr int B_LO = B_HI + N * SA;
    const int tid = threadIdx.x;
    for (int i = tid; i < N * K / 4; i += 256) {
        int n = i / (K / 4);
        int kq = i % (K / 4);
        *(uint2*)(smem + B_HI + n * SA + kq * 8) = ((const uint2*)WThi)[i];
        *(uint2*)(smem + B_LO + n * SA + kq * 8) = ((const uint2*)WTlo)[i];
    }
}

// Variant 1: A is fp32 in global (layer 1 only) — converts in-kernel.
template<int K, int N>
__global__ __launch_bounds__(256)
void hgemm_k(const float* __restrict__ X,
             const __nv_bfloat16* __restrict__ WThi,
             const __nv_bfloat16* __restrict__ WTlo,
             float* __restrict__ OUT, int M) {
    extern __shared__ char smem[];
    constexpr int SA = K * 2 + 16;
    constexpr int A_HI = 0;
    constexpr int A_LO = 128 * SA;
    const int tid = threadIdx.x;
    const int rowBase = blockIdx.x * 128;
    const uint32_t sb = smem_u32(smem);

    stage_B<K, N>(smem, WThi, WTlo);

    for (int item = tid; item < 128 * (K / 8); item += 256) {
        int r = item / (K / 8);
        int k0 = (item % (K / 8)) * 8;
        float v[8];
        int grow = rowBase + r;
        if (grow < M) {
            const float4* p = (const float4*)(X + (size_t)grow * K + k0);
            float4 a = p[0], b = p[1];
            v[0] = a.x; v[1] = a.y; v[2] = a.z; v[3] = a.w;
            v[4] = b.x; v[5] = b.y; v[6] = b.z; v[7] = b.w;
        } else {
#pragma unroll
            for (int j = 0; j < 8; ++j) v[j] = 0.0f;
        }
        uint32_t hw[4], lw[4];
#pragma unroll
        for (int j = 0; j < 4; ++j) split2(v[2 * j], v[2 * j + 1], hw[j], lw[j]);
        *(uint4*)(smem + A_HI + r * SA + k0 * 2) = make_uint4(hw[0], hw[1], hw[2], hw[3]);
        *(uint4*)(smem + A_LO + r * SA + k0 * 2) = make_uint4(lw[0], lw[1], lw[2], lw[3]);
    }
    __syncthreads();
    hgemm_core<K, N>(smem, sb, OUT, M, rowBase);
}

// Variant 2: A pre-split bf16 hi/lo in global — pure copy staging.
template<int K, int N>
__global__ __launch_bounds__(256)
void hgemm_pre_k(const __nv_bfloat16* __restrict__ Ahi,
                 const __nv_bfloat16* __restrict__ Alo,
                 const __nv_bfloat16* __restrict__ WThi,
                 const __nv_bfloat16* __restrict__ WTlo,
                 float* __restrict__ OUT, int M) {
    extern __shared__ char smem[];
    constexpr int SA = K * 2 + 16;
    constexpr int A_HI = 0;
    constexpr int A_LO = 128 * SA;
    const int tid = threadIdx.x;
    const int rowBase = blockIdx.x * 128;
    const uint32_t sb = smem_u32(smem);

    stage_B<K, N>(smem, WThi, WTlo);

    const uint4 z = make_uint4(0, 0, 0, 0);
    for (int item = tid; item < 128 * (K / 8); item += 256) {
        int r = item / (K / 8);
        int k0 = (item % (K / 8)) * 8;
        int grow = rowBase + r;
        uint4 vh = z, vl = z;
        if (grow < M) {
            vh = *(const uint4*)(Ahi + (size_t)grow * K + k0);
            vl = *(const uint4*)(Alo + (size_t)grow * K + k0);
        }
        *(uint4*)(smem + A_HI + r * SA + k0 * 2) = vh;
        *(uint4*)(smem + A_LO + r * SA + k0 * 2) = vl;
    }
    __syncthreads();
    hgemm_core<K, N>(smem, sb, OUT, M, rowBase);
}

// ---------------------------------------------------------------------------
// CSC build + norms
// ---------------------------------------------------------------------------
__global__ void init_k(int* cnt, float* gmax, float* gsum, float* pooled, int n) {
    int i = blockIdx.x * blockDim.x + threadIdx.x;
    if (i < n) cnt[i] = 0;
    if (i < 256) { gmax[i] = 0.0f; gsum[i] = 0.0f; }
    if (i < 256 * 128) pooled[i] = 0.0f;
}

__global__ void count_k(const int* __restrict__ col, int* __restrict__ cnt, int e) {
    int i = blockIdx.x * blockDim.x + threadIdx.x;
    if (i < e) atomicAdd(&cnt[col[i]], 1);
}

__global__ void dinv_k(const int* __restrict__ cnt, float* __restrict__ dinv, int n) {
    int i = blockIdx.x * blockDim.x + threadIdx.x;
    if (i < n) dinv[i] = rsqrtf((float)cnt[i] + 1.0f);
}

__global__ void scan1_k(const int* __restrict__ cnt, int* __restrict__ ptr,
                        int* __restrict__ bsum, int n) {
    __shared__ int s[512];
    int t = threadIdx.x;
    int i = blockIdx.x * 512 + t;
    int v = (i < n) ? cnt[i] : 0;
    s[t] = v; __syncthreads();
    for (int off = 1; off < 512; off <<= 1) {
        int tmp = (t >= off) ? s[t - off] : 0;
        __syncthreads();
        s[t] += tmp;
        __syncthreads();
    }
    if (i < n) ptr[i] = s[t] - v;
    if (t == 511) bsum[blockIdx.x] = s[511];
}

__global__ void scan2_k(int* __restrict__ bsum, int nb) {
    __shared__ int s[512];
    int t = threadIdx.x;
    int v = (t < nb) ? bsum[t] : 0;
    s[t] = v; __syncthreads();
    for (int off = 1; off < 512; off <<= 1) {
        int tmp = (t >= off) ? s[t - off] : 0;
        __syncthreads();
        s[t] += tmp;
        __syncthreads();
    }
    if (t < nb) bsum[t] = s[t] - v;
}

__global__ void scan3_k(int* __restrict__ ptr, const int* __restrict__ bsum,
                        int* __restrict__ cur, int n, int etot) {
    int i = blockIdx.x * blockDim.x + threadIdx.x;
    if (i < n) {
        int p = ptr[i] + bsum[i >> 9];
        ptr[i] = p;
        cur[i] = p;
    }
    if (i == 0) ptr[n] = etot;
}

__global__ void fill_k(const int* __restrict__ row, const int* __restrict__ col,
                       int* __restrict__ cur, int* __restrict__ rows, int e) {
    int i = blockIdx.x * blockDim.x + threadIdx.x;
    if (i < e) {
        int c = col[i];
        int p = atomicAdd(&cur[c], 1);
        rows[p] = row[i];
    }
}

// ---------------------------------------------------------------------------
// SIMT SGEMM (tiny MLP head only)
// ---------------------------------------------------------------------------
template<int K, int FT>
__global__ __launch_bounds__(256)
void sgemm_k(const float* __restrict__ X, const float* __restrict__ W,
             const float* __restrict__ bias, float* __restrict__ OUT,
             int M, int ldW, int doRelu) {
    constexpr int KC = 32;
    constexpr int TN = FT / 16;
    __shared__ float Xs[KC][132];
    __shared__ float Ws[KC][FT];

    int tid = threadIdx.x;
    int tx = tid & 15, ty = tid >> 4;
    int rowBase = blockIdx.x * 128;
    int cBase = blockIdx.y * FT;

    float acc[8][TN];
#pragma unroll
    for (int i = 0; i < 8; ++i)
#pragma unroll
        for (int j = 0; j < TN; ++j) acc[i][j] = 0.0f;

    for (int k0 = 0; k0 < K; k0 += KC) {
#pragma unroll
        for (int p = 0; p < 4; ++p) {
            int id = tid + p * 256;
            int r = id >> 3;
            int k4 = id & 7;
            float4 xv = make_float4(0.f, 0.f, 0.f, 0.f);
            int grow = rowBase + r;
            if (grow < M)
                xv = *(const float4*)(X + (size_t)grow * K + k0 + k4 * 4);
            Xs[k4 * 4 + 0][r] = xv.x;
            Xs[k4 * 4 + 1][r] = xv.y;
            Xs[k4 * 4 + 2][r] = xv.z;
            Xs[k4 * 4 + 3][r] = xv.w;
        }
        for (int id = tid; id < KC * FT / 4; id += 256) {
            int kk = (id * 4) / FT;
            int c  = (id * 4) % FT;
            *(float4*)&Ws[kk][c] =
                *(const float4*)(W + (size_t)(k0 + kk) * ldW + cBase + c);
        }
        __syncthreads();

#pragma unroll 8
        for (int kk = 0; kk < KC; ++kk) {
            float xr[8];
            float4 a = *(const float4*)&Xs[kk][ty * 8];
            float4 b = *(const float4*)&Xs[kk][ty * 8 + 4];
            xr[0] = a.x; xr[1] = a.y; xr[2] = a.z; xr[3] = a.w;
            xr[4] = b.x; xr[5] = b.y; xr[6] = b.z; xr[7] = b.w;
            float wv[TN];
            float4 w0 = *(const float4*)&Ws[kk][tx * 8];
            float4 w1 = *(const float4*)&Ws[kk][tx * 8 + 4];
            wv[0] = w0.x; wv[1] = w0.y; wv[2] = w0.z; wv[3] = w0.w;
            wv[4] = w1.x; wv[5] = w1.y; wv[6] = w1.z; wv[7] = w1.w;
#pragma unroll
            for (int i = 0; i < 8; ++i)
#pragma unroll
                for (int j = 0; j < TN; ++j)
                    acc[i][j] += xr[i] * wv[j];
        }
        __syncthreads();
    }

#pragma unroll
    for (int i = 0; i < 8; ++i) {
        int grow = rowBase + ty * 8 + i;
        if (grow >= M) continue;
#pragma unroll
        for (int j = 0; j < TN; ++j) {
            int c = cBase + tx * TN + j;
            float v = acc[i][j];
            if (bias) v += bias[c];
            if (doRelu) v = fmaxf(v, 0.0f);
            OUT[(size_t)grow * ldW + c] = v;
        }
    }
}

// ---------------------------------------------------------------------------
// Pull-based GCN propagation, unrolled x4 gather, bf16 hi/lo split output.
// F in {128, 64}. OUT rows are F bf16 each in OHI and OLO.
// ---------------------------------------------------------------------------
template<int F>
__global__ __launch_bounds__(256)
void prop_bf_k(const float* __restrict__ H, const int* __restrict__ ptr,
               const int* __restrict__ rows, const float* __restrict__ dinv,
               const float* __restrict__ bias,
               __nv_bfloat16* __restrict__ OHI, __nv_bfloat16* __restrict__ OLO, int n) {
    constexpr int V = F / 32;
    int node = (blockIdx.x * blockDim.x + threadIdx.x) >> 5;
    int lane = threadIdx.x & 31;
    if (node >= n) return;

    const float dn = dinv[node];
    const float selfw = dn * dn;
    const float* hb = H + lane * V;
    float acc[V];
    {
        const float* hp = hb + (size_t)node * F;
        if (V == 4) {
            float4 v = *(const float4*)hp;
            acc[0] = selfw * v.x; acc[1] = selfw * v.y;
            acc[2] = selfw * v.z; acc[3] = selfw * v.w;
        } else {
            float2 v = *(const float2*)hp;
            acc[0] = selfw * v.x; acc[1] = selfw * v.y;
        }
    }

    int beg = ptr[node], end = ptr[node + 1];
    for (int j0 = beg; j0 < end; j0 += 32) {
        int j = j0 + lane;
        int r = 0; float dv = 0.0f;
        if (j < end) { r = rows[j]; dv = dinv[r]; }
        int cnt = min(32, end - j0);
        int t = 0;
        for (; t + 4 <= cnt; t += 4) {
            int rr0 = __shfl_sync(0xffffffffu, r, t);
            int rr1 = __shfl_sync(0xffffffffu, r, t + 1);
            int rr2 = __shfl_sync(0xffffffffu, r, t + 2);
            int rr3 = __shfl_sync(0xffffffffu, r, t + 3);
            float w0 = __shfl_sync(0xffffffffu, dv, t)     * dn;
            float w1 = __shfl_sync(0xffffffffu, dv, t + 1) * dn;
            float w2 = __shfl_sync(0xffffffffu, dv, t + 2) * dn;
            float w3 = __shfl_sync(0xffffffffu, dv, t + 3) * dn;
            if (V == 4) {
                float4 v0 = *(const float4*)(hb + (size_t)rr0 * F);
                float4 v1 = *(const float4*)(hb + (size_t)rr1 * F);
                float4 v2 = *(const float4*)(hb + (size_t)rr2 * F);
                float4 v3 = *(const float4*)(hb + (size_t)rr3 * F);
                acc[0] += w0 * v0.x; acc[1] += w0 * v0.y; acc[2] += w0 * v0.z; acc[3] += w0 * v0.w;
                acc[0] += w1 * v1.x; acc[1] += w1 * v1.y; acc[2] += w1 * v1.z; acc[3] += w1 * v1.w;
                acc[0] += w2 * v2.x; acc[1] += w2 * v2.y; acc[2] += w2 * v2.z; acc[3] += w2 * v2.w;
                acc[0] += w3 * v3.x; acc[1] += w3 * v3.y; acc[2] += w3 * v3.z; acc[3] += w3 * v3.w;
            } else {
                float2 v0 = *(const float2*)(hb + (size_t)rr0 * F);
                float2 v1 = *(const float2*)(hb + (size_t)rr1 * F);
                float2 v2 = *(const float2*)(hb + (size_t)rr2 * F);
                float2 v3 = *(const float2*)(hb + (size_t)rr3 * F);
                acc[0] += w0 * v0.x; acc[1] += w0 * v0.y;
                acc[0] += w1 * v1.x; acc[1] += w1 * v1.y;
                acc[0] += w2 * v2.x; acc[1] += w2 * v2.y;
                acc[0] += w3 * v3.x; acc[1] += w3 * v3.y;
            }
        }
        for (; t < cnt; ++t) {
            int rr  = __shfl_sync(0xffffffffu, r,  t);
            float w = __shfl_sync(0xffffffffu, dv, t) * dn;
            if (V == 4) {
                float4 v = *(const float4*)(hb + (size_t)rr * F);
                acc[0] += w * v.x; acc[1] += w * v.y; acc[2] += w * v.z; acc[3] += w * v.w;
            } else {
                float2 v = *(const float2*)(hb + (size_t)rr * F);
                acc[0] += w * v.x; acc[1] += w * v.y;
            }
        }
    }

    // epilogue: bias + relu + bf16 hi/lo split
    if (V == 4) {
        float f0 = fmaxf(acc[0] + bias[lane * 4 + 0], 0.0f);
        float f1 = fmaxf(acc[1] + bias[lane * 4 + 1], 0.0f);
        float f2 = fmaxf(acc[2] + bias[lane * 4 + 2], 0.0f);
        float f3 = fmaxf(acc[3] + bias[lane * 4 + 3], 0.0f);
        uint32_t h01, l01, h23, l23;
        split2(f0, f1, h01, l01);
        split2(f2, f3, h23, l23);
        *(uint2*)(OHI + (size_t)node * F + lane * 4) = make_uint2(h01, h23);
        *(uint2*)(OLO + (size_t)node * F + lane * 4) = make_uint2(l01, l23);
    } else {
        float f0 = fmaxf(acc[0] + bias[lane * 2 + 0], 0.0f);
        float f1 = fmaxf(acc[1] + bias[lane * 2 + 1], 0.0f);
        uint32_t h, l;
        split2(f0, f1, h, l);
        *(uint32_t*)(OHI + (size_t)node * F + lane * 2) = h;
        *(uint32_t*)(OLO + (size_t)node * F + lane * 2) = l;
    }
}

// F=32 propagation fused with Wa3 dot: s[node] = dot(relu(prop+ba2), Wa3)
__global__ __launch_bounds__(256)
void prop32dot_k(const float* __restrict__ H, const int* __restrict__ ptr,
                 const int* __restrict__ rows, const float* __restrict__ dinv,
                 const float* __restrict__ ba2, const float* __restrict__ Wa3,
                 float* __restrict__ s, int n) {
    int node = (blockIdx.x * blockDim.x + threadIdx.x) >> 5;
    int lane = threadIdx.x & 31;
    if (node >= n) return;

    const float dn = dinv[node];
    float acc = dn * dn * H[(size_t)node * 32 + lane];
    const float* hb = H + lane;

    int beg = ptr[node], end = ptr[node + 1];
    for (int j0 = beg; j0 < end; j0 += 32) {
        int j = j0 + lane;
        int r = 0; float dv = 0.0f;
        if (j < end) { r = rows[j]; dv = dinv[r]; }
        int cnt = min(32, end - j0);
        int t = 0;
        for (; t + 4 <= cnt; t += 4) {
            int rr0 = __shfl_sync(0xffffffffu, r, t);
            int rr1 = __shfl_sync(0xffffffffu, r, t + 1);
            int rr2 = __shfl_sync(0xffffffffu, r, t + 2);
            int rr3 = __shfl_sync(0xffffffffu, r, t + 3);
            float w0 = __shfl_sync(0xffffffffu, dv, t)     * dn;
            float w1 = __shfl_sync(0xffffffffu, dv, t + 1) * dn;
            float w2 = __shfl_sync(0xffffffffu, dv, t + 2) * dn;
            float w3 = __shfl_sync(0xffffffffu, dv, t + 3) * dn;
            float v0 = hb[(size_t)rr0 * 32];
            float v1 = hb[(size_t)rr1 * 32];
            float v2 = hb[(size_t)rr2 * 32];
            float v3 = hb[(size_t)rr3 * 32];
            acc += w0 * v0 + w1 * v1 + w2 * v2 + w3 * v3;
        }
        for (; t < cnt; ++t) {
            int rr  = __shfl_sync(0xffffffffu, r,  t);
            float w = __shfl_sync(0xffffffffu, dv, t) * dn;
            acc += w * hb[(size_t)rr * 32];
        }
    }

    float v = fmaxf(acc + ba2[lane], 0.0f) * Wa3[lane];
#pragma unroll
    for (int o = 16; o; o >>= 1) v += __shfl_down_sync(0xffffffffu, v, o);
    if (lane == 0) s[node] = v;
}

// F=1 propagation (scalar features)
__global__ __launch_bounds__(256)
void prop1_k(const float* __restrict__ H, const int* __restrict__ ptr,
             const int* __restrict__ rows, const float* __restrict__ dinv,
             const float* __restrict__ bias, float* __restrict__ OUT, int n) {
    int node = (blockIdx.x * blockDim.x + threadIdx.x) >> 5;
    int lane = threadIdx.x & 31;
    if (node >= n) return;
    float dn = dinv[node];
    int beg = ptr[node], end = ptr[node + 1];
    float acc = 0.0f;
    for (int j = beg + lane; j < end; j += 32) {
        int r = rows[j];
        acc += dinv[r] * H[r];
    }
#pragma unroll
    for (int o = 16; o; o >>= 1) acc += __shfl_down_sync(0xffffffffu, acc, o);
    if (lane == 0) {
        float v = acc * dn + dn * dn * H[node] + bias[0];
        OUT[node] = fmaxf(v, 0.0f);
    }
}

// segment softmax pieces (w >= 0 after relu -> uint atomicMax is order-preserving)
__global__ void segmax_k(const float* __restrict__ w, const int* __restrict__ batch,
                         float* __restrict__ gmax, int n) {
    int i = blockIdx.x * blockDim.x + threadIdx.x;
    if (i < n) atomicMax((unsigned int*)&gmax[batch[i]], __float_as_uint(w[i]));
}

__global__ void expsum_k(const float* __restrict__ w, const int* __restrict__ batch,
                         const float* __restrict__ gmax, float* __restrict__ ew,
                         float* __restrict__ gsum, int n) {
    int i = blockIdx.x * blockDim.x + threadIdx.x;
    if (i < n) {
        int b = batch[i];
        float e = expf(w[i] - gmax[b]);
        ew[i] = e;
        atomicAdd(&gsum[b], e);
    }
}

// attention pooling over x3 stored as bf16 hi/lo
__global__ __launch_bounds__(256)
void pool_k(const __nv_bfloat16* __restrict__ X3hi, const __nv_bfloat16* __restrict__ X3lo,
            const float* __restrict__ ew, const float* __restrict__ gsum,
            const int* __restrict__ batch, float* __restrict__ pooled, int n) {
    int node = (blockIdx.x * blockDim.x + threadIdx.x) >> 5;
    int lane = threadIdx.x & 31;
    if (node >= n) return;
    int b = batch[node];
    float coef = ew[node] / (gsum[b] + 1e-16f);
    uint2 h = *(const uint2*)(X3hi + (size_t)node * 128 + lane * 4);
    uint2 l = *(const uint2*)(X3lo + (size_t)node * 128 + lane * 4);
    float f0 = __uint_as_float(h.x << 16)        + __uint_as_float(l.x << 16);
    float f1 = __uint_as_float(h.x & 0xffff0000u) + __uint_as_float(l.x & 0xffff0000u);
    float f2 = __uint_as_float(h.y << 16)        + __uint_as_float(l.y << 16);
    float f3 = __uint_as_float(h.y & 0xffff0000u) + __uint_as_float(l.y & 0xffff0000u);
    float* pb = pooled + b * 128 + lane * 4;
    atomicAdd(pb + 0, coef * f0);
    atomicAdd(pb + 1, coef * f1);
    atomicAdd(pb + 2, coef * f2);
    atomicAdd(pb + 3, coef * f3);
}

// ---------------------------------------------------------------------------
// Host launcher
// ---------------------------------------------------------------------------
extern "C" void kernel_launch(void* const* d_in, const int* in_sizes, int n_in,
                              void* d_out, int out_size) {
    const float* x     = (const float*)d_in[0];
    const int*   ei    = (const int*)d_in[1];
    const int*   batch = (const int*)d_in[2];
    const float* W1 = (const float*)d_in[3];   const float* b1 = (const float*)d_in[4];
    const float* W2 = (const float*)d_in[5];   const float* b2 = (const float*)d_in[6];
    const float* W3 = (const float*)d_in[7];   const float* b3 = (const float*)d_in[8];
    const float* Wa1 = (const float*)d_in[9];  const float* ba1 = (const float*)d_in[10];
    const float* Wa2 = (const float*)d_in[11]; const float* ba2 = (const float*)d_in[12];
    const float* Wa3 = (const float*)d_in[13]; const float* ba3 = (const float*)d_in[14];
    const float* Wm1 = (const float*)d_in[15]; const float* bm1 = (const float*)d_in[16];
    const float* Wm2 = (const float*)d_in[17]; const float* bm2 = (const float*)d_in[18];

    int N = in_sizes[0] / 128;
    int E = in_sizes[1] / 2;
    const int* row = ei;
    const int* col = ei + E;

    float *G0, *s, *wv, *dinv, *gmax, *gsum, *pooled, *hbuf;
    int *cnt, *ptr, *cur, *rows, *bsum;
    __nv_bfloat16 *Hhi, *Hlo, *X3hi, *X3lo, *wthi, *wtlo;
    cudaGetSymbolAddress((void**)&G0, g_G0);
    cudaGetSymbolAddress((void**)&Hhi, g_Hhi);
    cudaGetSymbolAddress((void**)&Hlo, g_Hlo);
    cudaGetSymbolAddress((void**)&X3hi, g_X3hi);
    cudaGetSymbolAddress((void**)&X3lo, g_X3lo);
    cudaGetSymbolAddress((void**)&s, g_s);
    cudaGetSymbolAddress((void**)&wv, g_wv);
    cudaGetSymbolAddress((void**)&dinv, g_dinv);
    cudaGetSymbolAddress((void**)&cnt, g_cnt);
    cudaGetSymbolAddress((void**)&ptr, g_ptr);
    cudaGetSymbolAddress((void**)&cur, g_cur);
    cudaGetSymbolAddress((void**)&rows, g_rows);
    cudaGetSymbolAddress((void**)&bsum, g_bsum);
    cudaGetSymbolAddress((void**)&gmax, g_gmax);
    cudaGetSymbolAddress((void**)&gsum, g_gsum);
    cudaGetSymbolAddress((void**)&pooled, g_pooled);
    cudaGetSymbolAddress((void**)&hbuf, g_h);
    cudaGetSymbolAddress((void**)&wthi, g_Wthi);
    cudaGetSymbolAddress((void**)&wtlo, g_Wtlo);

    const int SM_128_128 = 2 * 128 * 272 + 2 * 128 * 272;  // 139264
    const int SM_128_64  = 2 * 128 * 272 + 2 *  64 * 272;  // 104448
    const int SM_64_32   = 2 * 128 * 144 + 2 *  32 * 144;  //  46080
    cudaFuncSetAttribute(hgemm_k<128, 128>,     cudaFuncAttributeMaxDynamicSharedMemorySize, SM_128_128);
    cudaFuncSetAttribute(hgemm_pre_k<128, 128>, cudaFuncAttributeMaxDynamicSharedMemorySize, SM_128_128);
    cudaFuncSetAttribute(hgemm_pre_k<128, 64>,  cudaFuncAttributeMaxDynamicSharedMemorySize, SM_128_64);
    cudaFuncSetAttribute(hgemm_pre_k<64, 32>,   cudaFuncAttributeMaxDynamicSharedMemorySize, SM_64_32);

    int NB = (N + 511) / 512;
    int nInit = (N > 256 * 128) ? N : 256 * 128;

    // --- build CSC + norms ---
    init_k<<<(nInit + 255) / 256, 256>>>(cnt, gmax, gsum, pooled, N);
    count_k<<<(E + 255) / 256, 256>>>(col, cnt, E);
    dinv_k<<<(N + 255) / 256, 256>>>(cnt, dinv, N);
    scan1_k<<<NB, 512>>>(cnt, ptr, bsum, N);
    scan2_k<<<1, 512>>>(bsum, NB);
    scan3_k<<<(N + 255) / 256, 256>>>(ptr, bsum, cur, N, E);
    fill_k<<<(E + 255) / 256, 256>>>(row, col, cur, rows, E);

    // --- prep weights ---
    wprep_k<<<64, 256>>>(W1, 128, 128, wthi + 0,     wtlo + 0);
    wprep_k<<<64, 256>>>(W2, 128, 128, wthi + 16384, wtlo + 16384);
    wprep_k<<<64, 256>>>(W3, 128, 128, wthi + 32768, wtlo + 32768);
    wprep_k<<<32, 256>>>(Wa1, 128, 64, wthi + 49152, wtlo + 49152);
    wprep_k<<<8, 256>>>(Wa2, 64, 32,   wthi + 57344, wtlo + 57344);

    int MT = (N + 127) / 128;
    int propBlocks = (N + 7) / 8;

    // --- 3 GCN layers (128 -> 128) ---
    hgemm_k<128, 128><<<MT, 256, SM_128_128>>>(x, wthi + 0, wtlo + 0, G0, N);
    prop_bf_k<128><<<propBlocks, 256>>>(G0, ptr, rows, dinv, b1, Hhi, Hlo, N);
    hgemm_pre_k<128, 128><<<MT, 256, SM_128_128>>>(Hhi, Hlo, wthi + 16384, wtlo + 16384, G0, N);
    prop_bf_k<128><<<propBlocks, 256>>>(G0, ptr, rows, dinv, b2, Hhi, Hlo, N);
    hgemm_pre_k<128, 128><<<MT, 256, SM_128_128>>>(Hhi, Hlo, wthi + 32768, wtlo + 32768, G0, N);
    prop_bf_k<128><<<propBlocks, 256>>>(G0, ptr, rows, dinv, b3, X3hi, X3lo, N);

    // --- attention branch (128 -> 64 -> 32 -> 1) ---
    hgemm_pre_k<128, 64><<<MT, 256, SM_128_64>>>(X3hi, X3lo, wthi + 49152, wtlo + 49152, G0, N);
    prop_bf_k<64><<<propBlocks, 256>>>(G0, ptr, rows, dinv, ba1, Hhi, Hlo, N);
    hgemm_pre_k<64, 32><<<MT, 256, SM_64_32>>>(Hhi, Hlo, wthi + 57344, wtlo + 57344, G0, N);
    prop32dot_k<<<propBlocks, 256>>>(G0, ptr, rows, dinv, ba2, Wa3, s, N);
    prop1_k<<<propBlocks, 256>>>(s, ptr, rows, dinv, ba3, wv, N);

    // --- segment softmax + attention pooling ---
    segmax_k<<<(N + 255) / 256, 256>>>(wv, batch, gmax, N);
    expsum_k<<<(N + 255) / 256, 256>>>(wv, batch, gmax, s, gsum, N);
    pool_k<<<propBlocks, 256>>>(X3hi, X3lo, s, gsum, batch, pooled, N);

    // --- MLP head ---
    sgemm_k<128, 128><<<dim3(2, 1), 256>>>(pooled, Wm1, bm1, hbuf, 256, 128, 1);
    sgemm_k<128, 128><<<dim3(2, 2), 256>>>(hbuf, Wm2, bm2, (float*)d_out, 256, 256, 0);
}

// round 5
// speedup vs baseline: 1.2305x; 1.0874x over previous
#include <cuda_runtime.h>
#include <cuda_bf16.h>
#include <cstdint>

// ---------------------------------------------------------------------------
// Static scratch (no allocation allowed)
// ---------------------------------------------------------------------------
#define NMAX 100000
#define EMAX 1600000

__device__ float g_G0[NMAX * 128];                 // fp32 GEMM outputs / gather input
__device__ __nv_bfloat16 g_Hhi[NMAX * 128];        // prop output hi (recycled)
__device__ __nv_bfloat16 g_Hlo[NMAX * 128];        // prop output lo
__device__ __nv_bfloat16 g_X3hi[NMAX * 128];       // layer-3 output hi (kept for pool)
__device__ __nv_bfloat16 g_X3lo[NMAX * 128];
__device__ float g_s [NMAX];                       // attention scalar / exp weights
__device__ float g_wv[NMAX];
__device__ float g_dinv[NMAX];
__device__ int   g_cnt[NMAX];
__device__ int   g_ptr[NMAX + 1];
__device__ int   g_cur[NMAX];
__device__ int   g_rows[EMAX];
__device__ int   g_bsum[512];
__device__ float g_gmax[256];
__device__ float g_gsum[256];
__device__ float g_pooled[256 * 128];
__device__ float g_h[256 * 128];
__device__ __nv_bfloat16 g_Wthi[65536];
__device__ __nv_bfloat16 g_Wtlo[65536];

// ---------------------------------------------------------------------------
// Helpers
// ---------------------------------------------------------------------------
__device__ __forceinline__ uint32_t smem_u32(const void* p) {
    uint32_t a;
    asm("{ .reg .u64 t; cvta.to.shared.u64 t, %1; cvt.u32.u64 %0, t; }"
        : "=r"(a) : "l"(p));
    return a;
}

__device__ __forceinline__ void ldsm_x4(uint32_t& r0, uint32_t& r1,
                                        uint32_t& r2, uint32_t& r3, uint32_t addr) {
    asm volatile("ldmatrix.sync.aligned.m8n8.x4.shared.b16 {%0,%1,%2,%3}, [%4];"
                 : "=r"(r0), "=r"(r1), "=r"(r2), "=r"(r3) : "r"(addr));
}

__device__ __forceinline__ void mma_bf16(float* c, uint32_t a0, uint32_t a1,
                                         uint32_t a2, uint32_t a3,
                                         uint32_t b0, uint32_t b1) {
    asm volatile(
        "mma.sync.aligned.m16n8k16.row.col.f32.bf16.bf16.f32 "
        "{%0,%1,%2,%3}, {%4,%5,%6,%7}, {%8,%9}, {%0,%1,%2,%3};"
        : "+f"(c[0]), "+f"(c[1]), "+f"(c[2]), "+f"(c[3])
        : "r"(a0), "r"(a1), "r"(a2), "r"(a3), "r"(b0), "r"(b1));
}

// Packed split: (f0,f1) fp32 -> hi bf16x2 + lo bf16x2 (lo = rounded residual)
__device__ __forceinline__ void split2(float f0, float f1, uint32_t& h, uint32_t& l) {
    asm("cvt.rn.bf16x2.f32 %0, %1, %2;" : "=r"(h) : "f"(f1), "f"(f0));
    float h0 = __uint_as_float(h << 16);
    float h1 = __uint_as_float(h & 0xffff0000u);
    asm("cvt.rn.bf16x2.f32 %0, %1, %2;" : "=r"(l) : "f"(f1 - h1), "f"(f0 - h0));
}

// ---------------------------------------------------------------------------
// Fused weight prep: all 5 weight matrices in one launch.
// Transpose to WT[n][k], fp32 -> bf16 hi/lo. W is [K, N] row-major.
// ---------------------------------------------------------------------------
__global__ void wprep_all_k(const float* __restrict__ W1, const float* __restrict__ W2,
                            const float* __restrict__ W3, const float* __restrict__ Wa1,
                            const float* __restrict__ Wa2,
                            __nv_bfloat16* __restrict__ hi, __nv_bfloat16* __restrict__ lo) {
    int idx = blockIdx.x * blockDim.x + threadIdx.x;
    const float* W; int K, N, local;
    if (idx < 16384)      { W = W1;  K = 128; N = 128; local = idx; }
    else if (idx < 32768) { W = W2;  K = 128; N = 128; local = idx - 16384; }
    else if (idx < 49152) { W = W3;  K = 128; N = 128; local = idx - 32768; }
    else if (idx < 57344) { W = Wa1; K = 128; N = 64;  local = idx - 49152; }
    else if (idx < 59392) { W = Wa2; K = 64;  N = 32;  local = idx - 57344; }
    else return;
    int n = local / K, k = local % K;
    float v = W[(size_t)k * N + n];
    __nv_bfloat16 h = __float2bfloat16(v);
    __nv_bfloat16 l = __float2bfloat16(v - __bfloat162float(h));
    hi[idx] = h;
    lo[idx] = l;
}

// ---------------------------------------------------------------------------
// HMMA GEMM, 64-row M tiles for 2-3 CTAs/SM occupancy.
// 256 threads = 8 warps in 4(M) x 2(N) grid; warp: 16 rows x N/2 cols.
// Smem: A hi/lo (64 x SA) + B hi/lo (N x SA), SA = 2K+16 (padded rows).
// ---------------------------------------------------------------------------
template<int K, int N>
__device__ __forceinline__ void hgemm_core64(char* smem, uint32_t sb,
                                             float* __restrict__ OUT,
                                             int M, int rowBase) {
    constexpr int SA = K * 2 + 16;
    constexpr int A_HI = 0;
    constexpr int A_LO = 64 * SA;
    constexpr int B_HI = 128 * SA;
    constexpr int B_LO = B_HI + N * SA;
    constexpr int NW = N / 2;               // cols per warp
    constexpr int NT = NW / 8;

    const int tid = threadIdx.x;
    const int warp = tid >> 5;
    const int lane = tid & 31;
    const int wm = warp & 3;
    const int wn = warp >> 2;

    float acc[NT][4];
#pragma unroll
    for (int i = 0; i < NT; ++i)
#pragma unroll
        for (int j = 0; j < 4; ++j) acc[i][j] = 0.0f;

    const int m0 = wm * 16;
    const int q = lane >> 3;
    const int r8 = lane & 7;
    const uint32_t aRowOff = (uint32_t)(m0 + (q & 1) * 8 + r8) * SA + (uint32_t)(q >> 1) * 16;
    const uint32_t bOff = (uint32_t)(wn * NW + (q >> 1) * 8 + r8) * SA + (uint32_t)(q & 1) * 16;

    const uint32_t abase[3] = { sb + A_HI, sb + A_LO, sb + A_HI };
    const uint32_t bbase[3] = { sb + B_HI, sb + B_HI, sb + B_LO };

#pragma unroll
    for (int p = 0; p < 3; ++p) {
        const uint32_t ab = abase[p] + aRowOff;
        const uint32_t bb = bbase[p] + bOff;
#pragma unroll
        for (int kc = 0; kc < K / 16; ++kc) {
            uint32_t a0, a1, a2, a3;
            ldsm_x4(a0, a1, a2, a3, ab + kc * 32);
#pragma unroll
            for (int nt2 = 0; nt2 < NW / 16; ++nt2) {
                uint32_t b0, b1, b2, b3;
                ldsm_x4(b0, b1, b2, b3, bb + (uint32_t)(nt2 * 16) * SA + kc * 32);
                mma_bf16(acc[2 * nt2],     a0, a1, a2, a3, b0, b1);
                mma_bf16(acc[2 * nt2 + 1], a0, a1, a2, a3, b2, b3);
            }
        }
    }

    const int row0 = rowBase + m0 + (lane >> 2);
    const int row1 = row0 + 8;
    const int cbase = wn * NW + (lane & 3) * 2;
#pragma unroll
    for (int nt = 0; nt < NT; ++nt) {
        if (row0 < M)
            *(float2*)(OUT + (size_t)row0 * N + cbase + nt * 8) = make_float2(acc[nt][0], acc[nt][1]);
        if (row1 < M)
            *(float2*)(OUT + (size_t)row1 * N + cbase + nt * 8) = make_float2(acc[nt][2], acc[nt][3]);
    }
}

template<int K, int N>
__device__ __forceinline__ void stage_B64(char* smem,
                                          const __nv_bfloat16* __restrict__ WThi,
                                          const __nv_bfloat16* __restrict__ WTlo) {
    constexpr int SA = K * 2 + 16;
    constexpr int B_HI = 128 * SA;
    constexpr int B_LO = B_HI + N * SA;
    const int tid = threadIdx.x;
    for (int i = tid; i < N * K / 4; i += 256) {
        int n = i / (K / 4);
        int kq = i % (K / 4);
        *(uint2*)(smem + B_HI + n * SA + kq * 8) = ((const uint2*)WThi)[i];
        *(uint2*)(smem + B_LO + n * SA + kq * 8) = ((const uint2*)WTlo)[i];
    }
}

// Variant 1: A fp32 in global (layer 1) — converts in-kernel.
template<int K, int N>
__global__ __launch_bounds__(256, 2)
void hgemm_k(const float* __restrict__ X,
             const __nv_bfloat16* __restrict__ WThi,
             const __nv_bfloat16* __restrict__ WTlo,
             float* __restrict__ OUT, int M) {
    extern __shared__ char smem[];
    constexpr int SA = K * 2 + 16;
    constexpr int A_HI = 0;
    constexpr int A_LO = 64 * SA;
    const int tid = threadIdx.x;
    const int rowBase = blockIdx.x * 64;
    const uint32_t sb = smem_u32(smem);

    stage_B64<K, N>(smem, WThi, WTlo);

    for (int item = tid; item < 64 * (K / 8); item += 256) {
        int r = item / (K / 8);
        int k0 = (item % (K / 8)) * 8;
        float v[8];
        int grow = rowBase + r;
        if (grow < M) {
            const float4* p = (const float4*)(X + (size_t)grow * K + k0);
            float4 a = p[0], b = p[1];
            v[0] = a.x; v[1] = a.y; v[2] = a.z; v[3] = a.w;
            v[4] = b.x; v[5] = b.y; v[6] = b.z; v[7] = b.w;
        } else {
#pragma unroll
            for (int j = 0; j < 8; ++j) v[j] = 0.0f;
        }
        uint32_t hw[4], lw[4];
#pragma unroll
        for (int j = 0; j < 4; ++j) split2(v[2 * j], v[2 * j + 1], hw[j], lw[j]);
        *(uint4*)(smem + A_HI + r * SA + k0 * 2) = make_uint4(hw[0], hw[1], hw[2], hw[3]);
        *(uint4*)(smem + A_LO + r * SA + k0 * 2) = make_uint4(lw[0], lw[1], lw[2], lw[3]);
    }
    __syncthreads();
    hgemm_core64<K, N>(smem, sb, OUT, M, rowBase);
}

// Variant 2: A pre-split bf16 hi/lo in global — pure copy staging.
template<int K, int N>
__global__ __launch_bounds__(256, 2)
void hgemm_pre_k(const __nv_bfloat16* __restrict__ Ahi,
                 const __nv_bfloat16* __restrict__ Alo,
                 const __nv_bfloat16* __restrict__ WThi,
                 const __nv_bfloat16* __restrict__ WTlo,
                 float* __restrict__ OUT, int M) {
    extern __shared__ char smem[];
    constexpr int SA = K * 2 + 16;
    constexpr int A_HI = 0;
    constexpr int A_LO = 64 * SA;
    const int tid = threadIdx.x;
    const int rowBase = blockIdx.x * 64;
    const uint32_t sb = smem_u32(smem);

    stage_B64<K, N>(smem, WThi, WTlo);

    const uint4 z = make_uint4(0, 0, 0, 0);
    for (int item = tid; item < 64 * (K / 8); item += 256) {
        int r = item / (K / 8);
        int k0 = (item % (K / 8)) * 8;
        int grow = rowBase + r;
        uint4 vh = z, vl = z;
        if (grow < M) {
            vh = *(const uint4*)(Ahi + (size_t)grow * K + k0);
            vl = *(const uint4*)(Alo + (size_t)grow * K + k0);
        }
        *(uint4*)(smem + A_HI + r * SA + k0 * 2) = vh;
        *(uint4*)(smem + A_LO + r * SA + k0 * 2) = vl;
    }
    __syncthreads();
    hgemm_core64<K, N>(smem, sb, OUT, M, rowBase);
}

// ---------------------------------------------------------------------------
// CSC build + norms
// ---------------------------------------------------------------------------
__global__ void init_k(int* cnt, float* gmax, float* gsum, float* pooled, int n) {
    int i = blockIdx.x * blockDim.x + threadIdx.x;
    if (i < n) cnt[i] = 0;
    if (i < 256) { gmax[i] = 0.0f; gsum[i] = 0.0f; }
    if (i < 256 * 128) pooled[i] = 0.0f;
}

__global__ void count_k(const int* __restrict__ col, int* __restrict__ cnt, int e) {
    int i = blockIdx.x * blockDim.x + threadIdx.x;
    if (i < e) atomicAdd(&cnt[col[i]], 1);
}

// scan1 + dinv fused
__global__ void scan1_k(const int* __restrict__ cnt, int* __restrict__ ptr,
                        int* __restrict__ bsum, float* __restrict__ dinv, int n) {
    __shared__ int s[512];
    int t = threadIdx.x;
    int i = blockIdx.x * 512 + t;
    int v = (i < n) ? cnt[i] : 0;
    if (i < n) dinv[i] = rsqrtf((float)v + 1.0f);   // +1 = self loop
    s[t] = v; __syncthreads();
    for (int off = 1; off < 512; off <<= 1) {
        int tmp = (t >= off) ? s[t - off] : 0;
        __syncthreads();
        s[t] += tmp;
        __syncthreads();
    }
    if (i < n) ptr[i] = s[t] - v;
    if (t == 511) bsum[blockIdx.x] = s[511];
}

__global__ void scan2_k(int* __restrict__ bsum, int nb) {
    __shared__ int s[512];
    int t = threadIdx.x;
    int v = (t < nb) ? bsum[t] : 0;
    s[t] = v; __syncthreads();
    for (int off = 1; off < 512; off <<= 1) {
        int tmp = (t >= off) ? s[t - off] : 0;
        __syncthreads();
        s[t] += tmp;
        __syncthreads();
    }
    if (t < nb) bsum[t] = s[t] - v;
}

__global__ void scan3_k(int* __restrict__ ptr, const int* __restrict__ bsum,
                        int* __restrict__ cur, int n, int etot) {
    int i = blockIdx.x * blockDim.x + threadIdx.x;
    if (i < n) {
        int p = ptr[i] + bsum[i >> 9];
        ptr[i] = p;
        cur[i] = p;
    }
    if (i == 0) ptr[n] = etot;
}

__global__ void fill_k(const int* __restrict__ row, const int* __restrict__ col,
                       int* __restrict__ cur, int* __restrict__ rows, int e) {
    int i = blockIdx.x * blockDim.x + threadIdx.x;
    if (i < e) {
        int c = col[i];
        int p = atomicAdd(&cur[c], 1);
        rows[p] = row[i];
    }
}

// ---------------------------------------------------------------------------
// SIMT SGEMM (tiny MLP head only)
// ---------------------------------------------------------------------------
template<int K, int FT>
__global__ __launch_bounds__(256)
void sgemm_k(const float* __restrict__ X, const float* __restrict__ W,
             const float* __restrict__ bias, float* __restrict__ OUT,
             int M, int ldW, int doRelu) {
    constexpr int KC = 32;
    constexpr int TN = FT / 16;
    __shared__ float Xs[KC][132];
    __shared__ float Ws[KC][FT];

    int tid = threadIdx.x;
    int tx = tid & 15, ty = tid >> 4;
    int rowBase = blockIdx.x * 128;
    int cBase = blockIdx.y * FT;

    float acc[8][TN];
#pragma unroll
    for (int i = 0; i < 8; ++i)
#pragma unroll
        for (int j = 0; j < TN; ++j) acc[i][j] = 0.0f;

    for (int k0 = 0; k0 < K; k0 += KC) {
#pragma unroll
        for (int p = 0; p < 4; ++p) {
            int id = tid + p * 256;
            int r = id >> 3;
            int k4 = id & 7;
            float4 xv = make_float4(0.f, 0.f, 0.f, 0.f);
            int grow = rowBase + r;
            if (grow < M)
                xv = *(const float4*)(X + (size_t)grow * K + k0 + k4 * 4);
            Xs[k4 * 4 + 0][r] = xv.x;
            Xs[k4 * 4 + 1][r] = xv.y;
            Xs[k4 * 4 + 2][r] = xv.z;
            Xs[k4 * 4 + 3][r] = xv.w;
        }
        for (int id = tid; id < KC * FT / 4; id += 256) {
            int kk = (id * 4) / FT;
            int c  = (id * 4) % FT;
            *(float4*)&Ws[kk][c] =
                *(const float4*)(W + (size_t)(k0 + kk) * ldW + cBase + c);
        }
        __syncthreads();

#pragma unroll 8
        for (int kk = 0; kk < KC; ++kk) {
            float xr[8];
            float4 a = *(const float4*)&Xs[kk][ty * 8];
            float4 b = *(const float4*)&Xs[kk][ty * 8 + 4];
            xr[0] = a.x; xr[1] = a.y; xr[2] = a.z; xr[3] = a.w;
            xr[4] = b.x; xr[5] = b.y; xr[6] = b.z; xr[7] = b.w;
            float wv[TN];
            float4 w0 = *(const float4*)&Ws[kk][tx * 8];
            float4 w1 = *(const float4*)&Ws[kk][tx * 8 + 4];
            wv[0] = w0.x; wv[1] = w0.y; wv[2] = w0.z; wv[3] = w0.w;
            wv[4] = w1.x; wv[5] = w1.y; wv[6] = w1.z; wv[7] = w1.w;
#pragma unroll
            for (int i = 0; i < 8; ++i)
#pragma unroll
                for (int j = 0; j < TN; ++j)
                    acc[i][j] += xr[i] * wv[j];
        }
        __syncthreads();
    }

#pragma unroll
    for (int i = 0; i < 8; ++i) {
        int grow = rowBase + ty * 8 + i;
        if (grow >= M) continue;
#pragma unroll
        for (int j = 0; j < TN; ++j) {
            int c = cBase + tx * TN + j;
            float v = acc[i][j];
            if (bias) v += bias[c];
            if (doRelu) v = fmaxf(v, 0.0f);
            OUT[(size_t)grow * ldW + c] = v;
        }
    }
}

// ---------------------------------------------------------------------------
// Pull-based GCN propagation, unrolled x4 gather, bf16 hi/lo split output.
// ---------------------------------------------------------------------------
template<int F>
__global__ __launch_bounds__(256)
void prop_bf_k(const float* __restrict__ H, const int* __restrict__ ptr,
               const int* __restrict__ rows, const float* __restrict__ dinv,
               const float* __restrict__ bias,
               __nv_bfloat16* __restrict__ OHI, __nv_bfloat16* __restrict__ OLO, int n) {
    constexpr int V = F / 32;
    int node = (blockIdx.x * blockDim.x + threadIdx.x) >> 5;
    int lane = threadIdx.x & 31;
    if (node >= n) return;

    const float dn = dinv[node];
    const float selfw = dn * dn;
    const float* hb = H + lane * V;
    float acc[V];
    {
        const float* hp = hb + (size_t)node * F;
        if (V == 4) {
            float4 v = *(const float4*)hp;
            acc[0] = selfw * v.x; acc[1] = selfw * v.y;
            acc[2] = selfw * v.z; acc[3] = selfw * v.w;
        } else {
            float2 v = *(const float2*)hp;
            acc[0] = selfw * v.x; acc[1] = selfw * v.y;
        }
    }

    int beg = ptr[node], end = ptr[node + 1];
    for (int j0 = beg; j0 < end; j0 += 32) {
        int j = j0 + lane;
        int r = 0; float dv = 0.0f;
        if (j < end) { r = rows[j]; dv = dinv[r]; }
        int cnt = min(32, end - j0);
        int t = 0;
        for (; t + 4 <= cnt; t += 4) {
            int rr0 = __shfl_sync(0xffffffffu, r, t);
            int rr1 = __shfl_sync(0xffffffffu, r, t + 1);
            int rr2 = __shfl_sync(0xffffffffu, r, t + 2);
            int rr3 = __shfl_sync(0xffffffffu, r, t + 3);
            float w0 = __shfl_sync(0xffffffffu, dv, t)     * dn;
            float w1 = __shfl_sync(0xffffffffu, dv, t + 1) * dn;
            float w2 = __shfl_sync(0xffffffffu, dv, t + 2) * dn;
            float w3 = __shfl_sync(0xffffffffu, dv, t + 3) * dn;
            if (V == 4) {
                float4 v0 = *(const float4*)(hb + (size_t)rr0 * F);
                float4 v1 = *(const float4*)(hb + (size_t)rr1 * F);
                float4 v2 = *(const float4*)(hb + (size_t)rr2 * F);
                float4 v3 = *(const float4*)(hb + (size_t)rr3 * F);
                acc[0] += w0 * v0.x; acc[1] += w0 * v0.y; acc[2] += w0 * v0.z; acc[3] += w0 * v0.w;
                acc[0] += w1 * v1.x; acc[1] += w1 * v1.y; acc[2] += w1 * v1.z; acc[3] += w1 * v1.w;
                acc[0] += w2 * v2.x; acc[1] += w2 * v2.y; acc[2] += w2 * v2.z; acc[3] += w2 * v2.w;
                acc[0] += w3 * v3.x; acc[1] += w3 * v3.y; acc[2] += w3 * v3.z; acc[3] += w3 * v3.w;
            } else {
                float2 v0 = *(const float2*)(hb + (size_t)rr0 * F);
                float2 v1 = *(const float2*)(hb + (size_t)rr1 * F);
                float2 v2 = *(const float2*)(hb + (size_t)rr2 * F);
                float2 v3 = *(const float2*)(hb + (size_t)rr3 * F);
                acc[0] += w0 * v0.x; acc[1] += w0 * v0.y;
                acc[0] += w1 * v1.x; acc[1] += w1 * v1.y;
                acc[0] += w2 * v2.x; acc[1] += w2 * v2.y;
                acc[0] += w3 * v3.x; acc[1] += w3 * v3.y;
            }
        }
        for (; t < cnt; ++t) {
            int rr  = __shfl_sync(0xffffffffu, r,  t);
            float w = __shfl_sync(0xffffffffu, dv, t) * dn;
            if (V == 4) {
                float4 v = *(const float4*)(hb + (size_t)rr * F);
                acc[0] += w * v.x; acc[1] += w * v.y; acc[2] += w * v.z; acc[3] += w * v.w;
            } else {
                float2 v = *(const float2*)(hb + (size_t)rr * F);
                acc[0] += w * v.x; acc[1] += w * v.y;
            }
        }
    }

    if (V == 4) {
        float f0 = fmaxf(acc[0] + bias[lane * 4 + 0], 0.0f);
        float f1 = fmaxf(acc[1] + bias[lane * 4 + 1], 0.0f);
        float f2 = fmaxf(acc[2] + bias[lane * 4 + 2], 0.0f);
        float f3 = fmaxf(acc[3] + bias[lane * 4 + 3], 0.0f);
        uint32_t h01, l01, h23, l23;
        split2(f0, f1, h01, l01);
        split2(f2, f3, h23, l23);
        *(uint2*)(OHI + (size_t)node * F + lane * 4) = make_uint2(h01, h23);
        *(uint2*)(OLO + (size_t)node * F + lane * 4) = make_uint2(l01, l23);
    } else {
        float f0 = fmaxf(acc[0] + bias[lane * 2 + 0], 0.0f);
        float f1 = fmaxf(acc[1] + bias[lane * 2 + 1], 0.0f);
        uint32_t h, l;
        split2(f0, f1, h, l);
        *(uint32_t*)(OHI + (size_t)node * F + lane * 2) = h;
        *(uint32_t*)(OLO + (size_t)node * F + lane * 2) = l;
    }
}

// F=32 propagation fused with Wa3 dot: s[node] = dot(relu(prop+ba2), Wa3)
__global__ __launch_bounds__(256)
void prop32dot_k(const float* __restrict__ H, const int* __restrict__ ptr,
                 const int* __restrict__ rows, const float* __restrict__ dinv,
                 const float* __restrict__ ba2, const float* __restrict__ Wa3,
                 float* __restrict__ s, int n) {
    int node = (blockIdx.x * blockDim.x + threadIdx.x) >> 5;
    int lane = threadIdx.x & 31;
    if (node >= n) return;

    const float dn = dinv[node];
    float acc = dn * dn * H[(size_t)node * 32 + lane];
    const float* hb = H + lane;

    int beg = ptr[node], end = ptr[node + 1];
    for (int j0 = beg; j0 < end; j0 += 32) {
        int j = j0 + lane;
        int r = 0; float dv = 0.0f;
        if (j < end) { r = rows[j]; dv = dinv[r]; }
        int cnt = min(32, end - j0);
        int t = 0;
        for (; t + 4 <= cnt; t += 4) {
            int rr0 = __shfl_sync(0xffffffffu, r, t);
            int rr1 = __shfl_sync(0xffffffffu, r, t + 1);
            int rr2 = __shfl_sync(0xffffffffu, r, t + 2);
            int rr3 = __shfl_sync(0xffffffffu, r, t + 3);
            float w0 = __shfl_sync(0xffffffffu, dv, t)     * dn;
            float w1 = __shfl_sync(0xffffffffu, dv, t + 1) * dn;
            float w2 = __shfl_sync(0xffffffffu, dv, t + 2) * dn;
            float w3 = __shfl_sync(0xffffffffu, dv, t + 3) * dn;
            float v0 = hb[(size_t)rr0 * 32];
            float v1 = hb[(size_t)rr1 * 32];
            float v2 = hb[(size_t)rr2 * 32];
            float v3 = hb[(size_t)rr3 * 32];
            acc += w0 * v0 + w1 * v1 + w2 * v2 + w3 * v3;
        }
        for (; t < cnt; ++t) {
            int rr  = __shfl_sync(0xffffffffu, r,  t);
            float w = __shfl_sync(0xffffffffu, dv, t) * dn;
            acc += w * hb[(size_t)rr * 32];
        }
    }

    float v = fmaxf(acc + ba2[lane], 0.0f) * Wa3[lane];
#pragma unroll
    for (int o = 16; o; o >>= 1) v += __shfl_down_sync(0xffffffffu, v, o);
    if (lane == 0) s[node] = v;
}

// F=1 propagation fused with segment-max (w >= 0 after relu)
__global__ __launch_bounds__(256)
void prop1_k(const float* __restrict__ H, const int* __restrict__ ptr,
             const int* __restrict__ rows, const float* __restrict__ dinv,
             const float* __restrict__ bias, const int* __restrict__ batch,
             float* __restrict__ OUT, float* __restrict__ gmax, int n) {
    int node = (blockIdx.x * blockDim.x + threadIdx.x) >> 5;
    int lane = threadIdx.x & 31;
    if (node >= n) return;
    float dn = dinv[node];
    int beg = ptr[node], end = ptr[node + 1];
    float acc = 0.0f;
    for (int j = beg + lane; j < end; j += 32) {
        int r = rows[j];
        acc += dinv[r] * H[r];
    }
#pragma unroll
    for (int o = 16; o; o >>= 1) acc += __shfl_down_sync(0xffffffffu, acc, o);
    if (lane == 0) {
        float v = acc * dn + dn * dn * H[node] + bias[0];
        v = fmaxf(v, 0.0f);
        OUT[node] = v;
        atomicMax((unsigned int*)&gmax[batch[node]], __float_as_uint(v));
    }
}

__global__ void expsum_k(const float* __restrict__ w, const int* __restrict__ batch,
                         const float* __restrict__ gmax, float* __restrict__ ew,
                         float* __restrict__ gsum, int n) {
    int i = blockIdx.x * blockDim.x + threadIdx.x;
    if (i < n) {
        int b = batch[i];
        float e = expf(w[i] - gmax[b]);
        ew[i] = e;
        atomicAdd(&gsum[b], e);
    }
}

// attention pooling over x3 stored as bf16 hi/lo
__global__ __launch_bounds__(256)
void pool_k(const __nv_bfloat16* __restrict__ X3hi, const __nv_bfloat16* __restrict__ X3lo,
            const float* __restrict__ ew, const float* __restrict__ gsum,
            const int* __restrict__ batch, float* __restrict__ pooled, int n) {
    int node = (blockIdx.x * blockDim.x + threadIdx.x) >> 5;
    int lane = threadIdx.x & 31;
    if (node >= n) return;
    int b = batch[node];
    float coef = ew[node] / (gsum[b] + 1e-16f);
    uint2 h = *(const uint2*)(X3hi + (size_t)node * 128 + lane * 4);
    uint2 l = *(const uint2*)(X3lo + (size_t)node * 128 + lane * 4);
    float f0 = __uint_as_float(h.x << 16)         + __uint_as_float(l.x << 16);
    float f1 = __uint_as_float(h.x & 0xffff0000u) + __uint_as_float(l.x & 0xffff0000u);
    float f2 = __uint_as_float(h.y << 16)         + __uint_as_float(l.y << 16);
    float f3 = __uint_as_float(h.y & 0xffff0000u) + __uint_as_float(l.y & 0xffff0000u);
    float* pb = pooled + b * 128 + lane * 4;
    atomicAdd(pb + 0, coef * f0);
    atomicAdd(pb + 1, coef * f1);
    atomicAdd(pb + 2, coef * f2);
    atomicAdd(pb + 3, coef * f3);
}

// ---------------------------------------------------------------------------
// Host launcher
// ---------------------------------------------------------------------------
extern "C" void kernel_launch(void* const* d_in, const int* in_sizes, int n_in,
                              void* d_out, int out_size) {
    const float* x     = (const float*)d_in[0];
    const int*   ei    = (const int*)d_in[1];
    const int*   batch = (const int*)d_in[2];
    const float* W1 = (const float*)d_in[3];   const float* b1 = (const float*)d_in[4];
    const float* W2 = (const float*)d_in[5];   const float* b2 = (const float*)d_in[6];
    const float* W3 = (const float*)d_in[7];   const float* b3 = (const float*)d_in[8];
    const float* Wa1 = (const float*)d_in[9];  const float* ba1 = (const float*)d_in[10];
    const float* Wa2 = (const float*)d_in[11]; const float* ba2 = (const float*)d_in[12];
    const float* Wa3 = (const float*)d_in[13]; const float* ba3 = (const float*)d_in[14];
    const float* Wm1 = (const float*)d_in[15]; const float* bm1 = (const float*)d_in[16];
    const float* Wm2 = (const float*)d_in[17]; const float* bm2 = (const float*)d_in[18];

    int N = in_sizes[0] / 128;
    int E = in_sizes[1] / 2;
    const int* row = ei;
    const int* col = ei + E;

    float *G0, *s, *wv, *dinv, *gmax, *gsum, *pooled, *hbuf;
    int *cnt, *ptr, *cur, *rows, *bsum;
    __nv_bfloat16 *Hhi, *Hlo, *X3hi, *X3lo, *wthi, *wtlo;
    cudaGetSymbolAddress((void**)&G0, g_G0);
    cudaGetSymbolAddress((void**)&Hhi, g_Hhi);
    cudaGetSymbolAddress((void**)&Hlo, g_Hlo);
    cudaGetSymbolAddress((void**)&X3hi, g_X3hi);
    cudaGetSymbolAddress((void**)&X3lo, g_X3lo);
    cudaGetSymbolAddress((void**)&s, g_s);
    cudaGetSymbolAddress((void**)&wv, g_wv);
    cudaGetSymbolAddress((void**)&dinv, g_dinv);
    cudaGetSymbolAddress((void**)&cnt, g_cnt);
    cudaGetSymbolAddress((void**)&ptr, g_ptr);
    cudaGetSymbolAddress((void**)&cur, g_cur);
    cudaGetSymbolAddress((void**)&rows, g_rows);
    cudaGetSymbolAddress((void**)&bsum, g_bsum);
    cudaGetSymbolAddress((void**)&gmax, g_gmax);
    cudaGetSymbolAddress((void**)&gsum, g_gsum);
    cudaGetSymbolAddress((void**)&pooled, g_pooled);
    cudaGetSymbolAddress((void**)&hbuf, g_h);
    cudaGetSymbolAddress((void**)&wthi, g_Wthi);
    cudaGetSymbolAddress((void**)&wtlo, g_Wtlo);

    // dynamic smem: A hi/lo (64 x SA) + B hi/lo (N x SA), SA = 2K+16
    const int SM_128_128 = 128 * 272 + 2 * 128 * 272;  // 104448 -> 2 CTAs/SM
    const int SM_128_64  = 128 * 272 + 2 *  64 * 272;  //  69632 -> 3 CTAs/SM
    const int SM_64_32   = 128 * 144 + 2 *  32 * 144;  //  27648
    cudaFuncSetAttribute(hgemm_k<128, 128>,     cudaFuncAttributeMaxDynamicSharedMemorySize, SM_128_128);
    cudaFuncSetAttribute(hgemm_pre_k<128, 128>, cudaFuncAttributeMaxDynamicSharedMemorySize, SM_128_128);
    cudaFuncSetAttribute(hgemm_pre_k<128, 64>,  cudaFuncAttributeMaxDynamicSharedMemorySize, SM_128_64);
    cudaFuncSetAttribute(hgemm_pre_k<64, 32>,   cudaFuncAttributeMaxDynamicSharedMemorySize, SM_64_32);

    int NB = (N + 511) / 512;
    int nInit = (N > 256 * 128) ? N : 256 * 128;

    // --- build CSC + norms ---
    init_k<<<(nInit + 255) / 256, 256>>>(cnt, gmax, gsum, pooled, N);
    count_k<<<(E + 255) / 256, 256>>>(col, cnt, E);
    scan1_k<<<NB, 512>>>(cnt, ptr, bsum, dinv, N);
    scan2_k<<<1, 512>>>(bsum, NB);
    scan3_k<<<(N + 255) / 256, 256>>>(ptr, bsum, cur, N, E);
    fill_k<<<(E + 255) / 256, 256>>>(row, col, cur, rows, E);

    // --- prep weights (one launch) ---
    wprep_all_k<<<(59392 + 255) / 256, 256>>>(W1, W2, W3, Wa1, Wa2, wthi, wtlo);

    int MT = (N + 63) / 64;
    int propBlocks = (N + 7) / 8;

    // --- 3 GCN layers (128 -> 128) ---
    hgemm_k<128, 128><<<MT, 256, SM_128_128>>>(x, wthi + 0, wtlo + 0, G0, N);
    prop_bf_k<128><<<propBlocks, 256>>>(G0, ptr, rows, dinv, b1, Hhi, Hlo, N);
    hgemm_pre_k<128, 128><<<MT, 256, SM_128_128>>>(Hhi, Hlo, wthi + 16384, wtlo + 16384, G0, N);
    prop_bf_k<128><<<propBlocks, 256>>>(G0, ptr, rows, dinv, b2, Hhi, Hlo, N);
    hgemm_pre_k<128, 128><<<MT, 256, SM_128_128>>>(Hhi, Hlo, wthi + 32768, wtlo + 32768, G0, N);
    prop_bf_k<128><<<propBlocks, 256>>>(G0, ptr, rows, dinv, b3, X3hi, X3lo, N);

    // --- attention branch (128 -> 64 -> 32 -> 1) ---
    hgemm_pre_k<128, 64><<<MT, 256, SM_128_64>>>(X3hi, X3lo, wthi + 49152, wtlo + 49152, G0, N);
    prop_bf_k<64><<<propBlocks, 256>>>(G0, ptr, rows, dinv, ba1, Hhi, Hlo, N);
    hgemm_pre_k<64, 32><<<MT, 256, SM_64_32>>>(Hhi, Hlo, wthi + 57344, wtlo + 57344, G0, N);
    prop32dot_k<<<propBlocks, 256>>>(G0, ptr, rows, dinv, ba2, Wa3, s, N);
    prop1_k<<<propBlocks, 256>>>(s, ptr, rows, dinv, ba3, batch, wv, gmax, N);

    // --- segment softmax + attention pooling ---
    expsum_k<<<(N + 255) / 256, 256>>>(wv, batch, gmax, s, gsum, N);
    pool_k<<<propBlocks, 256>>>(X3hi, X3lo, s, gsum, batch, pooled, N);

    // --- MLP head ---
    sgemm_k<128, 128><<<dim3(2, 1), 256>>>(pooled, Wm1, bm1, hbuf, 256, 128, 1);
    sgemm_k<128, 128><<<dim3(2, 2), 256>>>(hbuf, Wm2, bm2, (float*)d_out, 256, 256, 0);
}

// round 6
// speedup vs baseline: 1.4262x; 1.1590x over previous
#include <cuda_runtime.h>
#include <cuda_bf16.h>
#include <cstdint>

// ---------------------------------------------------------------------------
// Static scratch (no allocation allowed)
// ---------------------------------------------------------------------------
#define NMAX 100000
#define EMAX 1600000

__device__ float g_G0[NMAX * 128];                 // fp32 GEMM outputs / gather input
__device__ __nv_bfloat16 g_Hhi[NMAX * 128];        // prop output hi (recycled)
__device__ __nv_bfloat16 g_Hlo[NMAX * 128];        // prop output lo
__device__ __nv_bfloat16 g_X3hi[NMAX * 128];       // layer-3 output hi (kept for pool)
__device__ __nv_bfloat16 g_X3lo[NMAX * 128];
__device__ float g_s [NMAX];                       // attention scalar
__device__ float g_wv[NMAX];
__device__ float g_dinv[NMAX];
__device__ int   g_cnt[NMAX];
__device__ int   g_ptr[NMAX + 1];
__device__ int   g_cur[NMAX];
__device__ int   g_rows[EMAX];
__device__ int   g_bsum[512];
__device__ float g_gmax[256];
__device__ float g_gsum[256];
__device__ float g_pooled[256 * 128];
__device__ float g_h[256 * 128];
__device__ __nv_bfloat16 g_Wthi[65536];
__device__ __nv_bfloat16 g_Wtlo[65536];

// ---------------------------------------------------------------------------
// Helpers
// ---------------------------------------------------------------------------
__device__ __forceinline__ uint32_t smem_u32(const void* p) {
    uint32_t a;
    asm("{ .reg .u64 t; cvta.to.shared.u64 t, %1; cvt.u32.u64 %0, t; }"
        : "=r"(a) : "l"(p));
    return a;
}

__device__ __forceinline__ void ldsm_x4(uint32_t& r0, uint32_t& r1,
                                        uint32_t& r2, uint32_t& r3, uint32_t addr) {
    asm volatile("ldmatrix.sync.aligned.m8n8.x4.shared.b16 {%0,%1,%2,%3}, [%4];"
                 : "=r"(r0), "=r"(r1), "=r"(r2), "=r"(r3) : "r"(addr));
}

__device__ __forceinline__ void mma_bf16(float* c, uint32_t a0, uint32_t a1,
                                         uint32_t a2, uint32_t a3,
                                         uint32_t b0, uint32_t b1) {
    asm volatile(
        "mma.sync.aligned.m16n8k16.row.col.f32.bf16.bf16.f32 "
        "{%0,%1,%2,%3}, {%4,%5,%6,%7}, {%8,%9}, {%0,%1,%2,%3};"
        : "+f"(c[0]), "+f"(c[1]), "+f"(c[2]), "+f"(c[3])
        : "r"(a0), "r"(a1), "r"(a2), "r"(a3), "r"(b0), "r"(b1));
}

// cp.async 16B copy, zero-fill when sz == 0
__device__ __forceinline__ void cp16(uint32_t dst, const void* src, int sz) {
    asm volatile("cp.async.cg.shared.global [%0], [%1], 16, %2;"
                 :: "r"(dst), "l"(src), "r"(sz));
}
__device__ __forceinline__ void cp_commit_wait() {
    asm volatile("cp.async.commit_group;");
    asm volatile("cp.async.wait_group 0;");
}

// Packed split: (f0,f1) fp32 -> hi bf16x2 + lo bf16x2 (lo = rounded residual)
__device__ __forceinline__ void split2(float f0, float f1, uint32_t& h, uint32_t& l) {
    asm("cvt.rn.bf16x2.f32 %0, %1, %2;" : "=r"(h) : "f"(f1), "f"(f0));
    float h0 = __uint_as_float(h << 16);
    float h1 = __uint_as_float(h & 0xffff0000u);
    asm("cvt.rn.bf16x2.f32 %0, %1, %2;" : "=r"(l) : "f"(f1 - h1), "f"(f0 - h0));
}

// ---------------------------------------------------------------------------
// Fused weight prep (5 matrices, one launch). W is [K, N] row-major.
// ---------------------------------------------------------------------------
__global__ void wprep_all_k(const float* __restrict__ W1, const float* __restrict__ W2,
                            const float* __restrict__ W3, const float* __restrict__ Wa1,
                            const float* __restrict__ Wa2,
                            __nv_bfloat16* __restrict__ hi, __nv_bfloat16* __restrict__ lo) {
    int idx = blockIdx.x * blockDim.x + threadIdx.x;
    const float* W; int K, N, local;
    if (idx < 16384)      { W = W1;  K = 128; N = 128; local = idx; }
    else if (idx < 32768) { W = W2;  K = 128; N = 128; local = idx - 16384; }
    else if (idx < 49152) { W = W3;  K = 128; N = 128; local = idx - 32768; }
    else if (idx < 57344) { W = Wa1; K = 128; N = 64;  local = idx - 49152; }
    else if (idx < 59392) { W = Wa2; K = 64;  N = 32;  local = idx - 57344; }
    else return;
    int n = local / K, k = local % K;
    float v = W[(size_t)k * N + n];
    __nv_bfloat16 h = __float2bfloat16(v);
    __nv_bfloat16 l = __float2bfloat16(v - __bfloat162float(h));
    hi[idx] = h;
    lo[idx] = l;
}

// ---------------------------------------------------------------------------
// HMMA GEMM, 64-row M tiles, single-sweep mainloop with hi/lo fragment reuse.
// 256 threads = 8 warps (4M x 2N); warp: 16 rows x N/2 cols.
// ---------------------------------------------------------------------------
template<int K, int N>
__device__ __forceinline__ void hgemm_core64(uint32_t sb, float* __restrict__ OUT,
                                             int M, int rowBase) {
    constexpr int SA = K * 2 + 16;
    constexpr int A_HI = 0;
    constexpr int A_LO = 64 * SA;
    constexpr int B_HI = 128 * SA;
    constexpr int B_LO = B_HI + N * SA;
    constexpr int NW = N / 2;
    constexpr int NT = NW / 8;

    const int tid = threadIdx.x;
    const int warp = tid >> 5;
    const int lane = tid & 31;
    const int wm = warp & 3;
    const int wn = warp >> 2;

    float acc[NT][4];
#pragma unroll
    for (int i = 0; i < NT; ++i)
#pragma unroll
        for (int j = 0; j < 4; ++j) acc[i][j] = 0.0f;

    const int m0 = wm * 16;
    const int q = lane >> 3;
    const int r8 = lane & 7;
    const uint32_t aRowOff = (uint32_t)(m0 + (q & 1) * 8 + r8) * SA + (uint32_t)(q >> 1) * 16;
    const uint32_t bOff = (uint32_t)(wn * NW + (q >> 1) * 8 + r8) * SA + (uint32_t)(q & 1) * 16;

    const uint32_t aHi = sb + A_HI + aRowOff;
    const uint32_t aLo = sb + A_LO + aRowOff;
    const uint32_t bHi = sb + B_HI + bOff;
    const uint32_t bLo = sb + B_LO + bOff;

#pragma unroll
    for (int kc = 0; kc < K / 16; ++kc) {
        uint32_t ah0, ah1, ah2, ah3, al0, al1, al2, al3;
        ldsm_x4(ah0, ah1, ah2, ah3, aHi + kc * 32);
        ldsm_x4(al0, al1, al2, al3, aLo + kc * 32);
#pragma unroll
        for (int nt2 = 0; nt2 < NW / 16; ++nt2) {
            uint32_t b0, b1, b2, b3;
            ldsm_x4(b0, b1, b2, b3, bHi + (uint32_t)(nt2 * 16) * SA + kc * 32);
            mma_bf16(acc[2 * nt2],     ah0, ah1, ah2, ah3, b0, b1);
            mma_bf16(acc[2 * nt2 + 1], ah0, ah1, ah2, ah3, b2, b3);
            mma_bf16(acc[2 * nt2],     al0, al1, al2, al3, b0, b1);
            mma_bf16(acc[2 * nt2 + 1], al0, al1, al2, al3, b2, b3);
            ldsm_x4(b0, b1, b2, b3, bLo + (uint32_t)(nt2 * 16) * SA + kc * 32);
            mma_bf16(acc[2 * nt2],     ah0, ah1, ah2, ah3, b0, b1);
            mma_bf16(acc[2 * nt2 + 1], ah0, ah1, ah2, ah3, b2, b3);
        }
    }

    const int row0 = rowBase + m0 + (lane >> 2);
    const int row1 = row0 + 8;
    const int cbase = wn * NW + (lane & 3) * 2;
#pragma unroll
    for (int nt = 0; nt < NT; ++nt) {
        if (row0 < M)
            *(float2*)(OUT + (size_t)row0 * N + cbase + nt * 8) = make_float2(acc[nt][0], acc[nt][1]);
        if (row1 < M)
            *(float2*)(OUT + (size_t)row1 * N + cbase + nt * 8) = make_float2(acc[nt][2], acc[nt][3]);
    }
}

// B staging via cp.async (rows are K*2 bytes packed in global, SA-padded in smem)
template<int K, int N>
__device__ __forceinline__ void stage_B64(uint32_t sb,
                                          const __nv_bfloat16* __restrict__ WThi,
                                          const __nv_bfloat16* __restrict__ WTlo) {
    constexpr int SA = K * 2 + 16;
    constexpr int B_HI = 128 * SA;
    constexpr int B_LO = B_HI + N * SA;
    constexpr int CH = K / 8;            // 16B chunks per row
    const int tid = threadIdx.x;
    for (int i = tid; i < N * CH; i += 256) {
        int n = i / CH;
        int c = i % CH;
        cp16(sb + B_HI + n * SA + c * 16, (const char*)WThi + n * (K * 2) + c * 16, 16);
        cp16(sb + B_LO + n * SA + c * 16, (const char*)WTlo + n * (K * 2) + c * 16, 16);
    }
}

// Variant 1: A fp32 in global (layer 1) — converts in-kernel.
template<int K, int N>
__global__ __launch_bounds__(256, 2)
void hgemm_k(const float* __restrict__ X,
             const __nv_bfloat16* __restrict__ WThi,
             const __nv_bfloat16* __restrict__ WTlo,
             float* __restrict__ OUT, int M) {
    extern __shared__ char smem[];
    constexpr int SA = K * 2 + 16;
    constexpr int A_HI = 0;
    constexpr int A_LO = 64 * SA;
    const int tid = threadIdx.x;
    const int rowBase = blockIdx.x * 64;
    const uint32_t sb = smem_u32(smem);

    stage_B64<K, N>(sb, WThi, WTlo);

    for (int item = tid; item < 64 * (K / 8); item += 256) {
        int r = item / (K / 8);
        int k0 = (item % (K / 8)) * 8;
        float v[8];
        int grow = rowBase + r;
        if (grow < M) {
            const float4* p = (const float4*)(X + (size_t)grow * K + k0);
            float4 a = p[0], b = p[1];
            v[0] = a.x; v[1] = a.y; v[2] = a.z; v[3] = a.w;
            v[4] = b.x; v[5] = b.y; v[6] = b.z; v[7] = b.w;
        } else {
#pragma unroll
            for (int j = 0; j < 8; ++j) v[j] = 0.0f;
        }
        uint32_t hw[4], lw[4];
#pragma unroll
        for (int j = 0; j < 4; ++j) split2(v[2 * j], v[2 * j + 1], hw[j], lw[j]);
        *(uint4*)(smem + A_HI + r * SA + k0 * 2) = make_uint4(hw[0], hw[1], hw[2], hw[3]);
        *(uint4*)(smem + A_LO + r * SA + k0 * 2) = make_uint4(lw[0], lw[1], lw[2], lw[3]);
    }
    cp_commit_wait();
    __syncthreads();
    hgemm_core64<K, N>(sb, OUT, M, rowBase);
}

// Variant 2: A pre-split bf16 hi/lo in global — cp.async staging.
template<int K, int N>
__global__ __launch_bounds__(256, 2)
void hgemm_pre_k(const __nv_bfloat16* __restrict__ Ahi,
                 const __nv_bfloat16* __restrict__ Alo,
                 const __nv_bfloat16* __restrict__ WThi,
                 const __nv_bfloat16* __restrict__ WTlo,
                 float* __restrict__ OUT, int M) {
    extern __shared__ char smem[];
    constexpr int SA = K * 2 + 16;
    constexpr int A_HI = 0;
    constexpr int A_LO = 64 * SA;
    constexpr int CH = K / 8;
    const int tid = threadIdx.x;
    const int rowBase = blockIdx.x * 64;
    const uint32_t sb = smem_u32(smem);

    stage_B64<K, N>(sb, WThi, WTlo);

    for (int item = tid; item < 64 * CH; item += 256) {
        int r = item / CH;
        int c = item % CH;
        int grow = rowBase + r;
        int inb = grow < M;
        size_t off = (size_t)(inb ? grow : 0) * K + c * 8;
        int sz = inb ? 16 : 0;
        cp16(sb + A_HI + r * SA + c * 16, (const char*)Ahi + off * 2, sz);
        cp16(sb + A_LO + r * SA + c * 16, (const char*)Alo + off * 2, sz);
    }
    cp_commit_wait();
    __syncthreads();
    hgemm_core64<K, N>(sb, OUT, M, rowBase);
}

// ---------------------------------------------------------------------------
// CSC build + norms
// ---------------------------------------------------------------------------
__global__ void init_k(int* cnt, float* gmax, float* gsum, float* pooled, int n) {
    int i = blockIdx.x * blockDim.x + threadIdx.x;
    if (i < n) cnt[i] = 0;
    if (i < 256) { gmax[i] = 0.0f; gsum[i] = 0.0f; }
    if (i < 256 * 128) pooled[i] = 0.0f;
}

__global__ void count_k(const int* __restrict__ col, int* __restrict__ cnt, int e) {
    int i = blockIdx.x * blockDim.x + threadIdx.x;
    if (i < e) atomicAdd(&cnt[col[i]], 1);
}

__global__ void scan1_k(const int* __restrict__ cnt, int* __restrict__ ptr,
                        int* __restrict__ bsum, float* __restrict__ dinv, int n) {
    __shared__ int s[512];
    int t = threadIdx.x;
    int i = blockIdx.x * 512 + t;
    int v = (i < n) ? cnt[i] : 0;
    if (i < n) dinv[i] = rsqrtf((float)v + 1.0f);
    s[t] = v; __syncthreads();
    for (int off = 1; off < 512; off <<= 1) {
        int tmp = (t >= off) ? s[t - off] : 0;
        __syncthreads();
        s[t] += tmp;
        __syncthreads();
    }
    if (i < n) ptr[i] = s[t] - v;
    if (t == 511) bsum[blockIdx.x] = s[511];
}

__global__ void scan2_k(int* __restrict__ bsum, int nb) {
    __shared__ int s[512];
    int t = threadIdx.x;
    int v = (t < nb) ? bsum[t] : 0;
    s[t] = v; __syncthreads();
    for (int off = 1; off < 512; off <<= 1) {
        int tmp = (t >= off) ? s[t - off] : 0;
        __syncthreads();
        s[t] += tmp;
        __syncthreads();
    }
    if (t < nb) bsum[t] = s[t] - v;
}

__global__ void scan3_k(int* __restrict__ ptr, const int* __restrict__ bsum,
                        int* __restrict__ cur, int n, int etot) {
    int i = blockIdx.x * blockDim.x + threadIdx.x;
    if (i < n) {
        int p = ptr[i] + bsum[i >> 9];
        ptr[i] = p;
        cur[i] = p;
    }
    if (i == 0) ptr[n] = etot;
}

__global__ void fill_k(const int* __restrict__ row, const int* __restrict__ col,
                       int* __restrict__ cur, int* __restrict__ rows, int e) {
    int i = blockIdx.x * blockDim.x + threadIdx.x;
    if (i < e) {
        int c = col[i];
        int p = atomicAdd(&cur[c], 1);
        rows[p] = row[i];
    }
}

// ---------------------------------------------------------------------------
// SIMT SGEMM (tiny MLP head only)
// ---------------------------------------------------------------------------
template<int K, int FT>
__global__ __launch_bounds__(256)
void sgemm_k(const float* __restrict__ X, const float* __restrict__ W,
             const float* __restrict__ bias, float* __restrict__ OUT,
             int M, int ldW, int doRelu) {
    constexpr int KC = 32;
    constexpr int TN = FT / 16;
    __shared__ float Xs[KC][132];
    __shared__ float Ws[KC][FT];

    int tid = threadIdx.x;
    int tx = tid & 15, ty = tid >> 4;
    int rowBase = blockIdx.x * 128;
    int cBase = blockIdx.y * FT;

    float acc[8][TN];
#pragma unroll
    for (int i = 0; i < 8; ++i)
#pragma unroll
        for (int j = 0; j < TN; ++j) acc[i][j] = 0.0f;

    for (int k0 = 0; k0 < K; k0 += KC) {
#pragma unroll
        for (int p = 0; p < 4; ++p) {
            int id = tid + p * 256;
            int r = id >> 3;
            int k4 = id & 7;
            float4 xv = make_float4(0.f, 0.f, 0.f, 0.f);
            int grow = rowBase + r;
            if (grow < M)
                xv = *(const float4*)(X + (size_t)grow * K + k0 + k4 * 4);
            Xs[k4 * 4 + 0][r] = xv.x;
            Xs[k4 * 4 + 1][r] = xv.y;
            Xs[k4 * 4 + 2][r] = xv.z;
            Xs[k4 * 4 + 3][r] = xv.w;
        }
        for (int id = tid; id < KC * FT / 4; id += 256) {
            int kk = (id * 4) / FT;
            int c  = (id * 4) % FT;
            *(float4*)&Ws[kk][c] =
                *(const float4*)(W + (size_t)(k0 + kk) * ldW + cBase + c);
        }
        __syncthreads();

#pragma unroll 8
        for (int kk = 0; kk < KC; ++kk) {
            float xr[8];
            float4 a = *(const float4*)&Xs[kk][ty * 8];
            float4 b = *(const float4*)&Xs[kk][ty * 8 + 4];
            xr[0] = a.x; xr[1] = a.y; xr[2] = a.z; xr[3] = a.w;
            xr[4] = b.x; xr[5] = b.y; xr[6] = b.z; xr[7] = b.w;
            float wv[TN];
            float4 w0 = *(const float4*)&Ws[kk][tx * 8];
            float4 w1 = *(const float4*)&Ws[kk][tx * 8 + 4];
            wv[0] = w0.x; wv[1] = w0.y; wv[2] = w0.z; wv[3] = w0.w;
            wv[4] = w1.x; wv[5] = w1.y; wv[6] = w1.z; wv[7] = w1.w;
#pragma unroll
            for (int i = 0; i < 8; ++i)
#pragma unroll
                for (int j = 0; j < TN; ++j)
                    acc[i][j] += xr[i] * wv[j];
        }
        __syncthreads();
    }

#pragma unroll
    for (int i = 0; i < 8; ++i) {
        int grow = rowBase + ty * 8 + i;
        if (grow >= M) continue;
#pragma unroll
        for (int j = 0; j < TN; ++j) {
            int c = cBase + tx * TN + j;
            float v = acc[i][j];
            if (bias) v += bias[c];
            if (doRelu) v = fmaxf(v, 0.0f);
            OUT[(size_t)grow * ldW + c] = v;
        }
    }
}

// ---------------------------------------------------------------------------
// Pull-based GCN propagation, unrolled x4 gather, bf16 hi/lo split output.
// ---------------------------------------------------------------------------
template<int F>
__global__ __launch_bounds__(256)
void prop_bf_k(const float* __restrict__ H, const int* __restrict__ ptr,
               const int* __restrict__ rows, const float* __restrict__ dinv,
               const float* __restrict__ bias,
               __nv_bfloat16* __restrict__ OHI, __nv_bfloat16* __restrict__ OLO, int n) {
    constexpr int V = F / 32;
    int node = (blockIdx.x * blockDim.x + threadIdx.x) >> 5;
    int lane = threadIdx.x & 31;
    if (node >= n) return;

    const float dn = dinv[node];
    const float selfw = dn * dn;
    const float* hb = H + lane * V;
    float acc[V];
    {
        const float* hp = hb + (size_t)node * F;
        if (V == 4) {
            float4 v = *(const float4*)hp;
            acc[0] = selfw * v.x; acc[1] = selfw * v.y;
            acc[2] = selfw * v.z; acc[3] = selfw * v.w;
        } else {
            float2 v = *(const float2*)hp;
            acc[0] = selfw * v.x; acc[1] = selfw * v.y;
        }
    }

    int beg = ptr[node], end = ptr[node + 1];
    for (int j0 = beg; j0 < end; j0 += 32) {
        int j = j0 + lane;
        int r = 0; float dv = 0.0f;
        if (j < end) { r = rows[j]; dv = dinv[r]; }
        int cnt = min(32, end - j0);
        int t = 0;
        for (; t + 4 <= cnt; t += 4) {
            int rr0 = __shfl_sync(0xffffffffu, r, t);
            int rr1 = __shfl_sync(0xffffffffu, r, t + 1);
            int rr2 = __shfl_sync(0xffffffffu, r, t + 2);
            int rr3 = __shfl_sync(0xffffffffu, r, t + 3);
            float w0 = __shfl_sync(0xffffffffu, dv, t)     * dn;
            float w1 = __shfl_sync(0xffffffffu, dv, t + 1) * dn;
            float w2 = __shfl_sync(0xffffffffu, dv, t + 2) * dn;
            float w3 = __shfl_sync(0xffffffffu, dv, t + 3) * dn;
            if (V == 4) {
                float4 v0 = *(const float4*)(hb + (size_t)rr0 * F);
                float4 v1 = *(const float4*)(hb + (size_t)rr1 * F);
                float4 v2 = *(const float4*)(hb + (size_t)rr2 * F);
                float4 v3 = *(const float4*)(hb + (size_t)rr3 * F);
                acc[0] += w0 * v0.x; acc[1] += w0 * v0.y; acc[2] += w0 * v0.z; acc[3] += w0 * v0.w;
                acc[0] += w1 * v1.x; acc[1] += w1 * v1.y; acc[2] += w1 * v1.z; acc[3] += w1 * v1.w;
                acc[0] += w2 * v2.x; acc[1] += w2 * v2.y; acc[2] += w2 * v2.z; acc[3] += w2 * v2.w;
                acc[0] += w3 * v3.x; acc[1] += w3 * v3.y; acc[2] += w3 * v3.z; acc[3] += w3 * v3.w;
            } else {
                float2 v0 = *(const float2*)(hb + (size_t)rr0 * F);
                float2 v1 = *(const float2*)(hb + (size_t)rr1 * F);
                float2 v2 = *(const float2*)(hb + (size_t)rr2 * F);
                float2 v3 = *(const float2*)(hb + (size_t)rr3 * F);
                acc[0] += w0 * v0.x; acc[1] += w0 * v0.y;
                acc[0] += w1 * v1.x; acc[1] += w1 * v1.y;
                acc[0] += w2 * v2.x; acc[1] += w2 * v2.y;
                acc[0] += w3 * v3.x; acc[1] += w3 * v3.y;
            }
        }
        for (; t < cnt; ++t) {
            int rr  = __shfl_sync(0xffffffffu, r,  t);
            float w = __shfl_sync(0xffffffffu, dv, t) * dn;
            if (V == 4) {
                float4 v = *(const float4*)(hb + (size_t)rr * F);
                acc[0] += w * v.x; acc[1] += w * v.y; acc[2] += w * v.z; acc[3] += w * v.w;
            } else {
                float2 v = *(const float2*)(hb + (size_t)rr * F);
                acc[0] += w * v.x; acc[1] += w * v.y;
            }
        }
    }

    if (V == 4) {
        float f0 = fmaxf(acc[0] + bias[lane * 4 + 0], 0.0f);
        float f1 = fmaxf(acc[1] + bias[lane * 4 + 1], 0.0f);
        float f2 = fmaxf(acc[2] + bias[lane * 4 + 2], 0.0f);
        float f3 = fmaxf(acc[3] + bias[lane * 4 + 3], 0.0f);
        uint32_t h01, l01, h23, l23;
        split2(f0, f1, h01, l01);
        split2(f2, f3, h23, l23);
        *(uint2*)(OHI + (size_t)node * F + lane * 4) = make_uint2(h01, h23);
        *(uint2*)(OLO + (size_t)node * F + lane * 4) = make_uint2(l01, l23);
    } else {
        float f0 = fmaxf(acc[0] + bias[lane * 2 + 0], 0.0f);
        float f1 = fmaxf(acc[1] + bias[lane * 2 + 1], 0.0f);
        uint32_t h, l;
        split2(f0, f1, h, l);
        *(uint32_t*)(OHI + (size_t)node * F + lane * 2) = h;
        *(uint32_t*)(OLO + (size_t)node * F + lane * 2) = l;
    }
}

// F=32 propagation fused with Wa3 dot
__global__ __launch_bounds__(256)
void prop32dot_k(const float* __restrict__ H, const int* __restrict__ ptr,
                 const int* __restrict__ rows, const float* __restrict__ dinv,
                 const float* __restrict__ ba2, const float* __restrict__ Wa3,
                 float* __restrict__ s, int n) {
    int node = (blockIdx.x * blockDim.x + threadIdx.x) >> 5;
    int lane = threadIdx.x & 31;
    if (node >= n) return;

    const float dn = dinv[node];
    float acc = dn * dn * H[(size_t)node * 32 + lane];
    const float* hb = H + lane;

    int beg = ptr[node], end = ptr[node + 1];
    for (int j0 = beg; j0 < end; j0 += 32) {
        int j = j0 + lane;
        int r = 0; float dv = 0.0f;
        if (j < end) { r = rows[j]; dv = dinv[r]; }
        int cnt = min(32, end - j0);
        int t = 0;
        for (; t + 4 <= cnt; t += 4) {
            int rr0 = __shfl_sync(0xffffffffu, r, t);
            int rr1 = __shfl_sync(0xffffffffu, r, t + 1);
            int rr2 = __shfl_sync(0xffffffffu, r, t + 2);
            int rr3 = __shfl_sync(0xffffffffu, r, t + 3);
            float w0 = __shfl_sync(0xffffffffu, dv, t)     * dn;
            float w1 = __shfl_sync(0xffffffffu, dv, t + 1) * dn;
            float w2 = __shfl_sync(0xffffffffu, dv, t + 2) * dn;
            float w3 = __shfl_sync(0xffffffffu, dv, t + 3) * dn;
            acc += w0 * hb[(size_t)rr0 * 32] + w1 * hb[(size_t)rr1 * 32]
                 + w2 * hb[(size_t)rr2 * 32] + w3 * hb[(size_t)rr3 * 32];
        }
        for (; t < cnt; ++t) {
            int rr  = __shfl_sync(0xffffffffu, r,  t);
            float w = __shfl_sync(0xffffffffu, dv, t) * dn;
            acc += w * hb[(size_t)rr * 32];
        }
    }

    float v = fmaxf(acc + ba2[lane], 0.0f) * Wa3[lane];
#pragma unroll
    for (int o = 16; o; o >>= 1) v += __shfl_down_sync(0xffffffffu, v, o);
    if (lane == 0) s[node] = v;
}

// F=1 propagation fused with segment-max
__global__ __launch_bounds__(256)
void prop1_k(const float* __restrict__ H, const int* __restrict__ ptr,
             const int* __restrict__ rows, const float* __restrict__ dinv,
             const float* __restrict__ bias, const int* __restrict__ batch,
             float* __restrict__ OUT, float* __restrict__ gmax, int n) {
    int node = (blockIdx.x * blockDim.x + threadIdx.x) >> 5;
    int lane = threadIdx.x & 31;
    if (node >= n) return;
    float dn = dinv[node];
    int beg = ptr[node], end = ptr[node + 1];
    float acc = 0.0f;
    for (int j = beg + lane; j < end; j += 32) {
        int r = rows[j];
        acc += dinv[r] * H[r];
    }
#pragma unroll
    for (int o = 16; o; o >>= 1) acc += __shfl_down_sync(0xffffffffu, acc, o);
    if (lane == 0) {
        float v = acc * dn + dn * dn * H[node] + bias[0];
        v = fmaxf(v, 0.0f);
        OUT[node] = v;
        atomicMax((unsigned int*)&gmax[batch[node]], __float_as_uint(v));
    }
}

// Fused exp + unnormalized pooling: pooled[b] += e * x3, gsum[b] += e
__global__ __launch_bounds__(256)
void pool_k(const __nv_bfloat16* __restrict__ X3hi, const __nv_bfloat16* __restrict__ X3lo,
            const float* __restrict__ wv, const float* __restrict__ gmax,
            const int* __restrict__ batch, float* __restrict__ pooled,
            float* __restrict__ gsum, int n) {
    int node = (blockIdx.x * blockDim.x + threadIdx.x) >> 5;
    int lane = threadIdx.x & 31;
    if (node >= n) return;
    int b = batch[node];
    float e = expf(wv[node] - gmax[b]);
    if (lane == 0) atomicAdd(&gsum[b], e);
    uint2 h = *(const uint2*)(X3hi + (size_t)node * 128 + lane * 4);
    uint2 l = *(const uint2*)(X3lo + (size_t)node * 128 + lane * 4);
    float f0 = __uint_as_float(h.x << 16)         + __uint_as_float(l.x << 16);
    float f1 = __uint_as_float(h.x & 0xffff0000u) + __uint_as_float(l.x & 0xffff0000u);
    float f2 = __uint_as_float(h.y << 16)         + __uint_as_float(l.y << 16);
    float f3 = __uint_as_float(h.y & 0xffff0000u) + __uint_as_float(l.y & 0xffff0000u);
    float* pb = pooled + b * 128 + lane * 4;
    atomicAdd(pb + 0, e * f0);
    atomicAdd(pb + 1, e * f1);
    atomicAdd(pb + 2, e * f2);
    atomicAdd(pb + 3, e * f3);
}

// normalize pooled by gsum
__global__ void norm_k(float* __restrict__ pooled, const float* __restrict__ gsum) {
    int i = blockIdx.x * blockDim.x + threadIdx.x;
    if (i < 256 * 128) pooled[i] = pooled[i] / (gsum[i >> 7] + 1e-16f);
}

// ---------------------------------------------------------------------------
// Host launcher
// ---------------------------------------------------------------------------
extern "C" void kernel_launch(void* const* d_in, const int* in_sizes, int n_in,
                              void* d_out, int out_size) {
    const float* x     = (const float*)d_in[0];
    const int*   ei    = (const int*)d_in[1];
    const int*   batch = (const int*)d_in[2];
    const float* W1 = (const float*)d_in[3];   const float* b1 = (const float*)d_in[4];
    const float* W2 = (const float*)d_in[5];   const float* b2 = (const float*)d_in[6];
    const float* W3 = (const float*)d_in[7];   const float* b3 = (const float*)d_in[8];
    const float* Wa1 = (const float*)d_in[9];  const float* ba1 = (const float*)d_in[10];
    const float* Wa2 = (const float*)d_in[11]; const float* ba2 = (const float*)d_in[12];
    const float* Wa3 = (const float*)d_in[13]; const float* ba3 = (const float*)d_in[14];
    const float* Wm1 = (const float*)d_in[15]; const float* bm1 = (const float*)d_in[16];
    const float* Wm2 = (const float*)d_in[17]; const float* bm2 = (const float*)d_in[18];

    int N = in_sizes[0] / 128;
    int E = in_sizes[1] / 2;
    const int* row = ei;
    const int* col = ei + E;

    float *G0, *s, *wv, *dinv, *gmax, *gsum, *pooled, *hbuf;
    int *cnt, *ptr, *cur, *rows, *bsum;
    __nv_bfloat16 *Hhi, *Hlo, *X3hi, *X3lo, *wthi, *wtlo;
    cudaGetSymbolAddress((void**)&G0, g_G0);
    cudaGetSymbolAddress((void**)&Hhi, g_Hhi);
    cudaGetSymbolAddress((void**)&Hlo, g_Hlo);
    cudaGetSymbolAddress((void**)&X3hi, g_X3hi);
    cudaGetSymbolAddress((void**)&X3lo, g_X3lo);
    cudaGetSymbolAddress((void**)&s, g_s);
    cudaGetSymbolAddress((void**)&wv, g_wv);
    cudaGetSymbolAddress((void**)&dinv, g_dinv);
    cudaGetSymbolAddress((void**)&cnt, g_cnt);
    cudaGetSymbolAddress((void**)&ptr, g_ptr);
    cudaGetSymbolAddress((void**)&cur, g_cur);
    cudaGetSymbolAddress((void**)&rows, g_rows);
    cudaGetSymbolAddress((void**)&bsum, g_bsum);
    cudaGetSymbolAddress((void**)&gmax, g_gmax);
    cudaGetSymbolAddress((void**)&gsum, g_gsum);
    cudaGetSymbolAddress((void**)&pooled, g_pooled);
    cudaGetSymbolAddress((void**)&hbuf, g_h);
    cudaGetSymbolAddress((void**)&wthi, g_Wthi);
    cudaGetSymbolAddress((void**)&wtlo, g_Wtlo);

    const int SM_128_128 = 128 * 272 + 2 * 128 * 272;  // 104448 -> 2 CTAs/SM
    const int SM_128_64  = 128 * 272 + 2 *  64 * 272;  //  69632
    const int SM_64_32   = 128 * 144 + 2 *  32 * 144;  //  27648
    cudaFuncSetAttribute(hgemm_k<128, 128>,     cudaFuncAttributeMaxDynamicSharedMemorySize, SM_128_128);
    cudaFuncSetAttribute(hgemm_pre_k<128, 128>, cudaFuncAttributeMaxDynamicSharedMemorySize, SM_128_128);
    cudaFuncSetAttribute(hgemm_pre_k<128, 64>,  cudaFuncAttributeMaxDynamicSharedMemorySize, SM_128_64);
    cudaFuncSetAttribute(hgemm_pre_k<64, 32>,   cudaFuncAttributeMaxDynamicSharedMemorySize, SM_64_32);

    int NB = (N + 511) / 512;
    int nInit = (N > 256 * 128) ? N : 256 * 128;

    // --- build CSC + norms ---
    init_k<<<(nInit + 255) / 256, 256>>>(cnt, gmax, gsum, pooled, N);
    count_k<<<(E + 255) / 256, 256>>>(col, cnt, E);
    scan1_k<<<NB, 512>>>(cnt, ptr, bsum, dinv, N);
    scan2_k<<<1, 512>>>(bsum, NB);
    scan3_k<<<(N + 255) / 256, 256>>>(ptr, bsum, cur, N, E);
    fill_k<<<(E + 255) / 256, 256>>>(row, col, cur, rows, E);

    // --- prep weights ---
    wprep_all_k<<<(59392 + 255) / 256, 256>>>(W1, W2, W3, Wa1, Wa2, wthi, wtlo);

    int MT = (N + 63) / 64;
    int propBlocks = (N + 7) / 8;

    // --- 3 GCN layers (128 -> 128) ---
    hgemm_k<128, 128><<<MT, 256, SM_128_128>>>(x, wthi + 0, wtlo + 0, G0, N);
    prop_bf_k<128><<<propBlocks, 256>>>(G0, ptr, rows, dinv, b1, Hhi, Hlo, N);
    hgemm_pre_k<128, 128><<<MT, 256, SM_128_128>>>(Hhi, Hlo, wthi + 16384, wtlo + 16384, G0, N);
    prop_bf_k<128><<<propBlocks, 256>>>(G0, ptr, rows, dinv, b2, Hhi, Hlo, N);
    hgemm_pre_k<128, 128><<<MT, 256, SM_128_128>>>(Hhi, Hlo, wthi + 32768, wtlo + 32768, G0, N);
    prop_bf_k<128><<<propBlocks, 256>>>(G0, ptr, rows, dinv, b3, X3hi, X3lo, N);

    // --- attention branch (128 -> 64 -> 32 -> 1) ---
    hgemm_pre_k<128, 64><<<MT, 256, SM_128_64>>>(X3hi, X3lo, wthi + 49152, wtlo + 49152, G0, N);
    prop_bf_k<64><<<propBlocks, 256>>>(G0, ptr, rows, dinv, ba1, Hhi, Hlo, N);
    hgemm_pre_k<64, 32><<<MT, 256, SM_64_32>>>(Hhi, Hlo, wthi + 57344, wtlo + 57344, G0, N);
    prop32dot_k<<<propBlocks, 256>>>(G0, ptr, rows, dinv, ba2, Wa3, s, N);
    prop1_k<<<propBlocks, 256>>>(s, ptr, rows, dinv, ba3, batch, wv, gmax, N);

    // --- softmax-pool (fused) + normalize ---
    pool_k<<<propBlocks, 256>>>(X3hi, X3lo, wv, gmax, batch, pooled, gsum, N);
    norm_k<<<128, 256>>>(pooled, gsum);

    // --- MLP head ---
    sgemm_k<128, 128><<<dim3(2, 1), 256>>>(pooled, Wm1, bm1, hbuf, 256, 128, 1);
    sgemm_k<128, 128><<<dim3(2, 2), 256>>>(hbuf, Wm2, bm2, (float*)d_out, 256, 256, 0);
}

// round 7
// speedup vs baseline: 1.4563x; 1.0211x over previous
#include <cuda_runtime.h>
#include <cuda_bf16.h>
#include <cstdint>

// ---------------------------------------------------------------------------
// Static scratch (no allocation allowed)
// ---------------------------------------------------------------------------
#define NMAX 100000
#define EMAX 1600000

__device__ float g_G0[NMAX * 128];                 // fp32 GEMM outputs / gather input
__device__ __nv_bfloat16 g_Hhi[NMAX * 128];        // prop output hi (recycled)
__device__ __nv_bfloat16 g_Hlo[NMAX * 128];        // prop output lo
__device__ __nv_bfloat16 g_X3hi[NMAX * 128];       // layer-3 output hi (kept for pool)
__device__ __nv_bfloat16 g_X3lo[NMAX * 128];
__device__ float g_s [NMAX];                       // attention scalar
__device__ float g_wv[NMAX];
__device__ float g_dinv[NMAX];
__device__ int   g_cnt[NMAX];
__device__ int   g_ptr[NMAX + 1];
__device__ int   g_cur[NMAX];
__device__ int   g_rows[EMAX];
__device__ int   g_bsum[512];
__device__ float g_gmax[256];
__device__ float g_gsum[256];
__device__ float g_pooled[256 * 128];
__device__ float g_h[256 * 128];
__device__ __nv_bfloat16 g_Wthi[65536];
__device__ __nv_bfloat16 g_Wtlo[65536];

// ---------------------------------------------------------------------------
// Helpers
// ---------------------------------------------------------------------------
__device__ __forceinline__ uint32_t smem_u32(const void* p) {
    uint32_t a;
    asm("{ .reg .u64 t; cvta.to.shared.u64 t, %1; cvt.u32.u64 %0, t; }"
        : "=r"(a) : "l"(p));
    return a;
}

__device__ __forceinline__ void ldsm_x4(uint32_t& r0, uint32_t& r1,
                                        uint32_t& r2, uint32_t& r3, uint32_t addr) {
    asm volatile("ldmatrix.sync.aligned.m8n8.x4.shared.b16 {%0,%1,%2,%3}, [%4];"
                 : "=r"(r0), "=r"(r1), "=r"(r2), "=r"(r3) : "r"(addr));
}

__device__ __forceinline__ void mma_bf16(float* c, uint32_t a0, uint32_t a1,
                                         uint32_t a2, uint32_t a3,
                                         uint32_t b0, uint32_t b1) {
    asm volatile(
        "mma.sync.aligned.m16n8k16.row.col.f32.bf16.bf16.f32 "
        "{%0,%1,%2,%3}, {%4,%5,%6,%7}, {%8,%9}, {%0,%1,%2,%3};"
        : "+f"(c[0]), "+f"(c[1]), "+f"(c[2]), "+f"(c[3])
        : "r"(a0), "r"(a1), "r"(a2), "r"(a3), "r"(b0), "r"(b1));
}

// cp.async 16B copy, zero-fill when sz == 0
__device__ __forceinline__ void cp16(uint32_t dst, const void* src, int sz) {
    asm volatile("cp.async.cg.shared.global [%0], [%1], 16, %2;"
                 :: "r"(dst), "l"(src), "r"(sz));
}
__device__ __forceinline__ void cp_commit_wait() {
    asm volatile("cp.async.commit_group;");
    asm volatile("cp.async.wait_group 0;");
}

// Packed split: (f0,f1) fp32 -> hi bf16x2 + lo bf16x2 (lo = rounded residual)
__device__ __forceinline__ void split2(float f0, float f1, uint32_t& h, uint32_t& l) {
    asm("cvt.rn.bf16x2.f32 %0, %1, %2;" : "=r"(h) : "f"(f1), "f"(f0));
    float h0 = __uint_as_float(h << 16);
    float h1 = __uint_as_float(h & 0xffff0000u);
    asm("cvt.rn.bf16x2.f32 %0, %1, %2;" : "=r"(l) : "f"(f1 - h1), "f"(f0 - h0));
}

// ---------------------------------------------------------------------------
// Fused weight prep (5 matrices, one launch). W is [K, N] row-major.
// ---------------------------------------------------------------------------
__global__ void wprep_all_k(const float* __restrict__ W1, const float* __restrict__ W2,
                            const float* __restrict__ W3, const float* __restrict__ Wa1,
                            const float* __restrict__ Wa2,
                            __nv_bfloat16* __restrict__ hi, __nv_bfloat16* __restrict__ lo) {
    int idx = blockIdx.x * blockDim.x + threadIdx.x;
    const float* W; int K, N, local;
    if (idx < 16384)      { W = W1;  K = 128; N = 128; local = idx; }
    else if (idx < 32768) { W = W2;  K = 128; N = 128; local = idx - 16384; }
    else if (idx < 49152) { W = W3;  K = 128; N = 128; local = idx - 32768; }
    else if (idx < 57344) { W = Wa1; K = 128; N = 64;  local = idx - 49152; }
    else if (idx < 59392) { W = Wa2; K = 64;  N = 32;  local = idx - 57344; }
    else return;
    int n = local / K, k = local % K;
    float v = W[(size_t)k * N + n];
    __nv_bfloat16 h = __float2bfloat16(v);
    __nv_bfloat16 l = __float2bfloat16(v - __bfloat162float(h));
    hi[idx] = h;
    lo[idx] = l;
}

// ---------------------------------------------------------------------------
// HMMA GEMM core: 64-row M tile, single-sweep mainloop with hi/lo reuse.
// 256 threads = 8 warps (4M x 2N); warp: 16 rows x N/2 cols.
// ---------------------------------------------------------------------------
template<int K, int N>
__device__ __forceinline__ void hgemm_core64(uint32_t sb, float* __restrict__ OUT,
                                             int M, int rowBase) {
    constexpr int SA = K * 2 + 16;
    constexpr int A_HI = 0;
    constexpr int A_LO = 64 * SA;
    constexpr int B_HI = 128 * SA;
    constexpr int B_LO = B_HI + N * SA;
    constexpr int NW = N / 2;
    constexpr int NT = NW / 8;

    const int tid = threadIdx.x;
    const int warp = tid >> 5;
    const int lane = tid & 31;
    const int wm = warp & 3;
    const int wn = warp >> 2;

    float acc[NT][4];
#pragma unroll
    for (int i = 0; i < NT; ++i)
#pragma unroll
        for (int j = 0; j < 4; ++j) acc[i][j] = 0.0f;

    const int m0 = wm * 16;
    const int q = lane >> 3;
    const int r8 = lane & 7;
    const uint32_t aRowOff = (uint32_t)(m0 + (q & 1) * 8 + r8) * SA + (uint32_t)(q >> 1) * 16;
    const uint32_t bOff = (uint32_t)(wn * NW + (q >> 1) * 8 + r8) * SA + (uint32_t)(q & 1) * 16;

    const uint32_t aHi = sb + A_HI + aRowOff;
    const uint32_t aLo = sb + A_LO + aRowOff;
    const uint32_t bHi = sb + B_HI + bOff;
    const uint32_t bLo = sb + B_LO + bOff;

#pragma unroll
    for (int kc = 0; kc < K / 16; ++kc) {
        uint32_t ah0, ah1, ah2, ah3, al0, al1, al2, al3;
        ldsm_x4(ah0, ah1, ah2, ah3, aHi + kc * 32);
        ldsm_x4(al0, al1, al2, al3, aLo + kc * 32);
#pragma unroll
        for (int nt2 = 0; nt2 < NW / 16; ++nt2) {
            uint32_t b0, b1, b2, b3;
            ldsm_x4(b0, b1, b2, b3, bHi + (uint32_t)(nt2 * 16) * SA + kc * 32);
            mma_bf16(acc[2 * nt2],     ah0, ah1, ah2, ah3, b0, b1);
            mma_bf16(acc[2 * nt2 + 1], ah0, ah1, ah2, ah3, b2, b3);
            mma_bf16(acc[2 * nt2],     al0, al1, al2, al3, b0, b1);
            mma_bf16(acc[2 * nt2 + 1], al0, al1, al2, al3, b2, b3);
            ldsm_x4(b0, b1, b2, b3, bLo + (uint32_t)(nt2 * 16) * SA + kc * 32);
            mma_bf16(acc[2 * nt2],     ah0, ah1, ah2, ah3, b0, b1);
            mma_bf16(acc[2 * nt2 + 1], ah0, ah1, ah2, ah3, b2, b3);
        }
    }

    const int row0 = rowBase + m0 + (lane >> 2);
    const int row1 = row0 + 8;
    const int cbase = wn * NW + (lane & 3) * 2;
#pragma unroll
    for (int nt = 0; nt < NT; ++nt) {
        if (row0 < M)
            *(float2*)(OUT + (size_t)row0 * N + cbase + nt * 8) = make_float2(acc[nt][0], acc[nt][1]);
        if (row1 < M)
            *(float2*)(OUT + (size_t)row1 * N + cbase + nt * 8) = make_float2(acc[nt][2], acc[nt][3]);
    }
}

// B staging via cp.async (rows K*2 bytes packed in global, SA-padded in smem)
template<int K, int N>
__device__ __forceinline__ void stage_B64(uint32_t sb,
                                          const __nv_bfloat16* __restrict__ WThi,
                                          const __nv_bfloat16* __restrict__ WTlo) {
    constexpr int SA = K * 2 + 16;
    constexpr int B_HI = 128 * SA;
    constexpr int B_LO = B_HI + N * SA;
    constexpr int CH = K / 8;
    const int tid = threadIdx.x;
    for (int i = tid; i < N * CH; i += 256) {
        int n = i / CH;
        int c = i % CH;
        cp16(sb + B_HI + n * SA + c * 16, (const char*)WThi + n * (K * 2) + c * 16, 16);
        cp16(sb + B_LO + n * SA + c * 16, (const char*)WTlo + n * (K * 2) + c * 16, 16);
    }
}

// Persistent variant 1: A fp32 in global (layer 1) — converts in-kernel.
// B staged ONCE per block; grid-stride over 64-row tiles.
template<int K, int N>
__global__ __launch_bounds__(256, 2)
void hgemm_k(const float* __restrict__ X,
             const __nv_bfloat16* __restrict__ WThi,
             const __nv_bfloat16* __restrict__ WTlo,
             float* __restrict__ OUT, int M) {
    extern __shared__ char smem[];
    constexpr int SA = K * 2 + 16;
    constexpr int A_HI = 0;
    constexpr int A_LO = 64 * SA;
    const int tid = threadIdx.x;
    const uint32_t sb = smem_u32(smem);

    stage_B64<K, N>(sb, WThi, WTlo);
    cp_commit_wait();                      // this thread's B chunks resident

    const int MT = (M + 63) >> 6;
    for (int tile = blockIdx.x; tile < MT; tile += gridDim.x) {
        const int rowBase = tile * 64;
        __syncthreads();                   // prior compute done; B visible (1st iter)
        for (int item = tid; item < 64 * (K / 8); item += 256) {
            int r = item / (K / 8);
            int k0 = (item % (K / 8)) * 8;
            float v[8];
            int grow = rowBase + r;
            if (grow < M) {
                const float4* p = (const float4*)(X + (size_t)grow * K + k0);
                float4 a = p[0], b = p[1];
                v[0] = a.x; v[1] = a.y; v[2] = a.z; v[3] = a.w;
                v[4] = b.x; v[5] = b.y; v[6] = b.z; v[7] = b.w;
            } else {
#pragma unroll
                for (int j = 0; j < 8; ++j) v[j] = 0.0f;
            }
            uint32_t hw[4], lw[4];
#pragma unroll
            for (int j = 0; j < 4; ++j) split2(v[2 * j], v[2 * j + 1], hw[j], lw[j]);
            *(uint4*)(smem + A_HI + r * SA + k0 * 2) = make_uint4(hw[0], hw[1], hw[2], hw[3]);
            *(uint4*)(smem + A_LO + r * SA + k0 * 2) = make_uint4(lw[0], lw[1], lw[2], lw[3]);
        }
        __syncthreads();
        hgemm_core64<K, N>(sb, OUT, M, rowBase);
    }
}

// Persistent variant 2: A pre-split bf16 hi/lo — cp.async staging, B once.
template<int K, int N>
__global__ __launch_bounds__(256, 2)
void hgemm_pre_k(const __nv_bfloat16* __restrict__ Ahi,
                 const __nv_bfloat16* __restrict__ Alo,
                 const __nv_bfloat16* __restrict__ WThi,
                 const __nv_bfloat16* __restrict__ WTlo,
                 float* __restrict__ OUT, int M) {
    extern __shared__ char smem[];
    constexpr int SA = K * 2 + 16;
    constexpr int A_HI = 0;
    constexpr int A_LO = 64 * SA;
    constexpr int CH = K / 8;
    const int tid = threadIdx.x;
    const uint32_t sb = smem_u32(smem);

    stage_B64<K, N>(sb, WThi, WTlo);
    asm volatile("cp.async.commit_group;");

    const int MT = (M + 63) >> 6;
    for (int tile = blockIdx.x; tile < MT; tile += gridDim.x) {
        const int rowBase = tile * 64;
        __syncthreads();                   // prior compute done before overwrite
        for (int item = tid; item < 64 * CH; item += 256) {
            int r = item / CH;
            int c = item % CH;
            int grow = rowBase + r;
            int inb = grow < M;
            size_t off = (size_t)(inb ? grow : 0) * K + c * 8;
            int sz = inb ? 16 : 0;
            cp16(sb + A_HI + r * SA + c * 16, (const char*)Ahi + off * 2, sz);
            cp16(sb + A_LO + r * SA + c * 16, (const char*)Alo + off * 2, sz);
        }
        cp_commit_wait();
        __syncthreads();
        hgemm_core64<K, N>(sb, OUT, M, rowBase);
    }
}

// ---------------------------------------------------------------------------
// CSC build + norms
// ---------------------------------------------------------------------------
__global__ void init_k(int* cnt, float* gmax, float* gsum, float* pooled, int n) {
    int i = blockIdx.x * blockDim.x + threadIdx.x;
    if (i < n) cnt[i] = 0;
    if (i < 256) { gmax[i] = 0.0f; gsum[i] = 0.0f; }
    if (i < 256 * 128) pooled[i] = 0.0f;
}

__global__ void count_k(const int* __restrict__ col, int* __restrict__ cnt, int e) {
    int i = blockIdx.x * blockDim.x + threadIdx.x;
    if (i < e) atomicAdd(&cnt[col[i]], 1);
}

__global__ void scan1_k(const int* __restrict__ cnt, int* __restrict__ ptr,
                        int* __restrict__ bsum, float* __restrict__ dinv, int n) {
    __shared__ int s[512];
    int t = threadIdx.x;
    int i = blockIdx.x * 512 + t;
    int v = (i < n) ? cnt[i] : 0;
    if (i < n) dinv[i] = rsqrtf((float)v + 1.0f);
    s[t] = v; __syncthreads();
    for (int off = 1; off < 512; off <<= 1) {
        int tmp = (t >= off) ? s[t - off] : 0;
        __syncthreads();
        s[t] += tmp;
        __syncthreads();
    }
    if (i < n) ptr[i] = s[t] - v;
    if (t == 511) bsum[blockIdx.x] = s[511];
}

__global__ void scan2_k(int* __restrict__ bsum, int nb) {
    __shared__ int s[512];
    int t = threadIdx.x;
    int v = (t < nb) ? bsum[t] : 0;
    s[t] = v; __syncthreads();
    for (int off = 1; off < 512; off <<= 1) {
        int tmp = (t >= off) ? s[t - off] : 0;
        __syncthreads();
        s[t] += tmp;
        __syncthreads();
    }
    if (t < nb) bsum[t] = s[t] - v;
}

__global__ void scan3_k(int* __restrict__ ptr, const int* __restrict__ bsum,
                        int* __restrict__ cur, int n, int etot) {
    int i = blockIdx.x * blockDim.x + threadIdx.x;
    if (i < n) {
        int p = ptr[i] + bsum[i >> 9];
        ptr[i] = p;
        cur[i] = p;
    }
    if (i == 0) ptr[n] = etot;
}

__global__ void fill_k(const int* __restrict__ row, const int* __restrict__ col,
                       int* __restrict__ cur, int* __restrict__ rows, int e) {
    int i = blockIdx.x * blockDim.x + threadIdx.x;
    if (i < e) {
        int c = col[i];
        int p = atomicAdd(&cur[c], 1);
        rows[p] = row[i];
    }
}

// ---------------------------------------------------------------------------
// SIMT SGEMM (tiny MLP head only); optional per-row pre-scale by 1/(rsum+eps)
// ---------------------------------------------------------------------------
template<int K, int FT>
__global__ __launch_bounds__(256)
void sgemm_k(const float* __restrict__ X, const float* __restrict__ W,
             const float* __restrict__ bias, float* __restrict__ OUT,
             int M, int ldW, int doRelu, const float* __restrict__ rsum) {
    constexpr int KC = 32;
    constexpr int TN = FT / 16;
    __shared__ float Xs[KC][132];
    __shared__ float Ws[KC][FT];

    int tid = threadIdx.x;
    int tx = tid & 15, ty = tid >> 4;
    int rowBase = blockIdx.x * 128;
    int cBase = blockIdx.y * FT;

    float acc[8][TN];
#pragma unroll
    for (int i = 0; i < 8; ++i)
#pragma unroll
        for (int j = 0; j < TN; ++j) acc[i][j] = 0.0f;

    for (int k0 = 0; k0 < K; k0 += KC) {
#pragma unroll
        for (int p = 0; p < 4; ++p) {
            int id = tid + p * 256;
            int r = id >> 3;
            int k4 = id & 7;
            float4 xv = make_float4(0.f, 0.f, 0.f, 0.f);
            int grow = rowBase + r;
            if (grow < M) {
                xv = *(const float4*)(X + (size_t)grow * K + k0 + k4 * 4);
                if (rsum) {
                    float sc = 1.0f / (rsum[grow] + 1e-16f);
                    xv.x *= sc; xv.y *= sc; xv.z *= sc; xv.w *= sc;
                }
            }
            Xs[k4 * 4 + 0][r] = xv.x;
            Xs[k4 * 4 + 1][r] = xv.y;
            Xs[k4 * 4 + 2][r] = xv.z;
            Xs[k4 * 4 + 3][r] = xv.w;
        }
        for (int id = tid; id < KC * FT / 4; id += 256) {
            int kk = (id * 4) / FT;
            int c  = (id * 4) % FT;
            *(float4*)&Ws[kk][c] =
                *(const float4*)(W + (size_t)(k0 + kk) * ldW + cBase + c);
        }
        __syncthreads();

#pragma unroll 8
        for (int kk = 0; kk < KC; ++kk) {
            float xr[8];
            float4 a = *(const float4*)&Xs[kk][ty * 8];
            float4 b = *(const float4*)&Xs[kk][ty * 8 + 4];
            xr[0] = a.x; xr[1] = a.y; xr[2] = a.z; xr[3] = a.w;
            xr[4] = b.x; xr[5] = b.y; xr[6] = b.z; xr[7] = b.w;
            float wv[TN];
            float4 w0 = *(const float4*)&Ws[kk][tx * 8];
            float4 w1 = *(const float4*)&Ws[kk][tx * 8 + 4];
            wv[0] = w0.x; wv[1] = w0.y; wv[2] = w0.z; wv[3] = w0.w;
            wv[4] = w1.x; wv[5] = w1.y; wv[6] = w1.z; wv[7] = w1.w;
#pragma unroll
            for (int i = 0; i < 8; ++i)
#pragma unroll
                for (int j = 0; j < TN; ++j)
                    acc[i][j] += xr[i] * wv[j];
        }
        __syncthreads();
    }

#pragma unroll
    for (int i = 0; i < 8; ++i) {
        int grow = rowBase + ty * 8 + i;
        if (grow >= M) continue;
#pragma unroll
        for (int j = 0; j < TN; ++j) {
            int c = cBase + tx * TN + j;
            float v = acc[i][j];
            if (bias) v += bias[c];
            if (doRelu) v = fmaxf(v, 0.0f);
            OUT[(size_t)grow * ldW + c] = v;
        }
    }
}

// ---------------------------------------------------------------------------
// Pull-based GCN propagation, unrolled x4 gather, bf16 hi/lo split output.
// ---------------------------------------------------------------------------
template<int F>
__global__ __launch_bounds__(256)
void prop_bf_k(const float* __restrict__ H, const int* __restrict__ ptr,
               const int* __restrict__ rows, const float* __restrict__ dinv,
               const float* __restrict__ bias,
               __nv_bfloat16* __restrict__ OHI, __nv_bfloat16* __restrict__ OLO, int n) {
    constexpr int V = F / 32;
    int node = (blockIdx.x * blockDim.x + threadIdx.x) >> 5;
    int lane = threadIdx.x & 31;
    if (node >= n) return;

    const float dn = dinv[node];
    const float selfw = dn * dn;
    const float* hb = H + lane * V;
    float acc[V];
    {
        const float* hp = hb + (size_t)node * F;
        if (V == 4) {
            float4 v = *(const float4*)hp;
            acc[0] = selfw * v.x; acc[1] = selfw * v.y;
            acc[2] = selfw * v.z; acc[3] = selfw * v.w;
        } else {
            float2 v = *(const float2*)hp;
            acc[0] = selfw * v.x; acc[1] = selfw * v.y;
        }
    }

    int beg = ptr[node], end = ptr[node + 1];
    for (int j0 = beg; j0 < end; j0 += 32) {
        int j = j0 + lane;
        int r = 0; float dv = 0.0f;
        if (j < end) { r = rows[j]; dv = dinv[r]; }
        int cnt = min(32, end - j0);
        int t = 0;
        for (; t + 4 <= cnt; t += 4) {
            int rr0 = __shfl_sync(0xffffffffu, r, t);
            int rr1 = __shfl_sync(0xffffffffu, r, t + 1);
            int rr2 = __shfl_sync(0xffffffffu, r, t + 2);
            int rr3 = __shfl_sync(0xffffffffu, r, t + 3);
            float w0 = __shfl_sync(0xffffffffu, dv, t)     * dn;
            float w1 = __shfl_sync(0xffffffffu, dv, t + 1) * dn;
            float w2 = __shfl_sync(0xffffffffu, dv, t + 2) * dn;
            float w3 = __shfl_sync(0xffffffffu, dv, t + 3) * dn;
            if (V == 4) {
                float4 v0 = *(const float4*)(hb + (size_t)rr0 * F);
                float4 v1 = *(const float4*)(hb + (size_t)rr1 * F);
                float4 v2 = *(const float4*)(hb + (size_t)rr2 * F);
                float4 v3 = *(const float4*)(hb + (size_t)rr3 * F);
                acc[0] += w0 * v0.x; acc[1] += w0 * v0.y; acc[2] += w0 * v0.z; acc[3] += w0 * v0.w;
                acc[0] += w1 * v1.x; acc[1] += w1 * v1.y; acc[2] += w1 * v1.z; acc[3] += w1 * v1.w;
                acc[0] += w2 * v2.x; acc[1] += w2 * v2.y; acc[2] += w2 * v2.z; acc[3] += w2 * v2.w;
                acc[0] += w3 * v3.x; acc[1] += w3 * v3.y; acc[2] += w3 * v3.z; acc[3] += w3 * v3.w;
            } else {
                float2 v0 = *(const float2*)(hb + (size_t)rr0 * F);
                float2 v1 = *(const float2*)(hb + (size_t)rr1 * F);
                float2 v2 = *(const float2*)(hb + (size_t)rr2 * F);
                float2 v3 = *(const float2*)(hb + (size_t)rr3 * F);
                acc[0] += w0 * v0.x; acc[1] += w0 * v0.y;
                acc[0] += w1 * v1.x; acc[1] += w1 * v1.y;
                acc[0] += w2 * v2.x; acc[1] += w2 * v2.y;
                acc[0] += w3 * v3.x; acc[1] += w3 * v3.y;
            }
        }
        for (; t < cnt; ++t) {
            int rr  = __shfl_sync(0xffffffffu, r,  t);
            float w = __shfl_sync(0xffffffffu, dv, t) * dn;
            if (V == 4) {
                float4 v = *(const float4*)(hb + (size_t)rr * F);
                acc[0] += w * v.x; acc[1] += w * v.y; acc[2] += w * v.z; acc[3] += w * v.w;
            } else {
                float2 v = *(const float2*)(hb + (size_t)rr * F);
                acc[0] += w * v.x; acc[1] += w * v.y;
            }
        }
    }

    if (V == 4) {
        float f0 = fmaxf(acc[0] + bias[lane * 4 + 0], 0.0f);
        float f1 = fmaxf(acc[1] + bias[lane * 4 + 1], 0.0f);
        float f2 = fmaxf(acc[2] + bias[lane * 4 + 2], 0.0f);
        float f3 = fmaxf(acc[3] + bias[lane * 4 + 3], 0.0f);
        uint32_t h01, l01, h23, l23;
        split2(f0, f1, h01, l01);
        split2(f2, f3, h23, l23);
        *(uint2*)(OHI + (size_t)node * F + lane * 4) = make_uint2(h01, h23);
        *(uint2*)(OLO + (size_t)node * F + lane * 4) = make_uint2(l01, l23);
    } else {
        float f0 = fmaxf(acc[0] + bias[lane * 2 + 0], 0.0f);
        float f1 = fmaxf(acc[1] + bias[lane * 2 + 1], 0.0f);
        uint32_t h, l;
        split2(f0, f1, h, l);
        *(uint32_t*)(OHI + (size_t)node * F + lane * 2) = h;
        *(uint32_t*)(OLO + (size_t)node * F + lane * 2) = l;
    }
}

// F=32 propagation fused with Wa3 dot
__global__ __launch_bounds__(256)
void prop32dot_k(const float* __restrict__ H, const int* __restrict__ ptr,
                 const int* __restrict__ rows, const float* __restrict__ dinv,
                 const float* __restrict__ ba2, const float* __restrict__ Wa3,
                 float* __restrict__ s, int n) {
    int node = (blockIdx.x * blockDim.x + threadIdx.x) >> 5;
    int lane = threadIdx.x & 31;
    if (node >= n) return;

    const float dn = dinv[node];
    float acc = dn * dn * H[(size_t)node * 32 + lane];
    const float* hb = H + lane;

    int beg = ptr[node], end = ptr[node + 1];
    for (int j0 = beg; j0 < end; j0 += 32) {
        int j = j0 + lane;
        int r = 0; float dv = 0.0f;
        if (j < end) { r = rows[j]; dv = dinv[r]; }
        int cnt = min(32, end - j0);
        int t = 0;
        for (; t + 4 <= cnt; t += 4) {
            int rr0 = __shfl_sync(0xffffffffu, r, t);
            int rr1 = __shfl_sync(0xffffffffu, r, t + 1);
            int rr2 = __shfl_sync(0xffffffffu, r, t + 2);
            int rr3 = __shfl_sync(0xffffffffu, r, t + 3);
            float w0 = __shfl_sync(0xffffffffu, dv, t)     * dn;
            float w1 = __shfl_sync(0xffffffffu, dv, t + 1) * dn;
            float w2 = __shfl_sync(0xffffffffu, dv, t + 2) * dn;
            float w3 = __shfl_sync(0xffffffffu, dv, t + 3) * dn;
            acc += w0 * hb[(size_t)rr0 * 32] + w1 * hb[(size_t)rr1 * 32]
                 + w2 * hb[(size_t)rr2 * 32] + w3 * hb[(size_t)rr3 * 32];
        }
        for (; t < cnt; ++t) {
            int rr  = __shfl_sync(0xffffffffu, r,  t);
            float w = __shfl_sync(0xffffffffu, dv, t) * dn;
            acc += w * hb[(size_t)rr * 32];
        }
    }

    float v = fmaxf(acc + ba2[lane], 0.0f) * Wa3[lane];
#pragma unroll
    for (int o = 16; o; o >>= 1) v += __shfl_down_sync(0xffffffffu, v, o);
    if (lane == 0) s[node] = v;
}

// F=1 propagation fused with segment-max
__global__ __launch_bounds__(256)
void prop1_k(const float* __restrict__ H, const int* __restrict__ ptr,
             const int* __restrict__ rows, const float* __restrict__ dinv,
             const float* __restrict__ bias, const int* __restrict__ batch,
             float* __restrict__ OUT, float* __restrict__ gmax, int n) {
    int node = (blockIdx.x * blockDim.x + threadIdx.x) >> 5;
    int lane = threadIdx.x & 31;
    if (node >= n) return;
    float dn = dinv[node];
    int beg = ptr[node], end = ptr[node + 1];
    float acc = 0.0f;
    for (int j = beg + lane; j < end; j += 32) {
        int r = rows[j];
        acc += dinv[r] * H[r];
    }
#pragma unroll
    for (int o = 16; o; o >>= 1) acc += __shfl_down_sync(0xffffffffu, acc, o);
    if (lane == 0) {
        float v = acc * dn + dn * dn * H[node] + bias[0];
        v = fmaxf(v, 0.0f);
        OUT[node] = v;
        atomicMax((unsigned int*)&gmax[batch[node]], __float_as_uint(v));
    }
}

// Fused exp + unnormalized pooling: pooled[b] += e * x3, gsum[b] += e
__global__ __launch_bounds__(256)
void pool_k(const __nv_bfloat16* __restrict__ X3hi, const __nv_bfloat16* __restrict__ X3lo,
            const float* __restrict__ wv, const float* __restrict__ gmax,
            const int* __restrict__ batch, float* __restrict__ pooled,
            float* __restrict__ gsum, int n) {
    int node = (blockIdx.x * blockDim.x + threadIdx.x) >> 5;
    int lane = threadIdx.x & 31;
    if (node >= n) return;
    int b = batch[node];
    float e = expf(wv[node] - gmax[b]);
    if (lane == 0) atomicAdd(&gsum[b], e);
    uint2 h = *(const uint2*)(X3hi + (size_t)node * 128 + lane * 4);
    uint2 l = *(const uint2*)(X3lo + (size_t)node * 128 + lane * 4);
    float f0 = __uint_as_float(h.x << 16)         + __uint_as_float(l.x << 16);
    float f1 = __uint_as_float(h.x & 0xffff0000u) + __uint_as_float(l.x & 0xffff0000u);
    float f2 = __uint_as_float(h.y << 16)         + __uint_as_float(l.y << 16);
    float f3 = __uint_as_float(h.y & 0xffff0000u) + __uint_as_float(l.y & 0xffff0000u);
    float* pb = pooled + b * 128 + lane * 4;
    atomicAdd(pb + 0, e * f0);
    atomicAdd(pb + 1, e * f1);
    atomicAdd(pb + 2, e * f2);
    atomicAdd(pb + 3, e * f3);
}

// ---------------------------------------------------------------------------
// Host launcher (two-stream fork for CSC build || weight prep + layer-1 GEMM)
// ---------------------------------------------------------------------------
extern "C" void kernel_launch(void* const* d_in, const int* in_sizes, int n_in,
                              void* d_out, int out_size) {
    const float* x     = (const float*)d_in[0];
    const int*   ei    = (const int*)d_in[1];
    const int*   batch = (const int*)d_in[2];
    const float* W1 = (const float*)d_in[3];   const float* b1 = (const float*)d_in[4];
    const float* W2 = (const float*)d_in[5];   const float* b2 = (const float*)d_in[6];
    const float* W3 = (const float*)d_in[7];   const float* b3 = (const float*)d_in[8];
    const float* Wa1 = (const float*)d_in[9];  const float* ba1 = (const float*)d_in[10];
    const float* Wa2 = (const float*)d_in[11]; const float* ba2 = (const float*)d_in[12];
    const float* Wa3 = (const float*)d_in[13]; const float* ba3 = (const float*)d_in[14];
    const float* Wm1 = (const float*)d_in[15]; const float* bm1 = (const float*)d_in[16];
    const float* Wm2 = (const float*)d_in[17]; const float* bm2 = (const float*)d_in[18];

    int N = in_sizes[0] / 128;
    int E = in_sizes[1] / 2;
    const int* row = ei;
    const int* col = ei + E;

    float *G0, *s, *wv, *dinv, *gmax, *gsum, *pooled, *hbuf;
    int *cnt, *ptr, *cur, *rows, *bsum;
    __nv_bfloat16 *Hhi, *Hlo, *X3hi, *X3lo, *wthi, *wtlo;
    cudaGetSymbolAddress((void**)&G0, g_G0);
    cudaGetSymbolAddress((void**)&Hhi, g_Hhi);
    cudaGetSymbolAddress((void**)&Hlo, g_Hlo);
    cudaGetSymbolAddress((void**)&X3hi, g_X3hi);
    cudaGetSymbolAddress((void**)&X3lo, g_X3lo);
    cudaGetSymbolAddress((void**)&s, g_s);
    cudaGetSymbolAddress((void**)&wv, g_wv);
    cudaGetSymbolAddress((void**)&dinv, g_dinv);
    cudaGetSymbolAddress((void**)&cnt, g_cnt);
    cudaGetSymbolAddress((void**)&ptr, g_ptr);
    cudaGetSymbolAddress((void**)&cur, g_cur);
    cudaGetSymbolAddress((void**)&rows, g_rows);
    cudaGetSymbolAddress((void**)&bsum, g_bsum);
    cudaGetSymbolAddress((void**)&gmax, g_gmax);
    cudaGetSymbolAddress((void**)&gsum, g_gsum);
    cudaGetSymbolAddress((void**)&pooled, g_pooled);
    cudaGetSymbolAddress((void**)&hbuf, g_h);
    cudaGetSymbolAddress((void**)&wthi, g_Wthi);
    cudaGetSymbolAddress((void**)&wtlo, g_Wtlo);

    const int SM_128_128 = 128 * 272 + 2 * 128 * 272;  // 104448 -> 2 CTAs/SM
    const int SM_128_64  = 128 * 272 + 2 *  64 * 272;  //  69632
    const int SM_64_32   = 128 * 144 + 2 *  32 * 144;  //  27648
    cudaFuncSetAttribute(hgemm_k<128, 128>,     cudaFuncAttributeMaxDynamicSharedMemorySize, SM_128_128);
    cudaFuncSetAttribute(hgemm_pre_k<128, 128>, cudaFuncAttributeMaxDynamicSharedMemorySize, SM_128_128);
    cudaFuncSetAttribute(hgemm_pre_k<128, 64>,  cudaFuncAttributeMaxDynamicSharedMemorySize, SM_128_64);
    cudaFuncSetAttribute(hgemm_pre_k<64, 32>,   cudaFuncAttributeMaxDynamicSharedMemorySize, SM_64_32);

    // side stream + fork/join events (created once, on the pre-capture call)
    static cudaStream_t side = nullptr;
    static cudaEvent_t evF = nullptr, evJ = nullptr;
    if (!side) {
        cudaStreamCreateWithFlags(&side, cudaStreamNonBlocking);
        cudaEventCreateWithFlags(&evF, cudaEventDisableTiming);
        cudaEventCreateWithFlags(&evJ, cudaEventDisableTiming);
    }

    int NB = (N + 511) / 512;
    int nInit = (N > 256 * 128) ? N : 256 * 128;
    int MT = (N + 63) / 64;
    int GP = (MT < 296) ? MT : 296;        // persistent GEMM grid (one 2-CTA/SM wave)
    int propBlocks = (N + 7) / 8;

    // --- fork: CSC build on side stream ---
    cudaEventRecord(evF, 0);
    cudaStreamWaitEvent(side, evF, 0);
    init_k<<<(nInit + 255) / 256, 256, 0, side>>>(cnt, gmax, gsum, pooled, N);
    count_k<<<(E + 255) / 256, 256, 0, side>>>(col, cnt, E);
    scan1_k<<<NB, 512, 0, side>>>(cnt, ptr, bsum, dinv, N);
    scan2_k<<<1, 512, 0, side>>>(bsum, NB);
    scan3_k<<<(N + 255) / 256, 256, 0, side>>>(ptr, bsum, cur, N, E);
    fill_k<<<(E + 255) / 256, 256, 0, side>>>(row, col, cur, rows, E);
    cudaEventRecord(evJ, side);

    // --- main stream: weight prep + layer-1 GEMM (independent of CSC) ---
    wprep_all_k<<<(59392 + 255) / 256, 256>>>(W1, W2, W3, Wa1, Wa2, wthi, wtlo);
    hgemm_k<128, 128><<<GP, 256, SM_128_128>>>(x, wthi + 0, wtlo + 0, G0, N);

    // --- join ---
    cudaStreamWaitEvent(0, evJ, 0);

    // --- 3 GCN layers (128 -> 128) ---
    prop_bf_k<128><<<propBlocks, 256>>>(G0, ptr, rows, dinv, b1, Hhi, Hlo, N);
    hgemm_pre_k<128, 128><<<GP, 256, SM_128_128>>>(Hhi, Hlo, wthi + 16384, wtlo + 16384, G0, N);
    prop_bf_k<128><<<propBlocks, 256>>>(G0, ptr, rows, dinv, b2, Hhi, Hlo, N);
    hgemm_pre_k<128, 128><<<GP, 256, SM_128_128>>>(Hhi, Hlo, wthi + 32768, wtlo + 32768, G0, N);
    prop_bf_k<128><<<propBlocks, 256>>>(G0, ptr, rows, dinv, b3, X3hi, X3lo, N);

    // --- attention branch (128 -> 64 -> 32 -> 1) ---
    hgemm_pre_k<128, 64><<<GP, 256, SM_128_64>>>(X3hi, X3lo, wthi + 49152, wtlo + 49152, G0, N);
    prop_bf_k<64><<<propBlocks, 256>>>(G0, ptr, rows, dinv, ba1, Hhi, Hlo, N);
    hgemm_pre_k<64, 32><<<GP, 256, SM_64_32>>>(Hhi, Hlo, wthi + 57344, wtlo + 57344, G0, N);
    prop32dot_k<<<propBlocks, 256>>>(G0, ptr, rows, dinv, ba2, Wa3, s, N);
    prop1_k<<<propBlocks, 256>>>(s, ptr, rows, dinv, ba3, batch, wv, gmax, N);

    // --- softmax-pool (fused, unnormalized) ---
    pool_k<<<propBlocks, 256>>>(X3hi, X3lo, wv, gmax, batch, pooled, gsum, N);

    // --- MLP head (normalization folded into first GEMM's staging) ---
    sgemm_k<128, 128><<<dim3(2, 1), 256>>>(pooled, Wm1, bm1, hbuf, 256, 128, 1, gsum);
    sgemm_k<128, 128><<<dim3(2, 2), 256>>>(hbuf, Wm2, bm2, (float*)d_out, 256, 256, 0, nullptr);
}

// round 8
// speedup vs baseline: 1.4845x; 1.0193x over previous
#include <cuda_runtime.h>
#include <cuda_bf16.h>
#include <cstdint>

// ---------------------------------------------------------------------------
// Static scratch (no allocation allowed)
// ---------------------------------------------------------------------------
#define NMAX 100000
#define EMAX 1600000

__device__ float g_G0[NMAX * 128];                 // fp32 GEMM outputs / gather input
__device__ __nv_bfloat16 g_Hhi[NMAX * 128];        // prop output hi (recycled)
__device__ __nv_bfloat16 g_Hlo[NMAX * 128];        // prop output lo
__device__ __nv_bfloat16 g_X3hi[NMAX * 128];       // layer-3 output hi (kept for pool)
__device__ __nv_bfloat16 g_X3lo[NMAX * 128];
__device__ float g_s [NMAX];                       // attention scalar
__device__ float g_wv[NMAX];
__device__ float g_dinv[NMAX];
__device__ int   g_cnt[NMAX];
__device__ int   g_ptr[NMAX + 1];
__device__ int   g_cur[NMAX];
__device__ int   g_rows[EMAX];
__device__ float g_wts[EMAX];                      // per-edge weight dinv[r]*dinv[c]
__device__ int   g_bsum[512];
__device__ float g_gmax[256];
__device__ float g_gsum[256];
__device__ float g_pooled[256 * 128];
__device__ float g_h[256 * 128];
__device__ __nv_bfloat16 g_Wthi[65536];
__device__ __nv_bfloat16 g_Wtlo[65536];

// ---------------------------------------------------------------------------
// Helpers
// ---------------------------------------------------------------------------
__device__ __forceinline__ uint32_t smem_u32(const void* p) {
    uint32_t a;
    asm("{ .reg .u64 t; cvta.to.shared.u64 t, %1; cvt.u32.u64 %0, t; }"
        : "=r"(a) : "l"(p));
    return a;
}

__device__ __forceinline__ void ldsm_x4(uint32_t& r0, uint32_t& r1,
                                        uint32_t& r2, uint32_t& r3, uint32_t addr) {
    asm volatile("ldmatrix.sync.aligned.m8n8.x4.shared.b16 {%0,%1,%2,%3}, [%4];"
                 : "=r"(r0), "=r"(r1), "=r"(r2), "=r"(r3) : "r"(addr));
}

__device__ __forceinline__ void mma_bf16(float* c, uint32_t a0, uint32_t a1,
                                         uint32_t a2, uint32_t a3,
                                         uint32_t b0, uint32_t b1) {
    asm volatile(
        "mma.sync.aligned.m16n8k16.row.col.f32.bf16.bf16.f32 "
        "{%0,%1,%2,%3}, {%4,%5,%6,%7}, {%8,%9}, {%0,%1,%2,%3};"
        : "+f"(c[0]), "+f"(c[1]), "+f"(c[2]), "+f"(c[3])
        : "r"(a0), "r"(a1), "r"(a2), "r"(a3), "r"(b0), "r"(b1));
}

// cp.async 16B copy, zero-fill when sz == 0
__device__ __forceinline__ void cp16(uint32_t dst, const void* src, int sz) {
    asm volatile("cp.async.cg.shared.global [%0], [%1], 16, %2;"
                 :: "r"(dst), "l"(src), "r"(sz));
}
__device__ __forceinline__ void cp_commit_wait() {
    asm volatile("cp.async.commit_group;");
    asm volatile("cp.async.wait_group 0;");
}

// Packed split: (f0,f1) fp32 -> hi bf16x2 + lo bf16x2 (lo = rounded residual)
__device__ __forceinline__ void split2(float f0, float f1, uint32_t& h, uint32_t& l) {
    asm("cvt.rn.bf16x2.f32 %0, %1, %2;" : "=r"(h) : "f"(f1), "f"(f0));
    float h0 = __uint_as_float(h << 16);
    float h1 = __uint_as_float(h & 0xffff0000u);
    asm("cvt.rn.bf16x2.f32 %0, %1, %2;" : "=r"(l) : "f"(f1 - h1), "f"(f0 - h0));
}

// ---------------------------------------------------------------------------
// Fused weight prep (5 matrices, one launch). W is [K, N] row-major.
// ---------------------------------------------------------------------------
__global__ void wprep_all_k(const float* __restrict__ W1, const float* __restrict__ W2,
                            const float* __restrict__ W3, const float* __restrict__ Wa1,
                            const float* __restrict__ Wa2,
                            __nv_bfloat16* __restrict__ hi, __nv_bfloat16* __restrict__ lo) {
    int idx = blockIdx.x * blockDim.x + threadIdx.x;
    const float* W; int K, N, local;
    if (idx < 16384)      { W = W1;  K = 128; N = 128; local = idx; }
    else if (idx < 32768) { W = W2;  K = 128; N = 128; local = idx - 16384; }
    else if (idx < 49152) { W = W3;  K = 128; N = 128; local = idx - 32768; }
    else if (idx < 57344) { W = Wa1; K = 128; N = 64;  local = idx - 49152; }
    else if (idx < 59392) { W = Wa2; K = 64;  N = 32;  local = idx - 57344; }
    else return;
    int n = local / K, k = local % K;
    float v = W[(size_t)k * N + n];
    __nv_bfloat16 h = __float2bfloat16(v);
    __nv_bfloat16 l = __float2bfloat16(v - __bfloat162float(h));
    hi[idx] = h;
    lo[idx] = l;
}

// ---------------------------------------------------------------------------
// HMMA GEMM core: 64-row M tile, single-sweep mainloop with hi/lo reuse.
// ---------------------------------------------------------------------------
template<int K, int N>
__device__ __forceinline__ void hgemm_core64(uint32_t sb, float* __restrict__ OUT,
                                             int M, int rowBase) {
    constexpr int SA = K * 2 + 16;
    constexpr int A_HI = 0;
    constexpr int A_LO = 64 * SA;
    constexpr int B_HI = 128 * SA;
    constexpr int B_LO = B_HI + N * SA;
    constexpr int NW = N / 2;
    constexpr int NT = NW / 8;

    const int tid = threadIdx.x;
    const int warp = tid >> 5;
    const int lane = tid & 31;
    const int wm = warp & 3;
    const int wn = warp >> 2;

    float acc[NT][4];
#pragma unroll
    for (int i = 0; i < NT; ++i)
#pragma unroll
        for (int j = 0; j < 4; ++j) acc[i][j] = 0.0f;

    const int m0 = wm * 16;
    const int q = lane >> 3;
    const int r8 = lane & 7;
    const uint32_t aRowOff = (uint32_t)(m0 + (q & 1) * 8 + r8) * SA + (uint32_t)(q >> 1) * 16;
    const uint32_t bOff = (uint32_t)(wn * NW + (q >> 1) * 8 + r8) * SA + (uint32_t)(q & 1) * 16;

    const uint32_t aHi = sb + A_HI + aRowOff;
    const uint32_t aLo = sb + A_LO + aRowOff;
    const uint32_t bHi = sb + B_HI + bOff;
    const uint32_t bLo = sb + B_LO + bOff;

#pragma unroll
    for (int kc = 0; kc < K / 16; ++kc) {
        uint32_t ah0, ah1, ah2, ah3, al0, al1, al2, al3;
        ldsm_x4(ah0, ah1, ah2, ah3, aHi + kc * 32);
        ldsm_x4(al0, al1, al2, al3, aLo + kc * 32);
#pragma unroll
        for (int nt2 = 0; nt2 < NW / 16; ++nt2) {
            uint32_t b0, b1, b2, b3;
            ldsm_x4(b0, b1, b2, b3, bHi + (uint32_t)(nt2 * 16) * SA + kc * 32);
            mma_bf16(acc[2 * nt2],     ah0, ah1, ah2, ah3, b0, b1);
            mma_bf16(acc[2 * nt2 + 1], ah0, ah1, ah2, ah3, b2, b3);
            mma_bf16(acc[2 * nt2],     al0, al1, al2, al3, b0, b1);
            mma_bf16(acc[2 * nt2 + 1], al0, al1, al2, al3, b2, b3);
            ldsm_x4(b0, b1, b2, b3, bLo + (uint32_t)(nt2 * 16) * SA + kc * 32);
            mma_bf16(acc[2 * nt2],     ah0, ah1, ah2, ah3, b0, b1);
            mma_bf16(acc[2 * nt2 + 1], ah0, ah1, ah2, ah3, b2, b3);
        }
    }

    const int row0 = rowBase + m0 + (lane >> 2);
    const int row1 = row0 + 8;
    const int cbase = wn * NW + (lane & 3) * 2;
#pragma unroll
    for (int nt = 0; nt < NT; ++nt) {
        if (row0 < M)
            *(float2*)(OUT + (size_t)row0 * N + cbase + nt * 8) = make_float2(acc[nt][0], acc[nt][1]);
        if (row1 < M)
            *(float2*)(OUT + (size_t)row1 * N + cbase + nt * 8) = make_float2(acc[nt][2], acc[nt][3]);
    }
}

template<int K, int N>
__device__ __forceinline__ void stage_B64(uint32_t sb,
                                          const __nv_bfloat16* __restrict__ WThi,
                                          const __nv_bfloat16* __restrict__ WTlo) {
    constexpr int SA = K * 2 + 16;
    constexpr int B_HI = 128 * SA;
    constexpr int B_LO = B_HI + N * SA;
    constexpr int CH = K / 8;
    const int tid = threadIdx.x;
    for (int i = tid; i < N * CH; i += 256) {
        int n = i / CH;
        int c = i % CH;
        cp16(sb + B_HI + n * SA + c * 16, (const char*)WThi + n * (K * 2) + c * 16, 16);
        cp16(sb + B_LO + n * SA + c * 16, (const char*)WTlo + n * (K * 2) + c * 16, 16);
    }
}

// Persistent variant 1: A fp32 in global (layer 1) — converts in-kernel.
template<int K, int N>
__global__ __launch_bounds__(256, 2)
void hgemm_k(const float* __restrict__ X,
             const __nv_bfloat16* __restrict__ WThi,
             const __nv_bfloat16* __restrict__ WTlo,
             float* __restrict__ OUT, int M) {
    extern __shared__ char smem[];
    constexpr int SA = K * 2 + 16;
    constexpr int A_HI = 0;
    constexpr int A_LO = 64 * SA;
    const int tid = threadIdx.x;
    const uint32_t sb = smem_u32(smem);

    stage_B64<K, N>(sb, WThi, WTlo);
    cp_commit_wait();

    const int MT = (M + 63) >> 6;
    for (int tile = blockIdx.x; tile < MT; tile += gridDim.x) {
        const int rowBase = tile * 64;
        __syncthreads();
        for (int item = tid; item < 64 * (K / 8); item += 256) {
            int r = item / (K / 8);
            int k0 = (item % (K / 8)) * 8;
            float v[8];
            int grow = rowBase + r;
            if (grow < M) {
                const float4* p = (const float4*)(X + (size_t)grow * K + k0);
                float4 a = p[0], b = p[1];
                v[0] = a.x; v[1] = a.y; v[2] = a.z; v[3] = a.w;
                v[4] = b.x; v[5] = b.y; v[6] = b.z; v[7] = b.w;
            } else {
#pragma unroll
                for (int j = 0; j < 8; ++j) v[j] = 0.0f;
            }
            uint32_t hw[4], lw[4];
#pragma unroll
            for (int j = 0; j < 4; ++j) split2(v[2 * j], v[2 * j + 1], hw[j], lw[j]);
            *(uint4*)(smem + A_HI + r * SA + k0 * 2) = make_uint4(hw[0], hw[1], hw[2], hw[3]);
            *(uint4*)(smem + A_LO + r * SA + k0 * 2) = make_uint4(lw[0], lw[1], lw[2], lw[3]);
        }
        __syncthreads();
        hgemm_core64<K, N>(sb, OUT, M, rowBase);
    }
}

// Persistent variant 2: A pre-split bf16 hi/lo — cp.async staging, B once.
template<int K, int N>
__global__ __launch_bounds__(256, 2)
void hgemm_pre_k(const __nv_bfloat16* __restrict__ Ahi,
                 const __nv_bfloat16* __restrict__ Alo,
                 const __nv_bfloat16* __restrict__ WThi,
                 const __nv_bfloat16* __restrict__ WTlo,
                 float* __restrict__ OUT, int M) {
    extern __shared__ char smem[];
    constexpr int SA = K * 2 + 16;
    constexpr int A_HI = 0;
    constexpr int A_LO = 64 * SA;
    constexpr int CH = K / 8;
    const int tid = threadIdx.x;
    const uint32_t sb = smem_u32(smem);

    stage_B64<K, N>(sb, WThi, WTlo);
    asm volatile("cp.async.commit_group;");

    const int MT = (M + 63) >> 6;
    for (int tile = blockIdx.x; tile < MT; tile += gridDim.x) {
        const int rowBase = tile * 64;
        __syncthreads();
        for (int item = tid; item < 64 * CH; item += 256) {
            int r = item / CH;
            int c = item % CH;
            int grow = rowBase + r;
            int inb = grow < M;
            size_t off = (size_t)(inb ? grow : 0) * K + c * 8;
            int sz = inb ? 16 : 0;
            cp16(sb + A_HI + r * SA + c * 16, (const char*)Ahi + off * 2, sz);
            cp16(sb + A_LO + r * SA + c * 16, (const char*)Alo + off * 2, sz);
        }
        cp_commit_wait();
        __syncthreads();
        hgemm_core64<K, N>(sb, OUT, M, rowBase);
    }
}

// ---------------------------------------------------------------------------
// CSC build + norms
// ---------------------------------------------------------------------------
__global__ void init_k(int* cnt, float* gmax, float* gsum, float* pooled, int n) {
    int i = blockIdx.x * blockDim.x + threadIdx.x;
    if (i < n) cnt[i] = 0;
    if (i < 256) { gmax[i] = 0.0f; gsum[i] = 0.0f; }
    if (i < 256 * 128) pooled[i] = 0.0f;
}

__global__ void count_k(const int* __restrict__ col, int* __restrict__ cnt, int e) {
    int i = blockIdx.x * blockDim.x + threadIdx.x;
    if (i < e) atomicAdd(&cnt[col[i]], 1);
}

__global__ void scan1_k(const int* __restrict__ cnt, int* __restrict__ ptr,
                        int* __restrict__ bsum, float* __restrict__ dinv, int n) {
    __shared__ int s[512];
    int t = threadIdx.x;
    int i = blockIdx.x * 512 + t;
    int v = (i < n) ? cnt[i] : 0;
    if (i < n) dinv[i] = rsqrtf((float)v + 1.0f);
    s[t] = v; __syncthreads();
    for (int off = 1; off < 512; off <<= 1) {
        int tmp = (t >= off) ? s[t - off] : 0;
        __syncthreads();
        s[t] += tmp;
        __syncthreads();
    }
    if (i < n) ptr[i] = s[t] - v;
    if (t == 511) bsum[blockIdx.x] = s[511];
}

__global__ void scan2_k(int* __restrict__ bsum, int nb) {
    __shared__ int s[512];
    int t = threadIdx.x;
    int v = (t < nb) ? bsum[t] : 0;
    s[t] = v; __syncthreads();
    for (int off = 1; off < 512; off <<= 1) {
        int tmp = (t >= off) ? s[t - off] : 0;
        __syncthreads();
        s[t] += tmp;
        __syncthreads();
    }
    if (t < nb) bsum[t] = s[t] - v;
}

__global__ void scan3_k(int* __restrict__ ptr, const int* __restrict__ bsum,
                        int* __restrict__ cur, int n, int etot) {
    int i = blockIdx.x * blockDim.x + threadIdx.x;
    if (i < n) {
        int p = ptr[i] + bsum[i >> 9];
        ptr[i] = p;
        cur[i] = p;
    }
    if (i == 0) ptr[n] = etot;
}

// fill CSC rows AND per-edge weights (dinv ready after scan1)
__global__ void fill_k(const int* __restrict__ row, const int* __restrict__ col,
                       int* __restrict__ cur, int* __restrict__ rows,
                       float* __restrict__ wts, const float* __restrict__ dinv, int e) {
    int i = blockIdx.x * blockDim.x + threadIdx.x;
    if (i < e) {
        int c = col[i];
        int r = row[i];
        int p = atomicAdd(&cur[c], 1);
        rows[p] = r;
        wts[p] = dinv[r] * dinv[c];
    }
}

// ---------------------------------------------------------------------------
// SIMT SGEMM (tiny MLP head only); optional per-row pre-scale by 1/(rsum+eps)
// ---------------------------------------------------------------------------
template<int K, int FT>
__global__ __launch_bounds__(256)
void sgemm_k(const float* __restrict__ X, const float* __restrict__ W,
             const float* __restrict__ bias, float* __restrict__ OUT,
             int M, int ldW, int doRelu, const float* __restrict__ rsum) {
    constexpr int KC = 32;
    constexpr int TN = FT / 16;
    __shared__ float Xs[KC][132];
    __shared__ float Ws[KC][FT];

    int tid = threadIdx.x;
    int tx = tid & 15, ty = tid >> 4;
    int rowBase = blockIdx.x * 128;
    int cBase = blockIdx.y * FT;

    float acc[8][TN];
#pragma unroll
    for (int i = 0; i < 8; ++i)
#pragma unroll
        for (int j = 0; j < TN; ++j) acc[i][j] = 0.0f;

    for (int k0 = 0; k0 < K; k0 += KC) {
#pragma unroll
        for (int p = 0; p < 4; ++p) {
            int id = tid + p * 256;
            int r = id >> 3;
            int k4 = id & 7;
            float4 xv = make_float4(0.f, 0.f, 0.f, 0.f);
            int grow = rowBase + r;
            if (grow < M) {
                xv = *(const float4*)(X + (size_t)grow * K + k0 + k4 * 4);
                if (rsum) {
                    float sc = 1.0f / (rsum[grow] + 1e-16f);
                    xv.x *= sc; xv.y *= sc; xv.z *= sc; xv.w *= sc;
                }
            }
            Xs[k4 * 4 + 0][r] = xv.x;
            Xs[k4 * 4 + 1][r] = xv.y;
            Xs[k4 * 4 + 2][r] = xv.z;
            Xs[k4 * 4 + 3][r] = xv.w;
        }
        for (int id = tid; id < KC * FT / 4; id += 256) {
            int kk = (id * 4) / FT;
            int c  = (id * 4) % FT;
            *(float4*)&Ws[kk][c] =
                *(const float4*)(W + (size_t)(k0 + kk) * ldW + cBase + c);
        }
        __syncthreads();

#pragma unroll 8
        for (int kk = 0; kk < KC; ++kk) {
            float xr[8];
            float4 a = *(const float4*)&Xs[kk][ty * 8];
            float4 b = *(const float4*)&Xs[kk][ty * 8 + 4];
            xr[0] = a.x; xr[1] = a.y; xr[2] = a.z; xr[3] = a.w;
            xr[4] = b.x; xr[5] = b.y; xr[6] = b.z; xr[7] = b.w;
            float wv[TN];
            float4 w0 = *(const float4*)&Ws[kk][tx * 8];
            float4 w1 = *(const float4*)&Ws[kk][tx * 8 + 4];
            wv[0] = w0.x; wv[1] = w0.y; wv[2] = w0.z; wv[3] = w0.w;
            wv[4] = w1.x; wv[5] = w1.y; wv[6] = w1.z; wv[7] = w1.w;
#pragma unroll
            for (int i = 0; i < 8; ++i)
#pragma unroll
                for (int j = 0; j < TN; ++j)
                    acc[i][j] += xr[i] * wv[j];
        }
        __syncthreads();
    }

#pragma unroll
    for (int i = 0; i < 8; ++i) {
        int grow = rowBase + ty * 8 + i;
        if (grow >= M) continue;
#pragma unroll
        for (int j = 0; j < TN; ++j) {
            int c = cBase + tx * TN + j;
            float v = acc[i][j];
            if (bias) v += bias[c];
            if (doRelu) v = fmaxf(v, 0.0f);
            OUT[(size_t)grow * ldW + c] = v;
        }
    }
}

// ---------------------------------------------------------------------------
// Pull-based GCN propagation with precomputed edge weights; bf16 hi/lo out.
// ---------------------------------------------------------------------------
template<int F>
__global__ __launch_bounds__(256)
void prop_bf_k(const float* __restrict__ H, const int* __restrict__ ptr,
               const int* __restrict__ rows, const float* __restrict__ wts,
               const float* __restrict__ dinv, const float* __restrict__ bias,
               __nv_bfloat16* __restrict__ OHI, __nv_bfloat16* __restrict__ OLO, int n) {
    constexpr int V = F / 32;
    int node = (blockIdx.x * blockDim.x + threadIdx.x) >> 5;
    int lane = threadIdx.x & 31;
    if (node >= n) return;

    const float dn = dinv[node];
    const float selfw = dn * dn;
    const char* hb = (const char*)(H + lane * V);
    float acc[V];
    {
        const float* hp = (const float*)(hb + (uint32_t)node * (F * 4));
        if (V == 4) {
            float4 v = *(const float4*)hp;
            acc[0] = selfw * v.x; acc[1] = selfw * v.y;
            acc[2] = selfw * v.z; acc[3] = selfw * v.w;
        } else {
            float2 v = *(const float2*)hp;
            acc[0] = selfw * v.x; acc[1] = selfw * v.y;
        }
    }

    int beg = ptr[node], end = ptr[node + 1];
    for (int j0 = beg; j0 < end; j0 += 32) {
        int j = j0 + lane;
        int r = 0; float w = 0.0f;
        if (j < end) { r = rows[j]; w = wts[j]; }
        int cnt = min(32, end - j0);
        int t = 0;
        for (; t + 4 <= cnt; t += 4) {
            uint32_t o0 = (uint32_t)__shfl_sync(0xffffffffu, r, t)     * (F * 4);
            uint32_t o1 = (uint32_t)__shfl_sync(0xffffffffu, r, t + 1) * (F * 4);
            uint32_t o2 = (uint32_t)__shfl_sync(0xffffffffu, r, t + 2) * (F * 4);
            uint32_t o3 = (uint32_t)__shfl_sync(0xffffffffu, r, t + 3) * (F * 4);
            float w0 = __shfl_sync(0xffffffffu, w, t);
            float w1 = __shfl_sync(0xffffffffu, w, t + 1);
            float w2 = __shfl_sync(0xffffffffu, w, t + 2);
            float w3 = __shfl_sync(0xffffffffu, w, t + 3);
            if (V == 4) {
                float4 v0 = *(const float4*)(hb + o0);
                float4 v1 = *(const float4*)(hb + o1);
                float4 v2 = *(const float4*)(hb + o2);
                float4 v3 = *(const float4*)(hb + o3);
                acc[0] += w0 * v0.x; acc[1] += w0 * v0.y; acc[2] += w0 * v0.z; acc[3] += w0 * v0.w;
                acc[0] += w1 * v1.x; acc[1] += w1 * v1.y; acc[2] += w1 * v1.z; acc[3] += w1 * v1.w;
                acc[0] += w2 * v2.x; acc[1] += w2 * v2.y; acc[2] += w2 * v2.z; acc[3] += w2 * v2.w;
                acc[0] += w3 * v3.x; acc[1] += w3 * v3.y; acc[2] += w3 * v3.z; acc[3] += w3 * v3.w;
            } else {
                float2 v0 = *(const float2*)(hb + o0);
                float2 v1 = *(const float2*)(hb + o1);
                float2 v2 = *(const float2*)(hb + o2);
                float2 v3 = *(const float2*)(hb + o3);
                acc[0] += w0 * v0.x; acc[1] += w0 * v0.y;
                acc[0] += w1 * v1.x; acc[1] += w1 * v1.y;
                acc[0] += w2 * v2.x; acc[1] += w2 * v2.y;
                acc[0] += w3 * v3.x; acc[1] += w3 * v3.y;
            }
        }
        for (; t < cnt; ++t) {
            uint32_t o = (uint32_t)__shfl_sync(0xffffffffu, r, t) * (F * 4);
            float wt = __shfl_sync(0xffffffffu, w, t);
            if (V == 4) {
                float4 v = *(const float4*)(hb + o);
                acc[0] += wt * v.x; acc[1] += wt * v.y; acc[2] += wt * v.z; acc[3] += wt * v.w;
            } else {
                float2 v = *(const float2*)(hb + o);
                acc[0] += wt * v.x; acc[1] += wt * v.y;
            }
        }
    }

    if (V == 4) {
        float f0 = fmaxf(acc[0] + bias[lane * 4 + 0], 0.0f);
        float f1 = fmaxf(acc[1] + bias[lane * 4 + 1], 0.0f);
        float f2 = fmaxf(acc[2] + bias[lane * 4 + 2], 0.0f);
        float f3 = fmaxf(acc[3] + bias[lane * 4 + 3], 0.0f);
        uint32_t h01, l01, h23, l23;
        split2(f0, f1, h01, l01);
        split2(f2, f3, h23, l23);
        *(uint2*)(OHI + (size_t)node * F + lane * 4) = make_uint2(h01, h23);
        *(uint2*)(OLO + (size_t)node * F + lane * 4) = make_uint2(l01, l23);
    } else {
        float f0 = fmaxf(acc[0] + bias[lane * 2 + 0], 0.0f);
        float f1 = fmaxf(acc[1] + bias[lane * 2 + 1], 0.0f);
        uint32_t h, l;
        split2(f0, f1, h, l);
        *(uint32_t*)(OHI + (size_t)node * F + lane * 2) = h;
        *(uint32_t*)(OLO + (size_t)node * F + lane * 2) = l;
    }
}

// F=32 propagation fused with Wa3 dot
__global__ __launch_bounds__(256)
void prop32dot_k(const float* __restrict__ H, const int* __restrict__ ptr,
                 const int* __restrict__ rows, const float* __restrict__ wts,
                 const float* __restrict__ dinv,
                 const float* __restrict__ ba2, const float* __restrict__ Wa3,
                 float* __restrict__ s, int n) {
    int node = (blockIdx.x * blockDim.x + threadIdx.x) >> 5;
    int lane = threadIdx.x & 31;
    if (node >= n) return;

    const float dn = dinv[node];
    float acc = dn * dn * H[(size_t)node * 32 + lane];
    const float* hb = H + lane;

    int beg = ptr[node], end = ptr[node + 1];
    for (int j0 = beg; j0 < end; j0 += 32) {
        int j = j0 + lane;
        int r = 0; float w = 0.0f;
        if (j < end) { r = rows[j]; w = wts[j]; }
        int cnt = min(32, end - j0);
        int t = 0;
        for (; t + 4 <= cnt; t += 4) {
            int rr0 = __shfl_sync(0xffffffffu, r, t);
            int rr1 = __shfl_sync(0xffffffffu, r, t + 1);
            int rr2 = __shfl_sync(0xffffffffu, r, t + 2);
            int rr3 = __shfl_sync(0xffffffffu, r, t + 3);
            float w0 = __shfl_sync(0xffffffffu, w, t);
            float w1 = __shfl_sync(0xffffffffu, w, t + 1);
            float w2 = __shfl_sync(0xffffffffu, w, t + 2);
            float w3 = __shfl_sync(0xffffffffu, w, t + 3);
            acc += w0 * hb[(uint32_t)rr0 * 32] + w1 * hb[(uint32_t)rr1 * 32]
                 + w2 * hb[(uint32_t)rr2 * 32] + w3 * hb[(uint32_t)rr3 * 32];
        }
        for (; t < cnt; ++t) {
            int rr  = __shfl_sync(0xffffffffu, r,  t);
            float wt = __shfl_sync(0xffffffffu, w, t);
            acc += wt * hb[(uint32_t)rr * 32];
        }
    }

    float v = fmaxf(acc + ba2[lane], 0.0f) * Wa3[lane];
#pragma unroll
    for (int o = 16; o; o >>= 1) v += __shfl_down_sync(0xffffffffu, v, o);
    if (lane == 0) s[node] = v;
}

// F=1 propagation fused with segment-max
__global__ __launch_bounds__(256)
void prop1_k(const float* __restrict__ H, const int* __restrict__ ptr,
             const int* __restrict__ rows, const float* __restrict__ wts,
             const float* __restrict__ dinv,
             const float* __restrict__ bias, const int* __restrict__ batch,
             float* __restrict__ OUT, float* __restrict__ gmax, int n) {
    int node = (blockIdx.x * blockDim.x + threadIdx.x) >> 5;
    int lane = threadIdx.x & 31;
    if (node >= n) return;
    float dn = dinv[node];
    int beg = ptr[node], end = ptr[node + 1];
    float acc = 0.0f;
    for (int j = beg + lane; j < end; j += 32) {
        acc += wts[j] * H[rows[j]];
    }
#pragma unroll
    for (int o = 16; o; o >>= 1) acc += __shfl_down_sync(0xffffffffu, acc, o);
    if (lane == 0) {
        float v = acc + dn * dn * H[node] + bias[0];
        v = fmaxf(v, 0.0f);
        OUT[node] = v;
        atomicMax((unsigned int*)&gmax[batch[node]], __float_as_uint(v));
    }
}

// Fused exp + unnormalized pooling: pooled[b] += e * x3, gsum[b] += e
__global__ __launch_bounds__(256)
void pool_k(const __nv_bfloat16* __restrict__ X3hi, const __nv_bfloat16* __restrict__ X3lo,
            const float* __restrict__ wv, const float* __restrict__ gmax,
            const int* __restrict__ batch, float* __restrict__ pooled,
            float* __restrict__ gsum, int n) {
    int node = (blockIdx.x * blockDim.x + threadIdx.x) >> 5;
    int lane = threadIdx.x & 31;
    if (node >= n) return;
    int b = batch[node];
    float e = expf(wv[node] - gmax[b]);
    if (lane == 0) atomicAdd(&gsum[b], e);
    uint2 h = *(const uint2*)(X3hi + (size_t)node * 128 + lane * 4);
    uint2 l = *(const uint2*)(X3lo + (size_t)node * 128 + lane * 4);
    float f0 = __uint_as_float(h.x << 16)         + __uint_as_float(l.x << 16);
    float f1 = __uint_as_float(h.x & 0xffff0000u) + __uint_as_float(l.x & 0xffff0000u);
    float f2 = __uint_as_float(h.y << 16)         + __uint_as_float(l.y << 16);
    float f3 = __uint_as_float(h.y & 0xffff0000u) + __uint_as_float(l.y & 0xffff0000u);
    float* pb = pooled + b * 128 + lane * 4;
    atomicAdd(pb + 0, e * f0);
    atomicAdd(pb + 1, e * f1);
    atomicAdd(pb + 2, e * f2);
    atomicAdd(pb + 3, e * f3);
}

// ---------------------------------------------------------------------------
// Host launcher (two-stream fork for CSC build || weight prep + layer-1 GEMM)
// ---------------------------------------------------------------------------
extern "C" void kernel_launch(void* const* d_in, const int* in_sizes, int n_in,
                              void* d_out, int out_size) {
    const float* x     = (const float*)d_in[0];
    const int*   ei    = (const int*)d_in[1];
    const int*   batch = (const int*)d_in[2];
    const float* W1 = (const float*)d_in[3];   const float* b1 = (const float*)d_in[4];
    const float* W2 = (const float*)d_in[5];   const float* b2 = (const float*)d_in[6];
    const float* W3 = (const float*)d_in[7];   const float* b3 = (const float*)d_in[8];
    const float* Wa1 = (const float*)d_in[9];  const float* ba1 = (const float*)d_in[10];
    const float* Wa2 = (const float*)d_in[11]; const float* ba2 = (const float*)d_in[12];
    const float* Wa3 = (const float*)d_in[13]; const float* ba3 = (const float*)d_in[14];
    const float* Wm1 = (const float*)d_in[15]; const float* bm1 = (const float*)d_in[16];
    const float* Wm2 = (const float*)d_in[17]; const float* bm2 = (const float*)d_in[18];

    int N = in_sizes[0] / 128;
    int E = in_sizes[1] / 2;
    const int* row = ei;
    const int* col = ei + E;

    float *G0, *s, *wv, *dinv, *gmax, *gsum, *pooled, *hbuf, *wts;
    int *cnt, *ptr, *cur, *rows, *bsum;
    __nv_bfloat16 *Hhi, *Hlo, *X3hi, *X3lo, *wthi, *wtlo;
    cudaGetSymbolAddress((void**)&G0, g_G0);
    cudaGetSymbolAddress((void**)&Hhi, g_Hhi);
    cudaGetSymbolAddress((void**)&Hlo, g_Hlo);
    cudaGetSymbolAddress((void**)&X3hi, g_X3hi);
    cudaGetSymbolAddress((void**)&X3lo, g_X3lo);
    cudaGetSymbolAddress((void**)&s, g_s);
    cudaGetSymbolAddress((void**)&wv, g_wv);
    cudaGetSymbolAddress((void**)&dinv, g_dinv);
    cudaGetSymbolAddress((void**)&cnt, g_cnt);
    cudaGetSymbolAddress((void**)&ptr, g_ptr);
    cudaGetSymbolAddress((void**)&cur, g_cur);
    cudaGetSymbolAddress((void**)&rows, g_rows);
    cudaGetSymbolAddress((void**)&wts, g_wts);
    cudaGetSymbolAddress((void**)&bsum, g_bsum);
    cudaGetSymbolAddress((void**)&gmax, g_gmax);
    cudaGetSymbolAddress((void**)&gsum, g_gsum);
    cudaGetSymbolAddress((void**)&pooled, g_pooled);
    cudaGetSymbolAddress((void**)&hbuf, g_h);
    cudaGetSymbolAddress((void**)&wthi, g_Wthi);
    cudaGetSymbolAddress((void**)&wtlo, g_Wtlo);

    const int SM_128_128 = 128 * 272 + 2 * 128 * 272;  // 104448 -> 2 CTAs/SM
    const int SM_128_64  = 128 * 272 + 2 *  64 * 272;  //  69632
    const int SM_64_32   = 128 * 144 + 2 *  32 * 144;  //  27648
    cudaFuncSetAttribute(hgemm_k<128, 128>,     cudaFuncAttributeMaxDynamicSharedMemorySize, SM_128_128);
    cudaFuncSetAttribute(hgemm_pre_k<128, 128>, cudaFuncAttributeMaxDynamicSharedMemorySize, SM_128_128);
    cudaFuncSetAttribute(hgemm_pre_k<128, 64>,  cudaFuncAttributeMaxDynamicSharedMemorySize, SM_128_64);
    cudaFuncSetAttribute(hgemm_pre_k<64, 32>,   cudaFuncAttributeMaxDynamicSharedMemorySize, SM_64_32);

    static cudaStream_t side = nullptr;
    static cudaEvent_t evF = nullptr, evJ = nullptr;
    if (!side) {
        cudaStreamCreateWithFlags(&side, cudaStreamNonBlocking);
        cudaEventCreateWithFlags(&evF, cudaEventDisableTiming);
        cudaEventCreateWithFlags(&evJ, cudaEventDisableTiming);
    }

    int NB = (N + 511) / 512;
    int nInit = (N > 256 * 128) ? N : 256 * 128;
    int MT = (N + 63) / 64;
    int GP = (MT < 296) ? MT : 296;
    int propBlocks = (N + 7) / 8;

    // --- fork: CSC build (+ edge weights) on side stream ---
    cudaEventRecord(evF, 0);
    cudaStreamWaitEvent(side, evF, 0);
    init_k<<<(nInit + 255) / 256, 256, 0, side>>>(cnt, gmax, gsum, pooled, N);
    count_k<<<(E + 255) / 256, 256, 0, side>>>(col, cnt, E);
    scan1_k<<<NB, 512, 0, side>>>(cnt, ptr, bsum, dinv, N);
    scan2_k<<<1, 512, 0, side>>>(bsum, NB);
    scan3_k<<<(N + 255) / 256, 256, 0, side>>>(ptr, bsum, cur, N, E);
    fill_k<<<(E + 255) / 256, 256, 0, side>>>(row, col, cur, rows, wts, dinv, E);
    cudaEventRecord(evJ, side);

    // --- main stream: weight prep + layer-1 GEMM ---
    wprep_all_k<<<(59392 + 255) / 256, 256>>>(W1, W2, W3, Wa1, Wa2, wthi, wtlo);
    hgemm_k<128, 128><<<GP, 256, SM_128_128>>>(x, wthi + 0, wtlo + 0, G0, N);

    // --- join ---
    cudaStreamWaitEvent(0, evJ, 0);

    // --- 3 GCN layers (128 -> 128) ---
    prop_bf_k<128><<<propBlocks, 256>>>(G0, ptr, rows, wts, dinv, b1, Hhi, Hlo, N);
    hgemm_pre_k<128, 128><<<GP, 256, SM_128_128>>>(Hhi, Hlo, wthi + 16384, wtlo + 16384, G0, N);
    prop_bf_k<128><<<propBlocks, 256>>>(G0, ptr, rows, wts, dinv, b2, Hhi, Hlo, N);
    hgemm_pre_k<128, 128><<<GP, 256, SM_128_128>>>(Hhi, Hlo, wthi + 32768, wtlo + 32768, G0, N);
    prop_bf_k<128><<<propBlocks, 256>>>(G0, ptr, rows, wts, dinv, b3, X3hi, X3lo, N);

    // --- attention branch (128 -> 64 -> 32 -> 1) ---
    hgemm_pre_k<128, 64><<<GP, 256, SM_128_64>>>(X3hi, X3lo, wthi + 49152, wtlo + 49152, G0, N);
    prop_bf_k<64><<<propBlocks, 256>>>(G0, ptr, rows, wts, dinv, ba1, Hhi, Hlo, N);
    hgemm_pre_k<64, 32><<<GP, 256, SM_64_32>>>(Hhi, Hlo, wthi + 57344, wtlo + 57344, G0, N);
    prop32dot_k<<<propBlocks, 256>>>(G0, ptr, rows, wts, dinv, ba2, Wa3, s, N);
    prop1_k<<<propBlocks, 256>>>(s, ptr, rows, wts, dinv, ba3, batch, wv, gmax, N);

    // --- softmax-pool (fused, unnormalized) ---
    pool_k<<<propBlocks, 256>>>(X3hi, X3lo, wv, gmax, batch, pooled, gsum, N);

    // --- MLP head (normalization folded into first GEMM's staging) ---
    sgemm_k<128, 128><<<dim3(2, 1), 256>>>(pooled, Wm1, bm1, hbuf, 256, 128, 1, gsum);
    sgemm_k<128, 128><<<dim3(2, 2), 256>>>(hbuf, Wm2, bm2, (float*)d_out, 256, 256, 0, nullptr);
}